// round 2
// baseline (speedup 1.0000x reference)
#include <cuda_runtime.h>

#define NMAX 50000
#define EMAX 800000
#define FIN  512
#define HID  128
#define NC   40

// ---------------- device scratch (static; no allocs allowed) ----------------
__device__ float g_h1  [NMAX * HID];   // x @ W1
__device__ float g_out1[NMAX * HID];   // relu(agg1 + b1)
__device__ float g_h2  [NMAX * NC];    // out1 @ W2
__device__ float g_dinv[NMAX];
__device__ int   g_cnt [NMAX];
__device__ int   g_fill[NMAX];
__device__ int   g_rowptr[NMAX + 1];
__device__ int   g_col [EMAX];
__device__ int   g_is64;

typedef unsigned long long u64;

// ---------------- f32x2 helpers (sm_100+ packed fp32) ----------------
__device__ __forceinline__ u64 pk2(float lo, float hi) {
    u64 r; asm("mov.b64 %0, {%1,%2};" : "=l"(r) : "f"(lo), "f"(hi)); return r;
}
__device__ __forceinline__ float2 unpk2(u64 v) {
    float2 f; asm("mov.b64 {%0,%1}, %2;" : "=f"(f.x), "=f"(f.y) : "l"(v)); return f;
}
__device__ __forceinline__ void ffma2(u64& d, u64 a, u64 b) {
    asm("fma.rn.f32x2 %0, %1, %2, %0;" : "+l"(d) : "l"(a), "l"(b));
}

// edge index accessor: handles both int32 and int64 edge_index
__device__ __forceinline__ int ld_idx(const void* ei, int pos) {
    if (g_is64) return (int)((const long long*)ei)[pos];
    return ((const int*)ei)[pos];
}

// ---------------- dtype detection ----------------
// If edge_index is int64, every odd 32-bit word in the first 4096 elements is the
// high word of a value < 2^31 => 0. If int32, those words are random node ids.
__global__ void k_detect(const unsigned* __restrict__ w, int e) {
    __shared__ unsigned red[256];
    int total = e < 4096 ? e : 4096;
    unsigned acc = 0;
    for (int i = threadIdx.x; i < total; i += 256) acc |= w[2 * i + 1];
    red[threadIdx.x] = acc;
    __syncthreads();
    for (int s = 128; s > 0; s >>= 1) {
        if (threadIdx.x < s) red[threadIdx.x] |= red[threadIdx.x + s];
        __syncthreads();
    }
    if (threadIdx.x == 0) g_is64 = (red[0] == 0u) ? 1 : 0;
}

__global__ void k_zero(int n) {
    int i = blockIdx.x * blockDim.x + threadIdx.x;
    if (i < n) { g_cnt[i] = 0; g_fill[i] = 0; }
}

__global__ void k_count(const void* __restrict__ ei, int e) {
    int i = blockIdx.x * blockDim.x + threadIdx.x;
    if (i >= e) return;
    int dst = ld_idx(ei, e + i);
    atomicAdd(&g_cnt[dst], 1);
}

// single-block exclusive scan over g_cnt -> g_rowptr, plus dinv = rsqrt(deg+1)
__global__ void k_scan(int n, int e) {
    __shared__ int part[1024];
    const int t = threadIdx.x;
    const int per = (n + 1023) >> 10;
    int start = t * per;
    int end = start + per; if (end > n) end = n;
    int s = 0;
    for (int i = start; i < end; i++) s += g_cnt[i];
    part[t] = s;
    __syncthreads();
    for (int off = 1; off < 1024; off <<= 1) {
        int v = (t >= off) ? part[t - off] : 0;
        __syncthreads();
        part[t] += v;
        __syncthreads();
    }
    int base = (t == 0) ? 0 : part[t - 1];
    for (int i = start; i < end; i++) {
        g_rowptr[i] = base;
        int c = g_cnt[i];
        base += c;
        g_dinv[i] = rsqrtf((float)(c + 1));   // +1 self-loop; deg >= 1 always
    }
    if (t == 1023) g_rowptr[n] = e;
}

__global__ void k_fill(const void* __restrict__ ei, int e) {
    int i = blockIdx.x * blockDim.x + threadIdx.x;
    if (i >= e) return;
    int src = ld_idx(ei, i);
    int dst = ld_idx(ei, e + i);
    int pos = g_rowptr[dst] + atomicAdd(&g_fill[dst], 1);
    g_col[pos] = src;
}

// ---------------- GEMM1: h1 = x[n,512] @ W1[512,128], f32x2 inner ----------------
// BM=128, BN=128 (full), BK=32, 256 threads; thread: 16 rows (8 row-pairs) x 4 cols.
__global__ __launch_bounds__(256) void k_gemm1(const float* __restrict__ x,
                                               const float* __restrict__ W,
                                               int n) {
    __shared__ __align__(16) float As[32][132];  // [k][row], +4 pad
    __shared__ __align__(16) float Bs[32][128];  // [k][col]

    const int tid = threadIdx.x;
    const int tx = tid & 31;        // col group: cols tx*4 .. +3
    const int ty = tid >> 5;        // row group: rows ty*16 .. +15
    const int row0 = blockIdx.x * 128;

    u64 acc[8][4];
#pragma unroll
    for (int p = 0; p < 8; p++)
#pragma unroll
        for (int j = 0; j < 4; j++) acc[p][j] = 0ull;

    for (int k0 = 0; k0 < FIN; k0 += 32) {
        // load A tile (128 rows x 32 k) transposed into As[k][row]
#pragma unroll
        for (int p = 0; p < 4; p++) {
            int u = tid + p * 256;          // 0..1023
            int r = u >> 3;                 // 0..127
            int kq = (u & 7) << 2;          // 0..28
            int grow = row0 + r;
            float4 v = make_float4(0.f, 0.f, 0.f, 0.f);
            if (grow < n) v = *(const float4*)(x + (size_t)grow * FIN + k0 + kq);
            As[kq + 0][r] = v.x; As[kq + 1][r] = v.y;
            As[kq + 2][r] = v.z; As[kq + 3][r] = v.w;
        }
        // load B tile (32 k x 128 cols)
#pragma unroll
        for (int p = 0; p < 4; p++) {
            int u = tid + p * 256;
            int br = u >> 5;
            int bc = (u & 31) << 2;
            *(float4*)&Bs[br][bc] = *(const float4*)(W + (size_t)(k0 + br) * HID + bc);
        }
        __syncthreads();

#pragma unroll 4
        for (int kk = 0; kk < 32; kk++) {
            float4 bq = *(const float4*)&Bs[kk][tx << 2];
            u64 bd[4] = { pk2(bq.x, bq.x), pk2(bq.y, bq.y),
                          pk2(bq.z, bq.z), pk2(bq.w, bq.w) };
            const u64* ap = (const u64*)&As[kk][ty << 4];
            ulonglong2 A0 = *(const ulonglong2*)(ap + 0);
            ulonglong2 A1 = *(const ulonglong2*)(ap + 2);
            ulonglong2 A2 = *(const ulonglong2*)(ap + 4);
            ulonglong2 A3 = *(const ulonglong2*)(ap + 6);
            u64 a2[8] = { A0.x, A0.y, A1.x, A1.y, A2.x, A2.y, A3.x, A3.y };
#pragma unroll
            for (int p = 0; p < 8; p++)
#pragma unroll
                for (int j = 0; j < 4; j++) ffma2(acc[p][j], a2[p], bd[j]);
        }
        __syncthreads();
    }

#pragma unroll
    for (int p = 0; p < 8; p++) {
        int r_lo = row0 + (ty << 4) + 2 * p;
        float2 c0 = unpk2(acc[p][0]);
        float2 c1 = unpk2(acc[p][1]);
        float2 c2 = unpk2(acc[p][2]);
        float2 c3 = unpk2(acc[p][3]);
        if (r_lo < n)
            *(float4*)(g_h1 + (size_t)r_lo * HID + (tx << 2)) =
                make_float4(c0.x, c1.x, c2.x, c3.x);
        if (r_lo + 1 < n)
            *(float4*)(g_h1 + (size_t)(r_lo + 1) * HID + (tx << 2)) =
                make_float4(c0.y, c1.y, c2.y, c3.y);
    }
}

// ---------------- agg1: out1 = relu(b1 + sum_norm(h1)) , warp per node ----------------
__global__ void k_agg1(const float* __restrict__ b1, int n) {
    int gw = (blockIdx.x * blockDim.x + threadIdx.x) >> 5;
    int lane = threadIdx.x & 31;
    if (gw >= n) return;
    const int i = gw;
    const float di = g_dinv[i];
    const float4* __restrict__ h4 = (const float4*)g_h1;

    float4 acc = h4[(size_t)i * 32 + lane];          // self-loop term
    float sw = di * di;
    acc.x *= sw; acc.y *= sw; acc.z *= sw; acc.w *= sw;

    const int rs = g_rowptr[i], re = g_rowptr[i + 1];
    for (int base = rs; base < re; base += 32) {
        int m = re - base; if (m > 32) m = 32;
        int s = 0; float w = 0.f;
        if (lane < m) { s = g_col[base + lane]; w = g_dinv[s] * di; }
#pragma unroll 4
        for (int j = 0; j < m; j++) {
            int ss = __shfl_sync(0xffffffffu, s, j);
            float ww = __shfl_sync(0xffffffffu, w, j);
            float4 v = h4[(size_t)ss * 32 + lane];
            acc.x += v.x * ww; acc.y += v.y * ww;
            acc.z += v.z * ww; acc.w += v.w * ww;
        }
    }
    float4 bb = ((const float4*)b1)[lane];
    acc.x = fmaxf(acc.x + bb.x, 0.f);
    acc.y = fmaxf(acc.y + bb.y, 0.f);
    acc.z = fmaxf(acc.z + bb.z, 0.f);
    acc.w = fmaxf(acc.w + bb.w, 0.f);
    ((float4*)g_out1)[(size_t)i * 32 + lane] = acc;
}

// ---------------- GEMM2: h2 = out1[n,128] @ W2[128,40], 160 threads/block ----------------
__global__ __launch_bounds__(160) void k_gemm2(const float* __restrict__ W2, int n) {
    __shared__ __align__(16) float Ws[HID * NC];   // [k][c], stride 40
    __shared__ float As[32 * 129];                 // [r][k], pad 129

    const int tid = threadIdx.x;
    for (int q = tid; q < HID * NC; q += 160) Ws[q] = W2[q];

    const int r0 = blockIdx.x * 32;
    for (int q = tid; q < 32 * HID; q += 160) {
        int r = q >> 7, k = q & 127;
        int grow = r0 + r;
        As[r * 129 + k] = (grow < n) ? g_out1[(size_t)grow * HID + k] : 0.f;
    }
    __syncthreads();

    const int r = tid & 31;
    const int cg = tid >> 5;       // 0..4
    const int c0 = cg * 8;
    float acc[8];
#pragma unroll
    for (int j = 0; j < 8; j++) acc[j] = 0.f;

#pragma unroll 4
    for (int k = 0; k < HID; k++) {
        float a = As[r * 129 + k];
        float4 w0 = *(const float4*)&Ws[k * NC + c0];
        float4 w1 = *(const float4*)&Ws[k * NC + c0 + 4];
        acc[0] += a * w0.x; acc[1] += a * w0.y; acc[2] += a * w0.z; acc[3] += a * w0.w;
        acc[4] += a * w1.x; acc[5] += a * w1.y; acc[6] += a * w1.z; acc[7] += a * w1.w;
    }
    int grow = r0 + r;
    if (grow < n) {
        *(float4*)(g_h2 + (size_t)grow * NC + c0) =
            make_float4(acc[0], acc[1], acc[2], acc[3]);
        *(float4*)(g_h2 + (size_t)grow * NC + c0 + 4) =
            make_float4(acc[4], acc[5], acc[6], acc[7]);
    }
}

// ---------------- agg2 + bias + log_softmax, warp per node ----------------
__global__ void k_agg2(const float* __restrict__ b2, float* __restrict__ out, int n) {
    int gw = (blockIdx.x * blockDim.x + threadIdx.x) >> 5;
    int lane = threadIdx.x & 31;
    if (gw >= n) return;
    const int i = gw;
    const float di = g_dinv[i];
    const float4* __restrict__ h4 = (const float4*)g_h2;

    float4 acc = make_float4(0.f, 0.f, 0.f, 0.f);
    if (lane < 10) {
        acc = h4[(size_t)i * 10 + lane];
        float sw = di * di;
        acc.x *= sw; acc.y *= sw; acc.z *= sw; acc.w *= sw;
    }
    const int rs = g_rowptr[i], re = g_rowptr[i + 1];
    for (int base = rs; base < re; base += 32) {
        int m = re - base; if (m > 32) m = 32;
        int s = 0; float w = 0.f;
        if (lane < m) { s = g_col[base + lane]; w = g_dinv[s] * di; }
#pragma unroll 4
        for (int j = 0; j < m; j++) {
            int ss = __shfl_sync(0xffffffffu, s, j);
            float ww = __shfl_sync(0xffffffffu, w, j);
            if (lane < 10) {
                float4 v = h4[(size_t)ss * 10 + lane];
                acc.x += v.x * ww; acc.y += v.y * ww;
                acc.z += v.z * ww; acc.w += v.w * ww;
            }
        }
    }
    if (lane < 10) {
        float4 bb = ((const float4*)b2)[lane];
        acc.x += bb.x; acc.y += bb.y; acc.z += bb.z; acc.w += bb.w;
    }
    // log-softmax over 40 values spread across lanes 0..9 (4 each)
    float m = (lane < 10)
        ? fmaxf(fmaxf(acc.x, acc.y), fmaxf(acc.z, acc.w)) : -3.0e38f;
#pragma unroll
    for (int off = 8; off; off >>= 1)
        m = fmaxf(m, __shfl_xor_sync(0xffffffffu, m, off, 16));
    float sum = (lane < 10)
        ? (expf(acc.x - m) + expf(acc.y - m) + expf(acc.z - m) + expf(acc.w - m))
        : 0.f;
#pragma unroll
    for (int off = 8; off; off >>= 1)
        sum += __shfl_xor_sync(0xffffffffu, sum, off, 16);
    float lse = m + logf(sum);
    if (lane < 10) {
        ((float4*)out)[(size_t)i * 10 + lane] =
            make_float4(acc.x - lse, acc.y - lse, acc.z - lse, acc.w - lse);
    }
}

// ---------------- launch ----------------
extern "C" void kernel_launch(void* const* d_in, const int* in_sizes, int n_in,
                              void* d_out, int out_size) {
    const float* x  = (const float*)d_in[0];
    const void*  ei = d_in[1];
    const float* W1 = (const float*)d_in[2];
    const float* b1 = (const float*)d_in[3];
    const float* W2 = (const float*)d_in[4];
    const float* b2 = (const float*)d_in[5];
    float* out = (float*)d_out;

    const int n = in_sizes[0] / FIN;   // 50000
    const int e = in_sizes[1] / 2;     // 800000 (element count same for i32/i64)

    k_detect<<<1, 256>>>((const unsigned*)ei, e);
    k_zero  <<<(n + 255) / 256, 256>>>(n);
    k_count <<<(e + 255) / 256, 256>>>(ei, e);
    k_scan  <<<1, 1024>>>(n, e);
    k_fill  <<<(e + 255) / 256, 256>>>(ei, e);
    k_gemm1 <<<(n + 127) / 128, 256>>>(x, W1, n);
    k_agg1  <<<(n + 7) / 8, 256>>>(b1, n);
    k_gemm2 <<<(n + 31) / 32, 160>>>(W2, n);
    k_agg2  <<<(n + 7) / 8, 256>>>(b2, out, n);
}

// round 5
// speedup vs baseline: 1.2331x; 1.2331x over previous
#include <cuda_runtime.h>

#define NMAX 50000
#define EMAX 800000
#define FIN  512
#define HID  128
#define NC   40
#define NBLK 256   // max scan blocks (ceil(NMAX/256) = 196 <= 256)

// ---------------- device scratch (static; no allocs allowed) ----------------
__device__ float g_h1  [NMAX * HID];   // x @ W1
__device__ float g_out1[NMAX * HID];   // relu(agg1 + b1)
__device__ float g_h2  [NMAX * NC];    // out1 @ W2
__device__ float g_dinv[NMAX];
__device__ int   g_cnt [NMAX];
__device__ int   g_fill[NMAX];
__device__ int   g_rowptr[NMAX + 1];
__device__ int2  g_cw  [EMAX];         // {src, bitcast(dinv[src]*dinv[dst])}
__device__ int   g_bsum[NBLK];
__device__ int   g_boff[NBLK];
__device__ int   g_is64;

typedef unsigned long long u64;

// ---------------- f32x2 helpers (sm_100+ packed fp32) ----------------
__device__ __forceinline__ u64 pk2(float lo, float hi) {
    u64 r; asm("mov.b64 %0, {%1,%2};" : "=l"(r) : "f"(lo), "f"(hi)); return r;
}
__device__ __forceinline__ float2 unpk2(u64 v) {
    float2 f; asm("mov.b64 {%0,%1}, %2;" : "=f"(f.x), "=f"(f.y) : "l"(v)); return f;
}
__device__ __forceinline__ void ffma2(u64& d, u64 a, u64 b) {
    asm("fma.rn.f32x2 %0, %1, %2, %0;" : "+l"(d) : "l"(a), "l"(b));
}

// edge index accessor: handles both int32 and int64 edge_index
__device__ __forceinline__ int ld_idx(const void* ei, int pos) {
    if (g_is64) return (int)((const long long*)ei)[pos];
    return ((const int*)ei)[pos];
}

// ---------------- dtype detection ----------------
__global__ void k_detect(const unsigned* __restrict__ w, int e) {
    __shared__ unsigned red[256];
    int total = e < 4096 ? e : 4096;
    unsigned acc = 0;
    for (int i = threadIdx.x; i < total; i += 256) acc |= w[2 * i + 1];
    red[threadIdx.x] = acc;
    __syncthreads();
    for (int s = 128; s > 0; s >>= 1) {
        if (threadIdx.x < s) red[threadIdx.x] |= red[threadIdx.x + s];
        __syncthreads();
    }
    if (threadIdx.x == 0) g_is64 = (red[0] == 0u) ? 1 : 0;
}

__global__ void k_zero(int n) {
    int i = blockIdx.x * blockDim.x + threadIdx.x;
    if (i < n) { g_cnt[i] = 0; g_fill[i] = 0; }
}

__global__ void k_count(const void* __restrict__ ei, int e) {
    int i = blockIdx.x * blockDim.x + threadIdx.x;
    if (i >= e) return;
    int dst = ld_idx(ei, e + i);
    atomicAdd(&g_cnt[dst], 1);
}

// ---------------- parallel exclusive scan over g_cnt (3 kernels) ----------------
// phase 1: per-block (256-element) sums
__global__ __launch_bounds__(256) void k_partial(int n) {
    int i = blockIdx.x * 256 + threadIdx.x;
    int v = (i < n) ? g_cnt[i] : 0;
#pragma unroll
    for (int o = 16; o; o >>= 1) v += __shfl_down_sync(0xffffffffu, v, o);
    __shared__ int ws[8];
    if ((threadIdx.x & 31) == 0) ws[threadIdx.x >> 5] = v;
    __syncthreads();
    if (threadIdx.x < 8) {
        int s = ws[threadIdx.x];
#pragma unroll
        for (int o = 4; o; o >>= 1) s += __shfl_down_sync(0xffu, s, o);
        if (threadIdx.x == 0) g_bsum[blockIdx.x] = s;
    }
}

// phase 2: one block scans the (<=256) block sums -> exclusive offsets
__global__ __launch_bounds__(256) void k_scanb(int nb) {
    const int t = threadIdx.x;
    const int lane = t & 31, w = t >> 5;
    int v = (t < nb) ? g_bsum[t] : 0;
    int inc = v;
#pragma unroll
    for (int o = 1; o < 32; o <<= 1) {
        int u = __shfl_up_sync(0xffffffffu, inc, o);
        if (lane >= o) inc += u;
    }
    __shared__ int ws[8];
    if (lane == 31) ws[w] = inc;
    __syncthreads();
    if (t < 8) {
        int s = ws[t];
#pragma unroll
        for (int o = 1; o < 8; o <<= 1) {
            int u = __shfl_up_sync(0xffu, s, o);
            if (t >= o) s += u;
        }
        ws[t] = s;
    }
    __syncthreads();
    int base = (w ? ws[w - 1] : 0);
    g_boff[t] = base + inc - v;   // exclusive
}

// phase 3: intra-block exclusive scan + write rowptr & dinv
__global__ __launch_bounds__(256) void k_rowptr(int n, int e) {
    int i = blockIdx.x * 256 + threadIdx.x;
    int c = (i < n) ? g_cnt[i] : 0;
    const int lane = threadIdx.x & 31, w = threadIdx.x >> 5;
    int inc = c;
#pragma unroll
    for (int o = 1; o < 32; o <<= 1) {
        int u = __shfl_up_sync(0xffffffffu, inc, o);
        if (lane >= o) inc += u;
    }
    __shared__ int ws[8];
    if (lane == 31) ws[w] = inc;
    __syncthreads();
    if (threadIdx.x < 8) {
        int s = ws[threadIdx.x];
#pragma unroll
        for (int o = 1; o < 8; o <<= 1) {
            int u = __shfl_up_sync(0xffu, s, o);
            if (threadIdx.x >= o) s += u;
        }
        ws[threadIdx.x] = s;
    }
    __syncthreads();
    int base = g_boff[blockIdx.x] + (w ? ws[w - 1] : 0);
    if (i < n) {
        g_rowptr[i] = base + inc - c;
        g_dinv[i] = rsqrtf((float)(c + 1));   // +1 self-loop
    }
    if (i == 0) g_rowptr[n] = e;
}

// fill CSR with src index AND precomputed edge weight dinv[src]*dinv[dst]
__global__ void k_fillw(const void* __restrict__ ei, int e) {
    int i = blockIdx.x * blockDim.x + threadIdx.x;
    if (i >= e) return;
    int src = ld_idx(ei, i);
    int dst = ld_idx(ei, e + i);
    int pos = g_rowptr[dst] + atomicAdd(&g_fill[dst], 1);
    float w = g_dinv[src] * g_dinv[dst];
    g_cw[pos] = make_int2(src, __float_as_int(w));
}

// ---------------- GEMM1: h1 = x[n,512] @ W1[512,128], f32x2 inner ----------------
__global__ __launch_bounds__(256) void k_gemm1(const float* __restrict__ x,
                                               const float* __restrict__ W,
                                               int n) {
    __shared__ __align__(16) float As[32][132];  // [k][row], +4 pad
    __shared__ __align__(16) float Bs[32][128];  // [k][col]

    const int tid = threadIdx.x;
    const int tx = tid & 31;        // col group: cols tx*4 .. +3
    const int ty = tid >> 5;        // row group: rows ty*16 .. +15
    const int row0 = blockIdx.x * 128;

    u64 acc[8][4];
#pragma unroll
    for (int p = 0; p < 8; p++)
#pragma unroll
        for (int j = 0; j < 4; j++) acc[p][j] = 0ull;

    for (int k0 = 0; k0 < FIN; k0 += 32) {
#pragma unroll
        for (int p = 0; p < 4; p++) {
            int u = tid + p * 256;
            int r = u >> 3;
            int kq = (u & 7) << 2;
            int grow = row0 + r;
            float4 v = make_float4(0.f, 0.f, 0.f, 0.f);
            if (grow < n) v = *(const float4*)(x + (size_t)grow * FIN + k0 + kq);
            As[kq + 0][r] = v.x; As[kq + 1][r] = v.y;
            As[kq + 2][r] = v.z; As[kq + 3][r] = v.w;
        }
#pragma unroll
        for (int p = 0; p < 4; p++) {
            int u = tid + p * 256;
            int br = u >> 5;
            int bc = (u & 31) << 2;
            *(float4*)&Bs[br][bc] = *(const float4*)(W + (size_t)(k0 + br) * HID + bc);
        }
        __syncthreads();

#pragma unroll 4
        for (int kk = 0; kk < 32; kk++) {
            float4 bq = *(const float4*)&Bs[kk][tx << 2];
            u64 bd[4] = { pk2(bq.x, bq.x), pk2(bq.y, bq.y),
                          pk2(bq.z, bq.z), pk2(bq.w, bq.w) };
            const u64* ap = (const u64*)&As[kk][ty << 4];
            ulonglong2 A0 = *(const ulonglong2*)(ap + 0);
            ulonglong2 A1 = *(const ulonglong2*)(ap + 2);
            ulonglong2 A2 = *(const ulonglong2*)(ap + 4);
            ulonglong2 A3 = *(const ulonglong2*)(ap + 6);
            u64 a2[8] = { A0.x, A0.y, A1.x, A1.y, A2.x, A2.y, A3.x, A3.y };
#pragma unroll
            for (int p = 0; p < 8; p++)
#pragma unroll
                for (int j = 0; j < 4; j++) ffma2(acc[p][j], a2[p], bd[j]);
        }
        __syncthreads();
    }

#pragma unroll
    for (int p = 0; p < 8; p++) {
        int r_lo = row0 + (ty << 4) + 2 * p;
        float2 c0 = unpk2(acc[p][0]);
        float2 c1 = unpk2(acc[p][1]);
        float2 c2 = unpk2(acc[p][2]);
        float2 c3 = unpk2(acc[p][3]);
        if (r_lo < n)
            *(float4*)(g_h1 + (size_t)r_lo * HID + (tx << 2)) =
                make_float4(c0.x, c1.x, c2.x, c3.x);
        if (r_lo + 1 < n)
            *(float4*)(g_h1 + (size_t)(r_lo + 1) * HID + (tx << 2)) =
                make_float4(c0.y, c1.y, c2.y, c3.y);
    }
}

// ---------------- agg1: out1 = relu(b1 + sum_norm(h1)), warp per node ----------------
__global__ void k_agg1(const float* __restrict__ b1, int n) {
    int gw = (blockIdx.x * blockDim.x + threadIdx.x) >> 5;
    int lane = threadIdx.x & 31;
    if (gw >= n) return;
    const int i = gw;
    const float di = g_dinv[i];
    const float4* __restrict__ h4 = (const float4*)g_h1;

    float4 acc = h4[(size_t)i * 32 + lane];          // self-loop term
    float sw = di * di;
    acc.x *= sw; acc.y *= sw; acc.z *= sw; acc.w *= sw;

    const int rs = g_rowptr[i], re = g_rowptr[i + 1];
    for (int base = rs; base < re; base += 32) {
        int m = re - base; if (m > 32) m = 32;
        int2 cw = make_int2(0, 0);
        if (lane < m) cw = g_cw[base + lane];
#pragma unroll 4
        for (int j = 0; j < m; j++) {
            int ss = __shfl_sync(0xffffffffu, cw.x, j);
            float ww = __int_as_float(__shfl_sync(0xffffffffu, cw.y, j));
            float4 v = h4[(size_t)ss * 32 + lane];
            acc.x += v.x * ww; acc.y += v.y * ww;
            acc.z += v.z * ww; acc.w += v.w * ww;
        }
    }
    float4 bb = ((const float4*)b1)[lane];
    acc.x = fmaxf(acc.x + bb.x, 0.f);
    acc.y = fmaxf(acc.y + bb.y, 0.f);
    acc.z = fmaxf(acc.z + bb.z, 0.f);
    acc.w = fmaxf(acc.w + bb.w, 0.f);
    ((float4*)g_out1)[(size_t)i * 32 + lane] = acc;
}

// ---------------- GEMM2: h2 = out1[n,128] @ W2[128,40] ----------------
__global__ __launch_bounds__(160) void k_gemm2(const float* __restrict__ W2, int n) {
    __shared__ __align__(16) float Ws[HID * NC];   // [k][c], stride 40
    __shared__ float As[32 * 129];                 // [r][k], pad 129

    const int tid = threadIdx.x;
    for (int q = tid; q < HID * NC; q += 160) Ws[q] = W2[q];

    const int r0 = blockIdx.x * 32;
    for (int q = tid; q < 32 * HID; q += 160) {
        int r = q >> 7, k = q & 127;
        int grow = r0 + r;
        As[r * 129 + k] = (grow < n) ? g_out1[(size_t)grow * HID + k] : 0.f;
    }
    __syncthreads();

    const int r = tid & 31;
    const int cg = tid >> 5;       // 0..4
    const int c0 = cg * 8;
    float acc[8];
#pragma unroll
    for (int j = 0; j < 8; j++) acc[j] = 0.f;

#pragma unroll 4
    for (int k = 0; k < HID; k++) {
        float a = As[r * 129 + k];
        float4 w0 = *(const float4*)&Ws[k * NC + c0];
        float4 w1 = *(const float4*)&Ws[k * NC + c0 + 4];
        acc[0] += a * w0.x; acc[1] += a * w0.y; acc[2] += a * w0.z; acc[3] += a * w0.w;
        acc[4] += a * w1.x; acc[5] += a * w1.y; acc[6] += a * w1.z; acc[7] += a * w1.w;
    }
    int grow = r0 + r;
    if (grow < n) {
        *(float4*)(g_h2 + (size_t)grow * NC + c0) =
            make_float4(acc[0], acc[1], acc[2], acc[3]);
        *(float4*)(g_h2 + (size_t)grow * NC + c0 + 4) =
            make_float4(acc[4], acc[5], acc[6], acc[7]);
    }
}

// ---------------- agg2 + bias + log_softmax, warp per node ----------------
__global__ void k_agg2(const float* __restrict__ b2, float* __restrict__ out, int n) {
    int gw = (blockIdx.x * blockDim.x + threadIdx.x) >> 5;
    int lane = threadIdx.x & 31;
    if (gw >= n) return;
    const int i = gw;
    const float di = g_dinv[i];
    const float4* __restrict__ h4 = (const float4*)g_h2;

    float4 acc = make_float4(0.f, 0.f, 0.f, 0.f);
    if (lane < 10) {
        acc = h4[(size_t)i * 10 + lane];
        float sw = di * di;
        acc.x *= sw; acc.y *= sw; acc.z *= sw; acc.w *= sw;
    }
    const int rs = g_rowptr[i], re = g_rowptr[i + 1];
    for (int base = rs; base < re; base += 32) {
        int m = re - base; if (m > 32) m = 32;
        int2 cw = make_int2(0, 0);
        if (lane < m) cw = g_cw[base + lane];
#pragma unroll 4
        for (int j = 0; j < m; j++) {
            int ss = __shfl_sync(0xffffffffu, cw.x, j);
            float ww = __int_as_float(__shfl_sync(0xffffffffu, cw.y, j));
            if (lane < 10) {
                float4 v = h4[(size_t)ss * 10 + lane];
                acc.x += v.x * ww; acc.y += v.y * ww;
                acc.z += v.z * ww; acc.w += v.w * ww;
            }
        }
    }
    if (lane < 10) {
        float4 bb = ((const float4*)b2)[lane];
        acc.x += bb.x; acc.y += bb.y; acc.z += bb.z; acc.w += bb.w;
    }
    float m = (lane < 10)
        ? fmaxf(fmaxf(acc.x, acc.y), fmaxf(acc.z, acc.w)) : -3.0e38f;
#pragma unroll
    for (int off = 8; off; off >>= 1)
        m = fmaxf(m, __shfl_xor_sync(0xffffffffu, m, off, 16));
    float sum = (lane < 10)
        ? (expf(acc.x - m) + expf(acc.y - m) + expf(acc.z - m) + expf(acc.w - m))
        : 0.f;
#pragma unroll
    for (int off = 8; off; off >>= 1)
        sum += __shfl_xor_sync(0xffffffffu, sum, off, 16);
    float lse = m + logf(sum);
    if (lane < 10) {
        ((float4*)out)[(size_t)i * 10 + lane] =
            make_float4(acc.x - lse, acc.y - lse, acc.z - lse, acc.w - lse);
    }
}

// ---------------- launch ----------------
extern "C" void kernel_launch(void* const* d_in, const int* in_sizes, int n_in,
                              void* d_out, int out_size) {
    const float* x  = (const float*)d_in[0];
    const void*  ei = d_in[1];
    const float* W1 = (const float*)d_in[2];
    const float* b1 = (const float*)d_in[3];
    const float* W2 = (const float*)d_in[4];
    const float* b2 = (const float*)d_in[5];
    float* out = (float*)d_out;

    const int n = in_sizes[0] / FIN;   // 50000
    const int e = in_sizes[1] / 2;     // 800000
    const int nb = (n + 255) / 256;    // 196

    k_detect <<<1, 256>>>((const unsigned*)ei, e);
    k_zero   <<<(n + 255) / 256, 256>>>(n);
    k_count  <<<(e + 255) / 256, 256>>>(ei, e);
    k_partial<<<nb, 256>>>(n);
    k_scanb  <<<1, 256>>>(nb);
    k_rowptr <<<nb, 256>>>(n, e);
    k_fillw  <<<(e + 255) / 256, 256>>>(ei, e);
    k_gemm1  <<<(n + 127) / 128, 256>>>(x, W1, n);
    k_agg1   <<<(n + 7) / 8, 256>>>(b1, n);
    k_gemm2  <<<(n + 31) / 32, 160>>>(W2, n);
    k_agg2   <<<(n + 7) / 8, 256>>>(b2, out, n);
}

// round 6
// speedup vs baseline: 1.4583x; 1.1826x over previous
#include <cuda_runtime.h>
#include <cstdint>

#define NMAX 50000
#define EMAX 800000
#define FIN  512
#define HID  128
#define NC   40
#define NBLK 256

// ---------------- device scratch (static; no allocs allowed) ----------------
__device__ float g_h1  [NMAX * HID];
__device__ float g_out1[NMAX * HID];
__device__ float g_h2  [NMAX * NC];
__device__ float g_dinv[NMAX];
__device__ int   g_cnt [NMAX];
__device__ int   g_fill[NMAX];
__device__ int   g_rowptr[NMAX + 1];
__device__ int2  g_cw  [EMAX];
__device__ int   g_bsum[NBLK];
__device__ int   g_boff[NBLK];
__device__ int   g_is64;
// W1 transposed + bf16-split: [n][k] layout, n=128 rows, k=512
__device__ unsigned short g_wThi[HID * FIN];
__device__ unsigned short g_wTlo[HID * FIN];

typedef unsigned long long u64;

// pack two floats as bf16x2: low half = lo_elem, high half = hi_elem
__device__ __forceinline__ uint32_t cvt2(float lo_elem, float hi_elem) {
    uint32_t r;
    asm("cvt.rn.bf16x2.f32 %0, %1, %2;" : "=r"(r) : "f"(hi_elem), "f"(lo_elem));
    return r;
}

#define LDSM4(d0, d1, d2, d3, addr) \
    asm volatile("ldmatrix.sync.aligned.m8n8.x4.shared.b16 {%0,%1,%2,%3}, [%4];" \
        : "=r"(d0), "=r"(d1), "=r"(d2), "=r"(d3) : "r"(addr))

#define MMA16816(c, a, b0, b1) \
    asm volatile("mma.sync.aligned.m16n8k16.row.col.f32.bf16.bf16.f32 " \
        "{%0,%1,%2,%3},{%4,%5,%6,%7},{%8,%9},{%0,%1,%2,%3};" \
        : "+f"((c)[0]), "+f"((c)[1]), "+f"((c)[2]), "+f"((c)[3]) \
        : "r"((a)[0]), "r"((a)[1]), "r"((a)[2]), "r"((a)[3]), "r"(b0), "r"(b1))

// edge index accessor
__device__ __forceinline__ int ld_idx(const void* ei, int pos) {
    if (g_is64) return (int)((const long long*)ei)[pos];
    return ((const int*)ei)[pos];
}

// ---------------- dtype detection ----------------
__global__ void k_detect(const unsigned* __restrict__ w, int e) {
    __shared__ unsigned red[256];
    int total = e < 4096 ? e : 4096;
    unsigned acc = 0;
    for (int i = threadIdx.x; i < total; i += 256) acc |= w[2 * i + 1];
    red[threadIdx.x] = acc;
    __syncthreads();
    for (int s = 128; s > 0; s >>= 1) {
        if (threadIdx.x < s) red[threadIdx.x] |= red[threadIdx.x + s];
        __syncthreads();
    }
    if (threadIdx.x == 0) g_is64 = (red[0] == 0u) ? 1 : 0;
}

__global__ void k_zero(int n) {
    int i = blockIdx.x * blockDim.x + threadIdx.x;
    if (i < n) { g_cnt[i] = 0; g_fill[i] = 0; }
}

__global__ void k_count(const void* __restrict__ ei, int e) {
    int i = blockIdx.x * blockDim.x + threadIdx.x;
    if (i >= e) return;
    int dst = ld_idx(ei, e + i);
    atomicAdd(&g_cnt[dst], 1);
}

// ---------------- parallel exclusive scan (3 kernels) ----------------
__global__ __launch_bounds__(256) void k_partial(int n) {
    int i = blockIdx.x * 256 + threadIdx.x;
    int v = (i < n) ? g_cnt[i] : 0;
#pragma unroll
    for (int o = 16; o; o >>= 1) v += __shfl_down_sync(0xffffffffu, v, o);
    __shared__ int ws[8];
    if ((threadIdx.x & 31) == 0) ws[threadIdx.x >> 5] = v;
    __syncthreads();
    if (threadIdx.x < 8) {
        int s = ws[threadIdx.x];
#pragma unroll
        for (int o = 4; o; o >>= 1) s += __shfl_down_sync(0xffu, s, o);
        if (threadIdx.x == 0) g_bsum[blockIdx.x] = s;
    }
}

__global__ __launch_bounds__(256) void k_scanb(int nb) {
    const int t = threadIdx.x;
    const int lane = t & 31, w = t >> 5;
    int v = (t < nb) ? g_bsum[t] : 0;
    int inc = v;
#pragma unroll
    for (int o = 1; o < 32; o <<= 1) {
        int u = __shfl_up_sync(0xffffffffu, inc, o);
        if (lane >= o) inc += u;
    }
    __shared__ int ws[8];
    if (lane == 31) ws[w] = inc;
    __syncthreads();
    if (t < 8) {
        int s = ws[t];
#pragma unroll
        for (int o = 1; o < 8; o <<= 1) {
            int u = __shfl_up_sync(0xffu, s, o);
            if (t >= o) s += u;
        }
        ws[t] = s;
    }
    __syncthreads();
    int base = (w ? ws[w - 1] : 0);
    g_boff[t] = base + inc - v;
}

__global__ __launch_bounds__(256) void k_rowptr(int n, int e) {
    int i = blockIdx.x * 256 + threadIdx.x;
    int c = (i < n) ? g_cnt[i] : 0;
    const int lane = threadIdx.x & 31, w = threadIdx.x >> 5;
    int inc = c;
#pragma unroll
    for (int o = 1; o < 32; o <<= 1) {
        int u = __shfl_up_sync(0xffffffffu, inc, o);
        if (lane >= o) inc += u;
    }
    __shared__ int ws[8];
    if (lane == 31) ws[w] = inc;
    __syncthreads();
    if (threadIdx.x < 8) {
        int s = ws[threadIdx.x];
#pragma unroll
        for (int o = 1; o < 8; o <<= 1) {
            int u = __shfl_up_sync(0xffu, s, o);
            if (threadIdx.x >= o) s += u;
        }
        ws[threadIdx.x] = s;
    }
    __syncthreads();
    int base = g_boff[blockIdx.x] + (w ? ws[w - 1] : 0);
    if (i < n) {
        g_rowptr[i] = base + inc - c;
        g_dinv[i] = rsqrtf((float)(c + 1));
    }
    if (i == 0) g_rowptr[n] = e;
}

__global__ void k_fillw(const void* __restrict__ ei, int e) {
    int i = blockIdx.x * blockDim.x + threadIdx.x;
    if (i >= e) return;
    int src = ld_idx(ei, i);
    int dst = ld_idx(ei, e + i);
    int pos = g_rowptr[dst] + atomicAdd(&g_fill[dst], 1);
    float w = g_dinv[src] * g_dinv[dst];
    g_cw[pos] = make_int2(src, __float_as_int(w));
}

// ---------------- W1 prep: transpose to [n][k] + bf16 hi/lo split ----------------
__global__ void k_prepW(const float* __restrict__ W) {
    int i = blockIdx.x * 256 + threadIdx.x;
    if (i >= FIN * HID) return;
    int k = i >> 7, nn = i & 127;
    float w = W[i];
    uint32_t ph = cvt2(w, 0.f);                       // low half = bf16(w)
    float hf = __uint_as_float(ph << 16);
    float l = w - hf;
    uint32_t pl = cvt2(l, 0.f);
    g_wThi[nn * FIN + k] = (unsigned short)(ph & 0xffffu);
    g_wTlo[nn * FIN + k] = (unsigned short)(pl & 0xffffu);
}

// ---------------- GEMM1: h1 = x[n,512] @ W1[512,128] via bf16x3 mma.sync ----------
// BM=128, BN=128, BK=32, 256 threads (8 warps), warp tile 64x32.
__global__ __launch_bounds__(256, 1) void k_gemm1(const float* __restrict__ x, int n) {
    // 80B row stride (40 bf16): conflict-free ldmatrix (row*20 banks distinct mod 32)
    __shared__ __align__(16) unsigned short Ah[128][40];
    __shared__ __align__(16) unsigned short Al[128][40];
    __shared__ __align__(16) unsigned short Bh[128][40];
    __shared__ __align__(16) unsigned short Bl[128][40];

    const int tid = threadIdx.x;
    const int lane = tid & 31;
    const int wid = tid >> 5;
    const int wm = wid & 1;          // 0..1 -> m offset 64*wm
    const int wn = wid >> 1;         // 0..3 -> n offset 32*wn
    const int m_base = wm * 64;
    const int n_base = wn * 32;
    const int row0 = blockIdx.x * 128;

    const int ldrow = tid >> 1;      // 0..127
    const int half = tid & 1;        // 0..1 (16 elements each)

    float c[4][4][4];
#pragma unroll
    for (int mt = 0; mt < 4; mt++)
#pragma unroll
        for (int nt = 0; nt < 4; nt++)
#pragma unroll
            for (int q = 0; q < 4; q++) c[mt][nt][q] = 0.f;

    // precompute ldmatrix lane addressing
    const int qd = lane >> 3;        // 0..3
    const int r8 = lane & 7;
    // A: row = m_base + mt*16 + (qd&1)*8 + r8 ; col = kk + (qd>>1)*8
    const int a_r = m_base + (qd & 1) * 8 + r8;
    const int a_c = (qd >> 1) * 8;
    // B: row(n) = n_base + pp*16 + (lane>>4)*8 + r8 ; col = kk + ((lane>>3)&1)*8
    const int b_r = n_base + (lane >> 4) * 8 + r8;
    const int b_c = ((lane >> 3) & 1) * 8;

    const uint32_t sAh = (uint32_t)__cvta_generic_to_shared(&Ah[0][0]);
    const uint32_t sAl = (uint32_t)__cvta_generic_to_shared(&Al[0][0]);
    const uint32_t sBh = (uint32_t)__cvta_generic_to_shared(&Bh[0][0]);
    const uint32_t sBl = (uint32_t)__cvta_generic_to_shared(&Bl[0][0]);

    for (int k0 = 0; k0 < FIN; k0 += 32) {
        // ---- load + split A tile: rows 0..127, k0..k0+31 ----
        {
            int grow = row0 + ldrow;
            const float* xp = x + (size_t)grow * FIN + k0 + half * 16;
            uint32_t* dh = (uint32_t*)&Ah[ldrow][half * 16];
            uint32_t* dl = (uint32_t*)&Al[ldrow][half * 16];
#pragma unroll
            for (int j = 0; j < 4; j++) {
                float4 v = make_float4(0.f, 0.f, 0.f, 0.f);
                if (grow < n) v = *(const float4*)(xp + j * 4);
                uint32_t p01 = cvt2(v.x, v.y);
                uint32_t p23 = cvt2(v.z, v.w);
                float h0 = __uint_as_float(p01 << 16);
                float h1 = __uint_as_float(p01 & 0xffff0000u);
                float h2 = __uint_as_float(p23 << 16);
                float h3 = __uint_as_float(p23 & 0xffff0000u);
                uint32_t q01 = cvt2(v.x - h0, v.y - h1);
                uint32_t q23 = cvt2(v.z - h2, v.w - h3);
                dh[j * 2 + 0] = p01; dh[j * 2 + 1] = p23;
                dl[j * 2 + 0] = q01; dl[j * 2 + 1] = q23;
            }
        }
        // ---- load B tile from prepped [n][k] arrays ----
        {
            const uint4* sh = (const uint4*)(g_wThi + ldrow * FIN + k0 + half * 16);
            const uint4* sl = (const uint4*)(g_wTlo + ldrow * FIN + k0 + half * 16);
            uint4* dh = (uint4*)&Bh[ldrow][half * 16];
            uint4* dl = (uint4*)&Bl[ldrow][half * 16];
            dh[0] = sh[0]; dh[1] = sh[1];
            dl[0] = sl[0]; dl[1] = sl[1];
        }
        __syncthreads();

#pragma unroll
        for (int kk = 0; kk < 32; kk += 16) {
            uint32_t ah[4][4], al[4][4], bh[2][4], bl[2][4];
#pragma unroll
            for (int mt = 0; mt < 4; mt++) {
                uint32_t off = (uint32_t)(((a_r + mt * 16) * 40 + kk + a_c) * 2);
                LDSM4(ah[mt][0], ah[mt][1], ah[mt][2], ah[mt][3], sAh + off);
                LDSM4(al[mt][0], al[mt][1], al[mt][2], al[mt][3], sAl + off);
            }
#pragma unroll
            for (int pp = 0; pp < 2; pp++) {
                uint32_t off = (uint32_t)(((b_r + pp * 16) * 40 + kk + b_c) * 2);
                LDSM4(bh[pp][0], bh[pp][1], bh[pp][2], bh[pp][3], sBh + off);
                LDSM4(bl[pp][0], bl[pp][1], bl[pp][2], bl[pp][3], sBl + off);
            }
#pragma unroll
            for (int mt = 0; mt < 4; mt++) {
#pragma unroll
                for (int nt = 0; nt < 4; nt++) {
                    int pp = nt >> 1, ix = (nt & 1) * 2;
                    MMA16816(c[mt][nt], ah[mt], bh[pp][ix], bh[pp][ix + 1]);
                    MMA16816(c[mt][nt], al[mt], bh[pp][ix], bh[pp][ix + 1]);
                    MMA16816(c[mt][nt], ah[mt], bl[pp][ix], bl[pp][ix + 1]);
                }
            }
        }
        __syncthreads();
    }

    // ---- store C ----
#pragma unroll
    for (int mt = 0; mt < 4; mt++) {
        int row = row0 + m_base + mt * 16 + (lane >> 2);
#pragma unroll
        for (int nt = 0; nt < 4; nt++) {
            int col = n_base + nt * 8 + (lane & 3) * 2;
            if (row < n)
                *(float2*)(g_h1 + (size_t)row * HID + col) =
                    make_float2(c[mt][nt][0], c[mt][nt][1]);
            if (row + 8 < n)
                *(float2*)(g_h1 + (size_t)(row + 8) * HID + col) =
                    make_float2(c[mt][nt][2], c[mt][nt][3]);
        }
    }
}

// ---------------- agg1: out1 = relu(b1 + sum_norm(h1)), warp per node ----------------
__global__ void k_agg1(const float* __restrict__ b1, int n) {
    int gw = (blockIdx.x * blockDim.x + threadIdx.x) >> 5;
    int lane = threadIdx.x & 31;
    if (gw >= n) return;
    const int i = gw;
    const float di = g_dinv[i];
    const float4* __restrict__ h4 = (const float4*)g_h1;

    float4 acc = h4[(size_t)i * 32 + lane];
    float sw = di * di;
    acc.x *= sw; acc.y *= sw; acc.z *= sw; acc.w *= sw;

    const int rs = g_rowptr[i], re = g_rowptr[i + 1];
    for (int base = rs; base < re; base += 32) {
        int m = re - base; if (m > 32) m = 32;
        int2 cw = make_int2(0, 0);
        if (lane < m) cw = g_cw[base + lane];
#pragma unroll 4
        for (int j = 0; j < m; j++) {
            int ss = __shfl_sync(0xffffffffu, cw.x, j);
            float ww = __int_as_float(__shfl_sync(0xffffffffu, cw.y, j));
            float4 v = h4[(size_t)ss * 32 + lane];
            acc.x += v.x * ww; acc.y += v.y * ww;
            acc.z += v.z * ww; acc.w += v.w * ww;
        }
    }
    float4 bb = ((const float4*)b1)[lane];
    acc.x = fmaxf(acc.x + bb.x, 0.f);
    acc.y = fmaxf(acc.y + bb.y, 0.f);
    acc.z = fmaxf(acc.z + bb.z, 0.f);
    acc.w = fmaxf(acc.w + bb.w, 0.f);
    ((float4*)g_out1)[(size_t)i * 32 + lane] = acc;
}

// ---------------- GEMM2: h2 = out1[n,128] @ W2[128,40] ----------------
__global__ __launch_bounds__(160) void k_gemm2(const float* __restrict__ W2, int n) {
    __shared__ __align__(16) float Ws[HID * NC];
    __shared__ float As[32 * 129];

    const int tid = threadIdx.x;
    for (int q = tid; q < HID * NC; q += 160) Ws[q] = W2[q];

    const int r0 = blockIdx.x * 32;
    for (int q = tid; q < 32 * HID; q += 160) {
        int r = q >> 7, k = q & 127;
        int grow = r0 + r;
        As[r * 129 + k] = (grow < n) ? g_out1[(size_t)grow * HID + k] : 0.f;
    }
    __syncthreads();

    const int r = tid & 31;
    const int cg = tid >> 5;
    const int c0 = cg * 8;
    float acc[8];
#pragma unroll
    for (int j = 0; j < 8; j++) acc[j] = 0.f;

#pragma unroll 4
    for (int k = 0; k < HID; k++) {
        float a = As[r * 129 + k];
        float4 w0 = *(const float4*)&Ws[k * NC + c0];
        float4 w1 = *(const float4*)&Ws[k * NC + c0 + 4];
        acc[0] += a * w0.x; acc[1] += a * w0.y; acc[2] += a * w0.z; acc[3] += a * w0.w;
        acc[4] += a * w1.x; acc[5] += a * w1.y; acc[6] += a * w1.z; acc[7] += a * w1.w;
    }
    int grow = r0 + r;
    if (grow < n) {
        *(float4*)(g_h2 + (size_t)grow * NC + c0) =
            make_float4(acc[0], acc[1], acc[2], acc[3]);
        *(float4*)(g_h2 + (size_t)grow * NC + c0 + 4) =
            make_float4(acc[4], acc[5], acc[6], acc[7]);
    }
}

// ---------------- agg2 + bias + log_softmax, warp per node ----------------
__global__ void k_agg2(const float* __restrict__ b2, float* __restrict__ out, int n) {
    int gw = (blockIdx.x * blockDim.x + threadIdx.x) >> 5;
    int lane = threadIdx.x & 31;
    if (gw >= n) return;
    const int i = gw;
    const float di = g_dinv[i];
    const float4* __restrict__ h4 = (const float4*)g_h2;

    float4 acc = make_float4(0.f, 0.f, 0.f, 0.f);
    if (lane < 10) {
        acc = h4[(size_t)i * 10 + lane];
        float sw = di * di;
        acc.x *= sw; acc.y *= sw; acc.z *= sw; acc.w *= sw;
    }
    const int rs = g_rowptr[i], re = g_rowptr[i + 1];
    for (int base = rs; base < re; base += 32) {
        int m = re - base; if (m > 32) m = 32;
        int2 cw = make_int2(0, 0);
        if (lane < m) cw = g_cw[base + lane];
#pragma unroll 4
        for (int j = 0; j < m; j++) {
            int ss = __shfl_sync(0xffffffffu, cw.x, j);
            float ww = __int_as_float(__shfl_sync(0xffffffffu, cw.y, j));
            if (lane < 10) {
                float4 v = h4[(size_t)ss * 10 + lane];
                acc.x += v.x * ww; acc.y += v.y * ww;
                acc.z += v.z * ww; acc.w += v.w * ww;
            }
        }
    }
    if (lane < 10) {
        float4 bb = ((const float4*)b2)[lane];
        acc.x += bb.x; acc.y += bb.y; acc.z += bb.z; acc.w += bb.w;
    }
    float m = (lane < 10)
        ? fmaxf(fmaxf(acc.x, acc.y), fmaxf(acc.z, acc.w)) : -3.0e38f;
#pragma unroll
    for (int off = 8; off; off >>= 1)
        m = fmaxf(m, __shfl_xor_sync(0xffffffffu, m, off, 16));
    float sum = (lane < 10)
        ? (expf(acc.x - m) + expf(acc.y - m) + expf(acc.z - m) + expf(acc.w - m))
        : 0.f;
#pragma unroll
    for (int off = 8; off; off >>= 1)
        sum += __shfl_xor_sync(0xffffffffu, sum, off, 16);
    float lse = m + logf(sum);
    if (lane < 10) {
        ((float4*)out)[(size_t)i * 10 + lane] =
            make_float4(acc.x - lse, acc.y - lse, acc.z - lse, acc.w - lse);
    }
}

// ---------------- launch ----------------
extern "C" void kernel_launch(void* const* d_in, const int* in_sizes, int n_in,
                              void* d_out, int out_size) {
    const float* x  = (const float*)d_in[0];
    const void*  ei = d_in[1];
    const float* W1 = (const float*)d_in[2];
    const float* b1 = (const float*)d_in[3];
    const float* W2 = (const float*)d_in[4];
    const float* b2 = (const float*)d_in[5];
    float* out = (float*)d_out;

    const int n = in_sizes[0] / FIN;   // 50000
    const int e = in_sizes[1] / 2;     // 800000
    const int nb = (n + 255) / 256;    // 196

    k_prepW  <<<(FIN * HID + 255) / 256, 256>>>(W1);
    k_detect <<<1, 256>>>((const unsigned*)ei, e);
    k_zero   <<<(n + 255) / 256, 256>>>(n);
    k_count  <<<(e + 255) / 256, 256>>>(ei, e);
    k_partial<<<nb, 256>>>(n);
    k_scanb  <<<1, 256>>>(nb);
    k_rowptr <<<nb, 256>>>(n, e);
    k_fillw  <<<(e + 255) / 256, 256>>>(ei, e);
    k_gemm1  <<<(n + 127) / 128, 256>>>(x, n);
    k_agg1   <<<(n + 7) / 8, 256>>>(b1, n);
    k_gemm2  <<<(n + 31) / 32, 160>>>(W2, n);
    k_agg2   <<<(n + 7) / 8, 256>>>(b2, out, n);
}

// round 7
// speedup vs baseline: 1.6049x; 1.1006x over previous
#include <cuda_runtime.h>
#include <cstdint>

#define NMAX 50000
#define EMAX 800000
#define FIN  512
#define HID  128
#define NC   40
#define NBLK 256

// ---------------- device scratch (static; no allocs allowed) ----------------
__device__ float g_h1  [NMAX * HID];
__device__ float g_out1[NMAX * HID];
__device__ float g_h2  [NMAX * NC];
__device__ float g_dinv[NMAX];
__device__ int   g_cnt [NMAX];
__device__ int   g_fill[NMAX];
__device__ int   g_rowptr[NMAX + 1];
__device__ int2  g_cw  [EMAX];
__device__ int   g_bsum[NBLK];
__device__ int   g_boff[NBLK];
__device__ int   g_is64;
// W1 transposed + bf16-split: [n][k] layout, n=128 rows, k=512
__device__ unsigned short g_wThi[HID * FIN];
__device__ unsigned short g_wTlo[HID * FIN];

typedef unsigned long long u64;

// pack two floats as bf16x2: low half = lo_elem, high half = hi_elem
__device__ __forceinline__ uint32_t cvt2(float lo_elem, float hi_elem) {
    uint32_t r;
    asm("cvt.rn.bf16x2.f32 %0, %1, %2;" : "=r"(r) : "f"(hi_elem), "f"(lo_elem));
    return r;
}

#define LDSM4(d0, d1, d2, d3, addr) \
    asm volatile("ldmatrix.sync.aligned.m8n8.x4.shared.b16 {%0,%1,%2,%3}, [%4];" \
        : "=r"(d0), "=r"(d1), "=r"(d2), "=r"(d3) : "r"(addr))

#define MMA16816(c, a, b0, b1) \
    asm volatile("mma.sync.aligned.m16n8k16.row.col.f32.bf16.bf16.f32 " \
        "{%0,%1,%2,%3},{%4,%5,%6,%7},{%8,%9},{%0,%1,%2,%3};" \
        : "+f"((c)[0]), "+f"((c)[1]), "+f"((c)[2]), "+f"((c)[3]) \
        : "r"((a)[0]), "r"((a)[1]), "r"((a)[2]), "r"((a)[3]), "r"(b0), "r"(b1))

// edge index accessor
__device__ __forceinline__ int ld_idx(const void* ei, int pos) {
    if (g_is64) return (int)((const long long*)ei)[pos];
    return ((const int*)ei)[pos];
}

// ---------------- dtype detection ----------------
__global__ void k_detect(const unsigned* __restrict__ w, int e) {
    __shared__ unsigned red[256];
    int total = e < 4096 ? e : 4096;
    unsigned acc = 0;
    for (int i = threadIdx.x; i < total; i += 256) acc |= w[2 * i + 1];
    red[threadIdx.x] = acc;
    __syncthreads();
    for (int s = 128; s > 0; s >>= 1) {
        if (threadIdx.x < s) red[threadIdx.x] |= red[threadIdx.x + s];
        __syncthreads();
    }
    if (threadIdx.x == 0) g_is64 = (red[0] == 0u) ? 1 : 0;
}

__global__ void k_zero(int n) {
    int i = blockIdx.x * blockDim.x + threadIdx.x;
    if (i < n) { g_cnt[i] = 0; g_fill[i] = 0; }
}

__global__ void k_count(const void* __restrict__ ei, int e) {
    int i = blockIdx.x * blockDim.x + threadIdx.x;
    if (i >= e) return;
    int dst = ld_idx(ei, e + i);
    atomicAdd(&g_cnt[dst], 1);
}

// ---------------- parallel exclusive scan (3 kernels) ----------------
__global__ __launch_bounds__(256) void k_partial(int n) {
    int i = blockIdx.x * 256 + threadIdx.x;
    int v = (i < n) ? g_cnt[i] : 0;
#pragma unroll
    for (int o = 16; o; o >>= 1) v += __shfl_down_sync(0xffffffffu, v, o);
    __shared__ int ws[8];
    if ((threadIdx.x & 31) == 0) ws[threadIdx.x >> 5] = v;
    __syncthreads();
    if (threadIdx.x < 8) {
        int s = ws[threadIdx.x];
#pragma unroll
        for (int o = 4; o; o >>= 1) s += __shfl_down_sync(0xffu, s, o);
        if (threadIdx.x == 0) g_bsum[blockIdx.x] = s;
    }
}

__global__ __launch_bounds__(256) void k_scanb(int nb) {
    const int t = threadIdx.x;
    const int lane = t & 31, w = t >> 5;
    int v = (t < nb) ? g_bsum[t] : 0;
    int inc = v;
#pragma unroll
    for (int o = 1; o < 32; o <<= 1) {
        int u = __shfl_up_sync(0xffffffffu, inc, o);
        if (lane >= o) inc += u;
    }
    __shared__ int ws[8];
    if (lane == 31) ws[w] = inc;
    __syncthreads();
    if (t < 8) {
        int s = ws[t];
#pragma unroll
        for (int o = 1; o < 8; o <<= 1) {
            int u = __shfl_up_sync(0xffu, s, o);
            if (t >= o) s += u;
        }
        ws[t] = s;
    }
    __syncthreads();
    int base = (w ? ws[w - 1] : 0);
    g_boff[t] = base + inc - v;
}

__global__ __launch_bounds__(256) void k_rowptr(int n, int e) {
    int i = blockIdx.x * 256 + threadIdx.x;
    int c = (i < n) ? g_cnt[i] : 0;
    const int lane = threadIdx.x & 31, w = threadIdx.x >> 5;
    int inc = c;
#pragma unroll
    for (int o = 1; o < 32; o <<= 1) {
        int u = __shfl_up_sync(0xffffffffu, inc, o);
        if (lane >= o) inc += u;
    }
    __shared__ int ws[8];
    if (lane == 31) ws[w] = inc;
    __syncthreads();
    if (threadIdx.x < 8) {
        int s = ws[threadIdx.x];
#pragma unroll
        for (int o = 1; o < 8; o <<= 1) {
            int u = __shfl_up_sync(0xffu, s, o);
            if (threadIdx.x >= o) s += u;
        }
        ws[threadIdx.x] = s;
    }
    __syncthreads();
    int base = g_boff[blockIdx.x] + (w ? ws[w - 1] : 0);
    if (i < n) {
        g_rowptr[i] = base + inc - c;
        g_dinv[i] = rsqrtf((float)(c + 1));
    }
    if (i == 0) g_rowptr[n] = e;
}

__global__ void k_fillw(const void* __restrict__ ei, int e) {
    int i = blockIdx.x * blockDim.x + threadIdx.x;
    if (i >= e) return;
    int src = ld_idx(ei, i);
    int dst = ld_idx(ei, e + i);
    int pos = g_rowptr[dst] + atomicAdd(&g_fill[dst], 1);
    float w = g_dinv[src] * g_dinv[dst];
    g_cw[pos] = make_int2(src, __float_as_int(w));
}

// ---------------- W1 prep: transpose to [n][k] + bf16 hi/lo split ----------------
__global__ void k_prepW(const float* __restrict__ W) {
    int i = blockIdx.x * 256 + threadIdx.x;
    if (i >= FIN * HID) return;
    int k = i >> 7, nn = i & 127;
    float w = W[i];
    uint32_t ph = cvt2(w, 0.f);                       // low half = bf16(w)
    float hf = __uint_as_float(ph << 16);
    float l = w - hf;
    uint32_t pl = cvt2(l, 0.f);
    g_wThi[nn * FIN + k] = (unsigned short)(ph & 0xffffu);
    g_wTlo[nn * FIN + k] = (unsigned short)(pl & 0xffffu);
}

// ---------------- GEMM1: h1 = x[n,512] @ W1[512,128] via bf16x3 mma.sync ----------
__global__ __launch_bounds__(256, 1) void k_gemm1(const float* __restrict__ x, int n) {
    __shared__ __align__(16) unsigned short Ah[128][40];
    __shared__ __align__(16) unsigned short Al[128][40];
    __shared__ __align__(16) unsigned short Bh[128][40];
    __shared__ __align__(16) unsigned short Bl[128][40];

    const int tid = threadIdx.x;
    const int lane = tid & 31;
    const int wid = tid >> 5;
    const int wm = wid & 1;
    const int wn = wid >> 1;
    const int m_base = wm * 64;
    const int n_base = wn * 32;
    const int row0 = blockIdx.x * 128;

    const int ldrow = tid >> 1;
    const int half = tid & 1;

    float c[4][4][4];
#pragma unroll
    for (int mt = 0; mt < 4; mt++)
#pragma unroll
        for (int nt = 0; nt < 4; nt++)
#pragma unroll
            for (int q = 0; q < 4; q++) c[mt][nt][q] = 0.f;

    const int qd = lane >> 3;
    const int r8 = lane & 7;
    const int a_r = m_base + (qd & 1) * 8 + r8;
    const int a_c = (qd >> 1) * 8;
    const int b_r = n_base + (lane >> 4) * 8 + r8;
    const int b_c = ((lane >> 3) & 1) * 8;

    const uint32_t sAh = (uint32_t)__cvta_generic_to_shared(&Ah[0][0]);
    const uint32_t sAl = (uint32_t)__cvta_generic_to_shared(&Al[0][0]);
    const uint32_t sBh = (uint32_t)__cvta_generic_to_shared(&Bh[0][0]);
    const uint32_t sBl = (uint32_t)__cvta_generic_to_shared(&Bl[0][0]);

    for (int k0 = 0; k0 < FIN; k0 += 32) {
        {
            int grow = row0 + ldrow;
            const float* xp = x + (size_t)grow * FIN + k0 + half * 16;
            uint32_t* dh = (uint32_t*)&Ah[ldrow][half * 16];
            uint32_t* dl = (uint32_t*)&Al[ldrow][half * 16];
#pragma unroll
            for (int j = 0; j < 4; j++) {
                float4 v = make_float4(0.f, 0.f, 0.f, 0.f);
                if (grow < n) v = *(const float4*)(xp + j * 4);
                uint32_t p01 = cvt2(v.x, v.y);
                uint32_t p23 = cvt2(v.z, v.w);
                float h0 = __uint_as_float(p01 << 16);
                float h1 = __uint_as_float(p01 & 0xffff0000u);
                float h2 = __uint_as_float(p23 << 16);
                float h3 = __uint_as_float(p23 & 0xffff0000u);
                uint32_t q01 = cvt2(v.x - h0, v.y - h1);
                uint32_t q23 = cvt2(v.z - h2, v.w - h3);
                dh[j * 2 + 0] = p01; dh[j * 2 + 1] = p23;
                dl[j * 2 + 0] = q01; dl[j * 2 + 1] = q23;
            }
        }
        {
            const uint4* sh = (const uint4*)(g_wThi + ldrow * FIN + k0 + half * 16);
            const uint4* sl = (const uint4*)(g_wTlo + ldrow * FIN + k0 + half * 16);
            uint4* dh = (uint4*)&Bh[ldrow][half * 16];
            uint4* dl = (uint4*)&Bl[ldrow][half * 16];
            dh[0] = sh[0]; dh[1] = sh[1];
            dl[0] = sl[0]; dl[1] = sl[1];
        }
        __syncthreads();

#pragma unroll
        for (int kk = 0; kk < 32; kk += 16) {
            uint32_t ah[4][4], al[4][4], bh[2][4], bl[2][4];
#pragma unroll
            for (int mt = 0; mt < 4; mt++) {
                uint32_t off = (uint32_t)(((a_r + mt * 16) * 40 + kk + a_c) * 2);
                LDSM4(ah[mt][0], ah[mt][1], ah[mt][2], ah[mt][3], sAh + off);
                LDSM4(al[mt][0], al[mt][1], al[mt][2], al[mt][3], sAl + off);
            }
#pragma unroll
            for (int pp = 0; pp < 2; pp++) {
                uint32_t off = (uint32_t)(((b_r + pp * 16) * 40 + kk + b_c) * 2);
                LDSM4(bh[pp][0], bh[pp][1], bh[pp][2], bh[pp][3], sBh + off);
                LDSM4(bl[pp][0], bl[pp][1], bl[pp][2], bl[pp][3], sBl + off);
            }
#pragma unroll
            for (int mt = 0; mt < 4; mt++) {
#pragma unroll
                for (int nt = 0; nt < 4; nt++) {
                    int pp = nt >> 1, ix = (nt & 1) * 2;
                    MMA16816(c[mt][nt], ah[mt], bh[pp][ix], bh[pp][ix + 1]);
                    MMA16816(c[mt][nt], al[mt], bh[pp][ix], bh[pp][ix + 1]);
                    MMA16816(c[mt][nt], ah[mt], bl[pp][ix], bl[pp][ix + 1]);
                }
            }
        }
        __syncthreads();
    }

#pragma unroll
    for (int mt = 0; mt < 4; mt++) {
        int row = row0 + m_base + mt * 16 + (lane >> 2);
#pragma unroll
        for (int nt = 0; nt < 4; nt++) {
            int col = n_base + nt * 8 + (lane & 3) * 2;
            if (row < n)
                *(float2*)(g_h1 + (size_t)row * HID + col) =
                    make_float2(c[mt][nt][0], c[mt][nt][1]);
            if (row + 8 < n)
                *(float2*)(g_h1 + (size_t)(row + 8) * HID + col) =
                    make_float2(c[mt][nt][2], c[mt][nt][3]);
        }
    }
}

// ---------------- agg1: out1 = relu(b1 + sum_norm(h1)), warp per node ----------------
__global__ void k_agg1(const float* __restrict__ b1, int n) {
    int gw = (blockIdx.x * blockDim.x + threadIdx.x) >> 5;
    int lane = threadIdx.x & 31;
    if (gw >= n) return;
    const int i = gw;
    const float di = g_dinv[i];
    const float4* __restrict__ h4 = (const float4*)g_h1;

    float4 acc = h4[(size_t)i * 32 + lane];
    float sw = di * di;
    acc.x *= sw; acc.y *= sw; acc.z *= sw; acc.w *= sw;

    const int rs = g_rowptr[i], re = g_rowptr[i + 1];
    for (int base = rs; base < re; base += 32) {
        int m = re - base; if (m > 32) m = 32;
        int2 cw = make_int2(0, 0);
        if (lane < m) cw = g_cw[base + lane];
#pragma unroll 4
        for (int j = 0; j < m; j++) {
            int ss = __shfl_sync(0xffffffffu, cw.x, j);
            float ww = __int_as_float(__shfl_sync(0xffffffffu, cw.y, j));
            float4 v = h4[(size_t)ss * 32 + lane];
            acc.x += v.x * ww; acc.y += v.y * ww;
            acc.z += v.z * ww; acc.w += v.w * ww;
        }
    }
    float4 bb = ((const float4*)b1)[lane];
    acc.x = fmaxf(acc.x + bb.x, 0.f);
    acc.y = fmaxf(acc.y + bb.y, 0.f);
    acc.z = fmaxf(acc.z + bb.z, 0.f);
    acc.w = fmaxf(acc.w + bb.w, 0.f);
    ((float4*)g_out1)[(size_t)i * 32 + lane] = acc;
}

// ---------------- GEMM2: h2 = out1[n,128] @ W2[128,40] ----------------
__global__ __launch_bounds__(160) void k_gemm2(const float* __restrict__ W2, int n) {
    __shared__ __align__(16) float Ws[HID * NC];
    __shared__ float As[32 * 129];

    const int tid = threadIdx.x;
    for (int q = tid; q < HID * NC; q += 160) Ws[q] = W2[q];

    const int r0 = blockIdx.x * 32;
    for (int q = tid; q < 32 * HID; q += 160) {
        int r = q >> 7, k = q & 127;
        int grow = r0 + r;
        As[r * 129 + k] = (grow < n) ? g_out1[(size_t)grow * HID + k] : 0.f;
    }
    __syncthreads();

    const int r = tid & 31;
    const int cg = tid >> 5;
    const int c0 = cg * 8;
    float acc[8];
#pragma unroll
    for (int j = 0; j < 8; j++) acc[j] = 0.f;

#pragma unroll 4
    for (int k = 0; k < HID; k++) {
        float a = As[r * 129 + k];
        float4 w0 = *(const float4*)&Ws[k * NC + c0];
        float4 w1 = *(const float4*)&Ws[k * NC + c0 + 4];
        acc[0] += a * w0.x; acc[1] += a * w0.y; acc[2] += a * w0.z; acc[3] += a * w0.w;
        acc[4] += a * w1.x; acc[5] += a * w1.y; acc[6] += a * w1.z; acc[7] += a * w1.w;
    }
    int grow = r0 + r;
    if (grow < n) {
        *(float4*)(g_h2 + (size_t)grow * NC + c0) =
            make_float4(acc[0], acc[1], acc[2], acc[3]);
        *(float4*)(g_h2 + (size_t)grow * NC + c0 + 4) =
            make_float4(acc[4], acc[5], acc[6], acc[7]);
    }
}

// ---------------- agg2 + bias + log_softmax, warp per node ----------------
__global__ void k_agg2(const float* __restrict__ b2, float* __restrict__ out, int n) {
    int gw = (blockIdx.x * blockDim.x + threadIdx.x) >> 5;
    int lane = threadIdx.x & 31;
    if (gw >= n) return;
    const int i = gw;
    const float di = g_dinv[i];
    const float4* __restrict__ h4 = (const float4*)g_h2;

    float4 acc = make_float4(0.f, 0.f, 0.f, 0.f);
    if (lane < 10) {
        acc = h4[(size_t)i * 10 + lane];
        float sw = di * di;
        acc.x *= sw; acc.y *= sw; acc.z *= sw; acc.w *= sw;
    }
    const int rs = g_rowptr[i], re = g_rowptr[i + 1];
    for (int base = rs; base < re; base += 32) {
        int m = re - base; if (m > 32) m = 32;
        int2 cw = make_int2(0, 0);
        if (lane < m) cw = g_cw[base + lane];
#pragma unroll 4
        for (int j = 0; j < m; j++) {
            int ss = __shfl_sync(0xffffffffu, cw.x, j);
            float ww = __int_as_float(__shfl_sync(0xffffffffu, cw.y, j));
            if (lane < 10) {
                float4 v = h4[(size_t)ss * 10 + lane];
                acc.x += v.x * ww; acc.y += v.y * ww;
                acc.z += v.z * ww; acc.w += v.w * ww;
            }
        }
    }
    if (lane < 10) {
        float4 bb = ((const float4*)b2)[lane];
        acc.x += bb.x; acc.y += bb.y; acc.z += bb.z; acc.w += bb.w;
    }
    float m = (lane < 10)
        ? fmaxf(fmaxf(acc.x, acc.y), fmaxf(acc.z, acc.w)) : -3.0e38f;
#pragma unroll
    for (int off = 8; off; off >>= 1)
        m = fmaxf(m, __shfl_xor_sync(0xffffffffu, m, off, 16));
    float sum = (lane < 10)
        ? (expf(acc.x - m) + expf(acc.y - m) + expf(acc.z - m) + expf(acc.w - m))
        : 0.f;
#pragma unroll
    for (int off = 8; off; off >>= 1)
        sum += __shfl_xor_sync(0xffffffffu, sum, off, 16);
    float lse = m + logf(sum);
    if (lane < 10) {
        ((float4*)out)[(size_t)i * 10 + lane] =
            make_float4(acc.x - lse, acc.y - lse, acc.z - lse, acc.w - lse);
    }
}

// ---------------- launch: fork-join overlap of CSR build with GEMM1 --------------
extern "C" void kernel_launch(void* const* d_in, const int* in_sizes, int n_in,
                              void* d_out, int out_size) {
    const float* x  = (const float*)d_in[0];
    const void*  ei = d_in[1];
    const float* W1 = (const float*)d_in[2];
    const float* b1 = (const float*)d_in[3];
    const float* W2 = (const float*)d_in[4];
    const float* b2 = (const float*)d_in[5];
    float* out = (float*)d_out;

    const int n = in_sizes[0] / FIN;   // 50000
    const int e = in_sizes[1] / 2;     // 800000
    const int nb = (n + 255) / 256;    // 196

    // Side stream + fork/join events. kernel_launch is only invoked for the
    // correctness call and the capture call (replays re-run the graph, not this
    // function), so creating-and-leaking these host-side handles is safe and
    // avoids destroying resources that are referenced by an active capture.
    cudaStream_t s2;
    cudaStreamCreateWithFlags(&s2, cudaStreamNonBlocking);
    cudaEvent_t evFork, evJoin;
    cudaEventCreateWithFlags(&evFork, cudaEventDisableTiming);
    cudaEventCreateWithFlags(&evJoin, cudaEventDisableTiming);

    // fork: side stream builds the CSR (depends only on edge_index)
    cudaEventRecord(evFork, 0);
    cudaStreamWaitEvent(s2, evFork, 0);

    k_detect <<<1, 256, 0, s2>>>((const unsigned*)ei, e);
    k_zero   <<<(n + 255) / 256, 256, 0, s2>>>(n);
    k_count  <<<(e + 255) / 256, 256, 0, s2>>>(ei, e);
    k_partial<<<nb, 256, 0, s2>>>(n);
    k_scanb  <<<1, 256, 0, s2>>>(nb);
    k_rowptr <<<nb, 256, 0, s2>>>(n, e);
    k_fillw  <<<(e + 255) / 256, 256, 0, s2>>>(ei, e);
    cudaEventRecord(evJoin, s2);

    // main stream: dense path (depends only on x, W1)
    k_prepW  <<<(FIN * HID + 255) / 256, 256>>>(W1);
    k_gemm1  <<<(n + 127) / 128, 256>>>(x, n);

    // join: aggregation needs both CSR and h1
    cudaStreamWaitEvent(0, evJoin, 0);
    k_agg1   <<<(n + 7) / 8, 256>>>(b1, n);
    k_gemm2  <<<(n + 31) / 32, 160>>>(W2, n);
    k_agg2   <<<(n + 7) / 8, 256>>>(b2, out, n);
}

// round 8
// speedup vs baseline: 1.8700x; 1.1652x over previous
#include <cuda_runtime.h>
#include <cstdint>

#define NMAX 50000
#define EMAX 800000
#define FIN  512
#define HID  128
#define NC   40
#define NBLK 256

// ---------------- device scratch (static; no allocs allowed) ----------------
__device__ float g_h1  [NMAX * HID];
__device__ float g_out1[NMAX * HID];
__device__ float g_h2  [NMAX * NC];
__device__ float g_dinv[NMAX];
__device__ int   g_cnt [NMAX];
__device__ int   g_fill[NMAX];
__device__ int   g_rowptr[NMAX + 1];
__device__ int2  g_cw  [EMAX];
__device__ int   g_bsum[NBLK];
__device__ int   g_boff[NBLK];
__device__ int   g_is64;
// W1 transposed + bf16-split: [n][k] layout, n=128 rows, k=512
__device__ unsigned short g_wThi[HID * FIN];
__device__ unsigned short g_wTlo[HID * FIN];

typedef unsigned long long u64;

// pack two floats as bf16x2: low half = lo_elem, high half = hi_elem
__device__ __forceinline__ uint32_t cvt2(float lo_elem, float hi_elem) {
    uint32_t r;
    asm("cvt.rn.bf16x2.f32 %0, %1, %2;" : "=r"(r) : "f"(hi_elem), "f"(lo_elem));
    return r;
}

#define LDSM4(d0, d1, d2, d3, addr) \
    asm volatile("ldmatrix.sync.aligned.m8n8.x4.shared.b16 {%0,%1,%2,%3}, [%4];" \
        : "=r"(d0), "=r"(d1), "=r"(d2), "=r"(d3) : "r"(addr))

#define MMA16816(c, a, b0, b1) \
    asm volatile("mma.sync.aligned.m16n8k16.row.col.f32.bf16.bf16.f32 " \
        "{%0,%1,%2,%3},{%4,%5,%6,%7},{%8,%9},{%0,%1,%2,%3};" \
        : "+f"((c)[0]), "+f"((c)[1]), "+f"((c)[2]), "+f"((c)[3]) \
        : "r"((a)[0]), "r"((a)[1]), "r"((a)[2]), "r"((a)[3]), "r"(b0), "r"(b1))

// edge index accessor
__device__ __forceinline__ int ld_idx(const void* ei, int pos) {
    if (g_is64) return (int)((const long long*)ei)[pos];
    return ((const int*)ei)[pos];
}

// ---------------- dtype detection ----------------
__global__ void k_detect(const unsigned* __restrict__ w, int e) {
    __shared__ unsigned red[256];
    int total = e < 4096 ? e : 4096;
    unsigned acc = 0;
    for (int i = threadIdx.x; i < total; i += 256) acc |= w[2 * i + 1];
    red[threadIdx.x] = acc;
    __syncthreads();
    for (int s = 128; s > 0; s >>= 1) {
        if (threadIdx.x < s) red[threadIdx.x] |= red[threadIdx.x + s];
        __syncthreads();
    }
    if (threadIdx.x == 0) g_is64 = (red[0] == 0u) ? 1 : 0;
}

__global__ void k_zero(int n) {
    int i = blockIdx.x * blockDim.x + threadIdx.x;
    if (i < n) { g_cnt[i] = 0; g_fill[i] = 0; }
}

__global__ void k_count(const void* __restrict__ ei, int e) {
    int i = blockIdx.x * blockDim.x + threadIdx.x;
    if (i >= e) return;
    int dst = ld_idx(ei, e + i);
    atomicAdd(&g_cnt[dst], 1);
}

// ---------------- parallel exclusive scan (3 kernels) ----------------
__global__ __launch_bounds__(256) void k_partial(int n) {
    int i = blockIdx.x * 256 + threadIdx.x;
    int v = (i < n) ? g_cnt[i] : 0;
#pragma unroll
    for (int o = 16; o; o >>= 1) v += __shfl_down_sync(0xffffffffu, v, o);
    __shared__ int ws[8];
    if ((threadIdx.x & 31) == 0) ws[threadIdx.x >> 5] = v;
    __syncthreads();
    if (threadIdx.x < 8) {
        int s = ws[threadIdx.x];
#pragma unroll
        for (int o = 4; o; o >>= 1) s += __shfl_down_sync(0xffu, s, o);
        if (threadIdx.x == 0) g_bsum[blockIdx.x] = s;
    }
}

__global__ __launch_bounds__(256) void k_scanb(int nb) {
    const int t = threadIdx.x;
    const int lane = t & 31, w = t >> 5;
    int v = (t < nb) ? g_bsum[t] : 0;
    int inc = v;
#pragma unroll
    for (int o = 1; o < 32; o <<= 1) {
        int u = __shfl_up_sync(0xffffffffu, inc, o);
        if (lane >= o) inc += u;
    }
    __shared__ int ws[8];
    if (lane == 31) ws[w] = inc;
    __syncthreads();
    if (t < 8) {
        int s = ws[t];
#pragma unroll
        for (int o = 1; o < 8; o <<= 1) {
            int u = __shfl_up_sync(0xffu, s, o);
            if (t >= o) s += u;
        }
        ws[t] = s;
    }
    __syncthreads();
    int base = (w ? ws[w - 1] : 0);
    g_boff[t] = base + inc - v;
}

__global__ __launch_bounds__(256) void k_rowptr(int n, int e) {
    int i = blockIdx.x * 256 + threadIdx.x;
    int c = (i < n) ? g_cnt[i] : 0;
    const int lane = threadIdx.x & 31, w = threadIdx.x >> 5;
    int inc = c;
#pragma unroll
    for (int o = 1; o < 32; o <<= 1) {
        int u = __shfl_up_sync(0xffffffffu, inc, o);
        if (lane >= o) inc += u;
    }
    __shared__ int ws[8];
    if (lane == 31) ws[w] = inc;
    __syncthreads();
    if (threadIdx.x < 8) {
        int s = ws[threadIdx.x];
#pragma unroll
        for (int o = 1; o < 8; o <<= 1) {
            int u = __shfl_up_sync(0xffu, s, o);
            if (threadIdx.x >= o) s += u;
        }
        ws[threadIdx.x] = s;
    }
    __syncthreads();
    int base = g_boff[blockIdx.x] + (w ? ws[w - 1] : 0);
    if (i < n) {
        g_rowptr[i] = base + inc - c;
        g_dinv[i] = rsqrtf((float)(c + 1));
    }
    if (i == 0) g_rowptr[n] = e;
}

__global__ void k_fillw(const void* __restrict__ ei, int e) {
    int i = blockIdx.x * blockDim.x + threadIdx.x;
    if (i >= e) return;
    int src = ld_idx(ei, i);
    int dst = ld_idx(ei, e + i);
    int pos = g_rowptr[dst] + atomicAdd(&g_fill[dst], 1);
    float w = g_dinv[src] * g_dinv[dst];
    g_cw[pos] = make_int2(src, __float_as_int(w));
}

// ---------------- W1 prep: transpose to [n][k] + bf16 hi/lo split ----------------
__global__ void k_prepW(const float* __restrict__ W) {
    int i = blockIdx.x * 256 + threadIdx.x;
    if (i >= FIN * HID) return;
    int k = i >> 7, nn = i & 127;
    float w = W[i];
    uint32_t ph = cvt2(w, 0.f);
    float hf = __uint_as_float(ph << 16);
    float l = w - hf;
    uint32_t pl = cvt2(l, 0.f);
    g_wThi[nn * FIN + k] = (unsigned short)(ph & 0xffffu);
    g_wTlo[nn * FIN + k] = (unsigned short)(pl & 0xffffu);
}

// ---------------- GEMM1: h1 = x[n,512] @ W1[512,128] via bf16x3 mma.sync ----------
// Software-pipelined: register prefetch of next K-tile overlaps LDG with MMA.
__global__ __launch_bounds__(256, 1) void k_gemm1(const float* __restrict__ x, int n) {
    __shared__ __align__(16) unsigned short Ah[128][40];
    __shared__ __align__(16) unsigned short Al[128][40];
    __shared__ __align__(16) unsigned short Bh[128][40];
    __shared__ __align__(16) unsigned short Bl[128][40];

    const int tid = threadIdx.x;
    const int lane = tid & 31;
    const int wid = tid >> 5;
    const int wm = wid & 1;
    const int wn = wid >> 1;
    const int m_base = wm * 64;
    const int n_base = wn * 32;
    const int row0 = blockIdx.x * 128;

    const int ldrow = tid >> 1;
    const int half = tid & 1;

    float c[4][4][4];
#pragma unroll
    for (int mt = 0; mt < 4; mt++)
#pragma unroll
        for (int nt = 0; nt < 4; nt++)
#pragma unroll
            for (int q = 0; q < 4; q++) c[mt][nt][q] = 0.f;

    const int qd = lane >> 3;
    const int r8 = lane & 7;
    const int a_r = m_base + (qd & 1) * 8 + r8;
    const int a_c = (qd >> 1) * 8;
    const int b_r = n_base + (lane >> 4) * 8 + r8;
    const int b_c = ((lane >> 3) & 1) * 8;

    const uint32_t sAh = (uint32_t)__cvta_generic_to_shared(&Ah[0][0]);
    const uint32_t sAl = (uint32_t)__cvta_generic_to_shared(&Al[0][0]);
    const uint32_t sBh = (uint32_t)__cvta_generic_to_shared(&Bh[0][0]);
    const uint32_t sBl = (uint32_t)__cvta_generic_to_shared(&Bl[0][0]);

    // prefetch staging
    const bool rowOK = (row0 + ldrow) < n;
    const float* xbase = x + (size_t)(row0 + ldrow) * FIN + half * 16;
    const unsigned short* whb = g_wThi + ldrow * FIN + half * 16;
    const unsigned short* wlb = g_wTlo + ldrow * FIN + half * 16;

    float4 av[4];
    uint4 bvh[2], bvl[2];

#define LOADG(K0) do { \
        _Pragma("unroll") \
        for (int j = 0; j < 4; j++) \
            av[j] = rowOK ? *(const float4*)(xbase + (K0) + j * 4) \
                          : make_float4(0.f, 0.f, 0.f, 0.f); \
        bvh[0] = *(const uint4*)(whb + (K0)); \
        bvh[1] = *(const uint4*)(whb + (K0) + 8); \
        bvl[0] = *(const uint4*)(wlb + (K0)); \
        bvl[1] = *(const uint4*)(wlb + (K0) + 8); \
    } while (0)

    LOADG(0);

#pragma unroll 1
    for (int it = 0; it < FIN / 32; it++) {
        // ---- convert + store current tile to smem (consumes regs) ----
        {
            uint32_t* dh = (uint32_t*)&Ah[ldrow][half * 16];
            uint32_t* dl = (uint32_t*)&Al[ldrow][half * 16];
#pragma unroll
            for (int j = 0; j < 4; j++) {
                float4 v = av[j];
                uint32_t p01 = cvt2(v.x, v.y);
                uint32_t p23 = cvt2(v.z, v.w);
                float h0 = __uint_as_float(p01 << 16);
                float h1 = __uint_as_float(p01 & 0xffff0000u);
                float h2 = __uint_as_float(p23 << 16);
                float h3 = __uint_as_float(p23 & 0xffff0000u);
                uint32_t q01 = cvt2(v.x - h0, v.y - h1);
                uint32_t q23 = cvt2(v.z - h2, v.w - h3);
                dh[j * 2 + 0] = p01; dh[j * 2 + 1] = p23;
                dl[j * 2 + 0] = q01; dl[j * 2 + 1] = q23;
            }
            uint4* bdh = (uint4*)&Bh[ldrow][half * 16];
            uint4* bdl = (uint4*)&Bl[ldrow][half * 16];
            bdh[0] = bvh[0]; bdh[1] = bvh[1];
            bdl[0] = bvl[0]; bdl[1] = bvl[1];
        }
        // ---- issue next tile's LDGs; latency hides under sync + MMA ----
        if (it + 1 < FIN / 32) LOADG((it + 1) * 32);
        __syncthreads();

#pragma unroll
        for (int kk = 0; kk < 32; kk += 16) {
            uint32_t ah[4][4], al[4][4], bh[2][4], bl[2][4];
#pragma unroll
            for (int mt = 0; mt < 4; mt++) {
                uint32_t off = (uint32_t)(((a_r + mt * 16) * 40 + kk + a_c) * 2);
                LDSM4(ah[mt][0], ah[mt][1], ah[mt][2], ah[mt][3], sAh + off);
                LDSM4(al[mt][0], al[mt][1], al[mt][2], al[mt][3], sAl + off);
            }
#pragma unroll
            for (int pp = 0; pp < 2; pp++) {
                uint32_t off = (uint32_t)(((b_r + pp * 16) * 40 + kk + b_c) * 2);
                LDSM4(bh[pp][0], bh[pp][1], bh[pp][2], bh[pp][3], sBh + off);
                LDSM4(bl[pp][0], bl[pp][1], bl[pp][2], bl[pp][3], sBl + off);
            }
#pragma unroll
            for (int mt = 0; mt < 4; mt++) {
#pragma unroll
                for (int nt = 0; nt < 4; nt++) {
                    int pp = nt >> 1, ix = (nt & 1) * 2;
                    MMA16816(c[mt][nt], ah[mt], bh[pp][ix], bh[pp][ix + 1]);
                    MMA16816(c[mt][nt], al[mt], bh[pp][ix], bh[pp][ix + 1]);
                    MMA16816(c[mt][nt], ah[mt], bl[pp][ix], bl[pp][ix + 1]);
                }
            }
        }
        __syncthreads();
    }
#undef LOADG

#pragma unroll
    for (int mt = 0; mt < 4; mt++) {
        int row = row0 + m_base + mt * 16 + (lane >> 2);
#pragma unroll
        for (int nt = 0; nt < 4; nt++) {
            int col = n_base + nt * 8 + (lane & 3) * 2;
            if (row < n)
                *(float2*)(g_h1 + (size_t)row * HID + col) =
                    make_float2(c[mt][nt][0], c[mt][nt][1]);
            if (row + 8 < n)
                *(float2*)(g_h1 + (size_t)(row + 8) * HID + col) =
                    make_float2(c[mt][nt][2], c[mt][nt][3]);
        }
    }
}

// ---------------- agg1: out1 = relu(b1 + sum_norm(h1)), warp per node ----------------
__global__ void k_agg1(const float* __restrict__ b1, int n) {
    int gw = (blockIdx.x * blockDim.x + threadIdx.x) >> 5;
    int lane = threadIdx.x & 31;
    if (gw >= n) return;
    const int i = gw;
    const float di = g_dinv[i];
    const float4* __restrict__ h4 = (const float4*)g_h1;

    float4 acc = h4[(size_t)i * 32 + lane];
    float sw = di * di;
    acc.x *= sw; acc.y *= sw; acc.z *= sw; acc.w *= sw;

    const int rs = g_rowptr[i], re = g_rowptr[i + 1];
    for (int base = rs; base < re; base += 32) {
        int m = re - base; if (m > 32) m = 32;
        int2 cw = make_int2(0, 0);
        if (lane < m) cw = g_cw[base + lane];
#pragma unroll 4
        for (int j = 0; j < m; j++) {
            int ss = __shfl_sync(0xffffffffu, cw.x, j);
            float ww = __int_as_float(__shfl_sync(0xffffffffu, cw.y, j));
            float4 v = h4[(size_t)ss * 32 + lane];
            acc.x += v.x * ww; acc.y += v.y * ww;
            acc.z += v.z * ww; acc.w += v.w * ww;
        }
    }
    float4 bb = ((const float4*)b1)[lane];
    acc.x = fmaxf(acc.x + bb.x, 0.f);
    acc.y = fmaxf(acc.y + bb.y, 0.f);
    acc.z = fmaxf(acc.z + bb.z, 0.f);
    acc.w = fmaxf(acc.w + bb.w, 0.f);
    ((float4*)g_out1)[(size_t)i * 32 + lane] = acc;
}

// ---------------- GEMM2: h2 = out1[n,128] @ W2[128,40] ----------------
__global__ __launch_bounds__(160) void k_gemm2(const float* __restrict__ W2, int n) {
    __shared__ __align__(16) float Ws[HID * NC];
    __shared__ float As[32 * 129];

    const int tid = threadIdx.x;
    for (int q = tid; q < HID * NC; q += 160) Ws[q] = W2[q];

    const int r0 = blockIdx.x * 32;
    for (int q = tid; q < 32 * HID; q += 160) {
        int r = q >> 7, k = q & 127;
        int grow = r0 + r;
        As[r * 129 + k] = (grow < n) ? g_out1[(size_t)grow * HID + k] : 0.f;
    }
    __syncthreads();

    const int r = tid & 31;
    const int cg = tid >> 5;
    const int c0 = cg * 8;
    float acc[8];
#pragma unroll
    for (int j = 0; j < 8; j++) acc[j] = 0.f;

#pragma unroll 4
    for (int k = 0; k < HID; k++) {
        float a = As[r * 129 + k];
        float4 w0 = *(const float4*)&Ws[k * NC + c0];
        float4 w1 = *(const float4*)&Ws[k * NC + c0 + 4];
        acc[0] += a * w0.x; acc[1] += a * w0.y; acc[2] += a * w0.z; acc[3] += a * w0.w;
        acc[4] += a * w1.x; acc[5] += a * w1.y; acc[6] += a * w1.z; acc[7] += a * w1.w;
    }
    int grow = r0 + r;
    if (grow < n) {
        *(float4*)(g_h2 + (size_t)grow * NC + c0) =
            make_float4(acc[0], acc[1], acc[2], acc[3]);
        *(float4*)(g_h2 + (size_t)grow * NC + c0 + 4) =
            make_float4(acc[4], acc[5], acc[6], acc[7]);
    }
}

// ---------------- agg2 + bias + log_softmax, warp per node ----------------
__global__ void k_agg2(const float* __restrict__ b2, float* __restrict__ out, int n) {
    int gw = (blockIdx.x * blockDim.x + threadIdx.x) >> 5;
    int lane = threadIdx.x & 31;
    if (gw >= n) return;
    const int i = gw;
    const float di = g_dinv[i];
    const float4* __restrict__ h4 = (const float4*)g_h2;

    float4 acc = make_float4(0.f, 0.f, 0.f, 0.f);
    if (lane < 10) {
        acc = h4[(size_t)i * 10 + lane];
        float sw = di * di;
        acc.x *= sw; acc.y *= sw; acc.z *= sw; acc.w *= sw;
    }
    const int rs = g_rowptr[i], re = g_rowptr[i + 1];
    for (int base = rs; base < re; base += 32) {
        int m = re - base; if (m > 32) m = 32;
        int2 cw = make_int2(0, 0);
        if (lane < m) cw = g_cw[base + lane];
#pragma unroll 4
        for (int j = 0; j < m; j++) {
            int ss = __shfl_sync(0xffffffffu, cw.x, j);
            float ww = __int_as_float(__shfl_sync(0xffffffffu, cw.y, j));
            if (lane < 10) {
                float4 v = h4[(size_t)ss * 10 + lane];
                acc.x += v.x * ww; acc.y += v.y * ww;
                acc.z += v.z * ww; acc.w += v.w * ww;
            }
        }
    }
    if (lane < 10) {
        float4 bb = ((const float4*)b2)[lane];
        acc.x += bb.x; acc.y += bb.y; acc.z += bb.z; acc.w += bb.w;
    }
    float m = (lane < 10)
        ? fmaxf(fmaxf(acc.x, acc.y), fmaxf(acc.z, acc.w)) : -3.0e38f;
#pragma unroll
    for (int off = 8; off; off >>= 1)
        m = fmaxf(m, __shfl_xor_sync(0xffffffffu, m, off, 16));
    float sum = (lane < 10)
        ? (expf(acc.x - m) + expf(acc.y - m) + expf(acc.z - m) + expf(acc.w - m))
        : 0.f;
#pragma unroll
    for (int off = 8; off; off >>= 1)
        sum += __shfl_xor_sync(0xffffffffu, sum, off, 16);
    float lse = m + logf(sum);
    if (lane < 10) {
        ((float4*)out)[(size_t)i * 10 + lane] =
            make_float4(acc.x - lse, acc.y - lse, acc.z - lse, acc.w - lse);
    }
}

// ---------------- launch: fork-join overlap of CSR build with GEMM1 --------------
extern "C" void kernel_launch(void* const* d_in, const int* in_sizes, int n_in,
                              void* d_out, int out_size) {
    const float* x  = (const float*)d_in[0];
    const void*  ei = d_in[1];
    const float* W1 = (const float*)d_in[2];
    const float* b1 = (const float*)d_in[3];
    const float* W2 = (const float*)d_in[4];
    const float* b2 = (const float*)d_in[5];
    float* out = (float*)d_out;

    const int n = in_sizes[0] / FIN;   // 50000
    const int e = in_sizes[1] / 2;     // 800000
    const int nb = (n + 255) / 256;    // 196

    cudaStream_t s2;
    cudaStreamCreateWithFlags(&s2, cudaStreamNonBlocking);
    cudaEvent_t evFork, evJoin;
    cudaEventCreateWithFlags(&evFork, cudaEventDisableTiming);
    cudaEventCreateWithFlags(&evJoin, cudaEventDisableTiming);

    cudaEventRecord(evFork, 0);
    cudaStreamWaitEvent(s2, evFork, 0);

    k_detect <<<1, 256, 0, s2>>>((const unsigned*)ei, e);
    k_zero   <<<(n + 255) / 256, 256, 0, s2>>>(n);
    k_count  <<<(e + 255) / 256, 256, 0, s2>>>(ei, e);
    k_partial<<<nb, 256, 0, s2>>>(n);
    k_scanb  <<<1, 256, 0, s2>>>(nb);
    k_rowptr <<<nb, 256, 0, s2>>>(n, e);
    k_fillw  <<<(e + 255) / 256, 256, 0, s2>>>(ei, e);
    cudaEventRecord(evJoin, s2);

    k_prepW  <<<(FIN * HID + 255) / 256, 256>>>(W1);
    k_gemm1  <<<(n + 127) / 128, 256>>>(x, n);

    cudaStreamWaitEvent(0, evJoin, 0);
    k_agg1   <<<(n + 7) / 8, 256>>>(b1, n);
    k_gemm2  <<<(n + 31) / 32, 160>>>(W2, n);
    k_agg2   <<<(n + 7) / 8, 256>>>(b2, out, n);
}

// round 9
// speedup vs baseline: 1.9484x; 1.0419x over previous
#include <cuda_runtime.h>
#include <cstdint>

#define NMAX 50000
#define EMAX 800000
#define FIN  512
#define HID  128
#define NC   40
#define NBLK 256

// ---------------- device scratch (static; no allocs allowed) ----------------
__device__ unsigned short g_h1b[NMAX * HID];   // x @ W1, bf16
__device__ float g_out1[NMAX * HID];
__device__ float g_h2  [NMAX * NC];
__device__ float g_dinv[NMAX];
__device__ int   g_cnt [NMAX];
__device__ int   g_fill[NMAX];
__device__ int   g_rowptr[NMAX + 1];
__device__ int2  g_cw  [EMAX];
__device__ int   g_bsum[NBLK];
__device__ int   g_boff[NBLK];
__device__ int   g_is64;
// W1 transposed + bf16-split: [n][k] layout
__device__ unsigned short g_wThi[HID * FIN];
__device__ unsigned short g_wTlo[HID * FIN];

typedef unsigned long long u64;

// pack two floats as bf16x2: low half = lo_elem, high half = hi_elem
__device__ __forceinline__ uint32_t cvt2(float lo_elem, float hi_elem) {
    uint32_t r;
    asm("cvt.rn.bf16x2.f32 %0, %1, %2;" : "=r"(r) : "f"(hi_elem), "f"(lo_elem));
    return r;
}

#define LDSM4(d0, d1, d2, d3, addr) \
    asm volatile("ldmatrix.sync.aligned.m8n8.x4.shared.b16 {%0,%1,%2,%3}, [%4];" \
        : "=r"(d0), "=r"(d1), "=r"(d2), "=r"(d3) : "r"(addr))

#define MMA16816(c, a, b0, b1) \
    asm volatile("mma.sync.aligned.m16n8k16.row.col.f32.bf16.bf16.f32 " \
        "{%0,%1,%2,%3},{%4,%5,%6,%7},{%8,%9},{%0,%1,%2,%3};" \
        : "+f"((c)[0]), "+f"((c)[1]), "+f"((c)[2]), "+f"((c)[3]) \
        : "r"((a)[0]), "r"((a)[1]), "r"((a)[2]), "r"((a)[3]), "r"(b0), "r"(b1))

// edge index accessor
__device__ __forceinline__ int ld_idx(const void* ei, int pos) {
    if (g_is64) return (int)((const long long*)ei)[pos];
    return ((const int*)ei)[pos];
}

// ---------------- dtype detection ----------------
__global__ void k_detect(const unsigned* __restrict__ w, int e) {
    __shared__ unsigned red[256];
    int total = e < 4096 ? e : 4096;
    unsigned acc = 0;
    for (int i = threadIdx.x; i < total; i += 256) acc |= w[2 * i + 1];
    red[threadIdx.x] = acc;
    __syncthreads();
    for (int s = 128; s > 0; s >>= 1) {
        if (threadIdx.x < s) red[threadIdx.x] |= red[threadIdx.x + s];
        __syncthreads();
    }
    if (threadIdx.x == 0) g_is64 = (red[0] == 0u) ? 1 : 0;
}

__global__ void k_zero(int n) {
    int i = blockIdx.x * blockDim.x + threadIdx.x;
    if (i < n) { g_cnt[i] = 0; g_fill[i] = 0; }
}

__global__ void k_count(const void* __restrict__ ei, int e) {
    int i = blockIdx.x * blockDim.x + threadIdx.x;
    if (i >= e) return;
    int dst = ld_idx(ei, e + i);
    atomicAdd(&g_cnt[dst], 1);
}

// ---------------- parallel exclusive scan (3 kernels) ----------------
__global__ __launch_bounds__(256) void k_partial(int n) {
    int i = blockIdx.x * 256 + threadIdx.x;
    int v = (i < n) ? g_cnt[i] : 0;
#pragma unroll
    for (int o = 16; o; o >>= 1) v += __shfl_down_sync(0xffffffffu, v, o);
    __shared__ int ws[8];
    if ((threadIdx.x & 31) == 0) ws[threadIdx.x >> 5] = v;
    __syncthreads();
    if (threadIdx.x < 8) {
        int s = ws[threadIdx.x];
#pragma unroll
        for (int o = 4; o; o >>= 1) s += __shfl_down_sync(0xffu, s, o);
        if (threadIdx.x == 0) g_bsum[blockIdx.x] = s;
    }
}

__global__ __launch_bounds__(256) void k_scanb(int nb) {
    const int t = threadIdx.x;
    const int lane = t & 31, w = t >> 5;
    int v = (t < nb) ? g_bsum[t] : 0;
    int inc = v;
#pragma unroll
    for (int o = 1; o < 32; o <<= 1) {
        int u = __shfl_up_sync(0xffffffffu, inc, o);
        if (lane >= o) inc += u;
    }
    __shared__ int ws[8];
    if (lane == 31) ws[w] = inc;
    __syncthreads();
    if (t < 8) {
        int s = ws[t];
#pragma unroll
        for (int o = 1; o < 8; o <<= 1) {
            int u = __shfl_up_sync(0xffu, s, o);
            if (t >= o) s += u;
        }
        ws[t] = s;
    }
    __syncthreads();
    int base = (w ? ws[w - 1] : 0);
    g_boff[t] = base + inc - v;
}

__global__ __launch_bounds__(256) void k_rowptr(int n, int e) {
    int i = blockIdx.x * 256 + threadIdx.x;
    int c = (i < n) ? g_cnt[i] : 0;
    const int lane = threadIdx.x & 31, w = threadIdx.x >> 5;
    int inc = c;
#pragma unroll
    for (int o = 1; o < 32; o <<= 1) {
        int u = __shfl_up_sync(0xffffffffu, inc, o);
        if (lane >= o) inc += u;
    }
    __shared__ int ws[8];
    if (lane == 31) ws[w] = inc;
    __syncthreads();
    if (threadIdx.x < 8) {
        int s = ws[threadIdx.x];
#pragma unroll
        for (int o = 1; o < 8; o <<= 1) {
            int u = __shfl_up_sync(0xffu, s, o);
            if (threadIdx.x >= o) s += u;
        }
        ws[threadIdx.x] = s;
    }
    __syncthreads();
    int base = g_boff[blockIdx.x] + (w ? ws[w - 1] : 0);
    if (i < n) {
        g_rowptr[i] = base + inc - c;
        g_dinv[i] = rsqrtf((float)(c + 1));
    }
    if (i == 0) g_rowptr[n] = e;
}

__global__ void k_fillw(const void* __restrict__ ei, int e) {
    int i = blockIdx.x * blockDim.x + threadIdx.x;
    if (i >= e) return;
    int src = ld_idx(ei, i);
    int dst = ld_idx(ei, e + i);
    int pos = g_rowptr[dst] + atomicAdd(&g_fill[dst], 1);
    float w = g_dinv[src] * g_dinv[dst];
    g_cw[pos] = make_int2(src, __float_as_int(w));
}

// ---------------- W1 prep: transpose to [n][k] + bf16 hi/lo split ----------------
__global__ void k_prepW(const float* __restrict__ W) {
    int i = blockIdx.x * 256 + threadIdx.x;
    if (i >= FIN * HID) return;
    int k = i >> 7, nn = i & 127;
    float w = W[i];
    uint32_t ph = cvt2(w, 0.f);
    float hf = __uint_as_float(ph << 16);
    float l = w - hf;
    uint32_t pl = cvt2(l, 0.f);
    g_wThi[nn * FIN + k] = (unsigned short)(ph & 0xffffu);
    g_wTlo[nn * FIN + k] = (unsigned short)(pl & 0xffffu);
}

// ---------------- GEMM1: h1 = x[n,512] @ W1[512,128] via bf16x3 mma.sync ----------
// Software-pipelined; epilogue stores bf16 h1.
__global__ __launch_bounds__(256, 1) void k_gemm1(const float* __restrict__ x, int n) {
    __shared__ __align__(16) unsigned short Ah[128][40];
    __shared__ __align__(16) unsigned short Al[128][40];
    __shared__ __align__(16) unsigned short Bh[128][40];
    __shared__ __align__(16) unsigned short Bl[128][40];

    const int tid = threadIdx.x;
    const int lane = tid & 31;
    const int wid = tid >> 5;
    const int wm = wid & 1;
    const int wn = wid >> 1;
    const int m_base = wm * 64;
    const int n_base = wn * 32;
    const int row0 = blockIdx.x * 128;

    const int ldrow = tid >> 1;
    const int half = tid & 1;

    float c[4][4][4];
#pragma unroll
    for (int mt = 0; mt < 4; mt++)
#pragma unroll
        for (int nt = 0; nt < 4; nt++)
#pragma unroll
            for (int q = 0; q < 4; q++) c[mt][nt][q] = 0.f;

    const int qd = lane >> 3;
    const int r8 = lane & 7;
    const int a_r = m_base + (qd & 1) * 8 + r8;
    const int a_c = (qd >> 1) * 8;
    const int b_r = n_base + (lane >> 4) * 8 + r8;
    const int b_c = ((lane >> 3) & 1) * 8;

    const uint32_t sAh = (uint32_t)__cvta_generic_to_shared(&Ah[0][0]);
    const uint32_t sAl = (uint32_t)__cvta_generic_to_shared(&Al[0][0]);
    const uint32_t sBh = (uint32_t)__cvta_generic_to_shared(&Bh[0][0]);
    const uint32_t sBl = (uint32_t)__cvta_generic_to_shared(&Bl[0][0]);

    const bool rowOK = (row0 + ldrow) < n;
    const float* xbase = x + (size_t)(row0 + ldrow) * FIN + half * 16;
    const unsigned short* whb = g_wThi + ldrow * FIN + half * 16;
    const unsigned short* wlb = g_wTlo + ldrow * FIN + half * 16;

    float4 av[4];
    uint4 bvh[2], bvl[2];

#define LOADG(K0) do { \
        _Pragma("unroll") \
        for (int j = 0; j < 4; j++) \
            av[j] = rowOK ? *(const float4*)(xbase + (K0) + j * 4) \
                          : make_float4(0.f, 0.f, 0.f, 0.f); \
        bvh[0] = *(const uint4*)(whb + (K0)); \
        bvh[1] = *(const uint4*)(whb + (K0) + 8); \
        bvl[0] = *(const uint4*)(wlb + (K0)); \
        bvl[1] = *(const uint4*)(wlb + (K0) + 8); \
    } while (0)

    LOADG(0);

#pragma unroll 1
    for (int it = 0; it < FIN / 32; it++) {
        {
            uint32_t* dh = (uint32_t*)&Ah[ldrow][half * 16];
            uint32_t* dl = (uint32_t*)&Al[ldrow][half * 16];
#pragma unroll
            for (int j = 0; j < 4; j++) {
                float4 v = av[j];
                uint32_t p01 = cvt2(v.x, v.y);
                uint32_t p23 = cvt2(v.z, v.w);
                float h0 = __uint_as_float(p01 << 16);
                float h1 = __uint_as_float(p01 & 0xffff0000u);
                float h2 = __uint_as_float(p23 << 16);
                float h3 = __uint_as_float(p23 & 0xffff0000u);
                uint32_t q01 = cvt2(v.x - h0, v.y - h1);
                uint32_t q23 = cvt2(v.z - h2, v.w - h3);
                dh[j * 2 + 0] = p01; dh[j * 2 + 1] = p23;
                dl[j * 2 + 0] = q01; dl[j * 2 + 1] = q23;
            }
            uint4* bdh = (uint4*)&Bh[ldrow][half * 16];
            uint4* bdl = (uint4*)&Bl[ldrow][half * 16];
            bdh[0] = bvh[0]; bdh[1] = bvh[1];
            bdl[0] = bvl[0]; bdl[1] = bvl[1];
        }
        if (it + 1 < FIN / 32) LOADG((it + 1) * 32);
        __syncthreads();

#pragma unroll
        for (int kk = 0; kk < 32; kk += 16) {
            uint32_t ah[4][4], al[4][4], bh[2][4], bl[2][4];
#pragma unroll
            for (int mt = 0; mt < 4; mt++) {
                uint32_t off = (uint32_t)(((a_r + mt * 16) * 40 + kk + a_c) * 2);
                LDSM4(ah[mt][0], ah[mt][1], ah[mt][2], ah[mt][3], sAh + off);
                LDSM4(al[mt][0], al[mt][1], al[mt][2], al[mt][3], sAl + off);
            }
#pragma unroll
            for (int pp = 0; pp < 2; pp++) {
                uint32_t off = (uint32_t)(((b_r + pp * 16) * 40 + kk + b_c) * 2);
                LDSM4(bh[pp][0], bh[pp][1], bh[pp][2], bh[pp][3], sBh + off);
                LDSM4(bl[pp][0], bl[pp][1], bl[pp][2], bl[pp][3], sBl + off);
            }
#pragma unroll
            for (int mt = 0; mt < 4; mt++) {
#pragma unroll
                for (int nt = 0; nt < 4; nt++) {
                    int pp = nt >> 1, ix = (nt & 1) * 2;
                    MMA16816(c[mt][nt], ah[mt], bh[pp][ix], bh[pp][ix + 1]);
                    MMA16816(c[mt][nt], al[mt], bh[pp][ix], bh[pp][ix + 1]);
                    MMA16816(c[mt][nt], ah[mt], bl[pp][ix], bl[pp][ix + 1]);
                }
            }
        }
        __syncthreads();
    }
#undef LOADG

    // ---- store C as bf16 ----
#pragma unroll
    for (int mt = 0; mt < 4; mt++) {
        int row = row0 + m_base + mt * 16 + (lane >> 2);
#pragma unroll
        for (int nt = 0; nt < 4; nt++) {
            int col = n_base + nt * 8 + (lane & 3) * 2;   // even
            if (row < n)
                *(uint32_t*)(g_h1b + (size_t)row * HID + col) =
                    cvt2(c[mt][nt][0], c[mt][nt][1]);
            if (row + 8 < n)
                *(uint32_t*)(g_h1b + (size_t)(row + 8) * HID + col) =
                    cvt2(c[mt][nt][2], c[mt][nt][3]);
        }
    }
}

// unpack 4 bf16 (uint2) -> float4, exact
__device__ __forceinline__ float4 bf16x4_to_f4(uint2 u) {
    float4 v;
    v.x = __uint_as_float(u.x << 16);
    v.y = __uint_as_float(u.x & 0xffff0000u);
    v.z = __uint_as_float(u.y << 16);
    v.w = __uint_as_float(u.y & 0xffff0000u);
    return v;
}

// ---------------- agg1: out1 = relu(b1 + sum_norm(h1_bf16)), warp per node --------
__global__ void k_agg1(const float* __restrict__ b1, int n) {
    int gw = (blockIdx.x * blockDim.x + threadIdx.x) >> 5;
    int lane = threadIdx.x & 31;
    if (gw >= n) return;
    const int i = gw;
    const float di = g_dinv[i];
    const uint2* __restrict__ h2p = (const uint2*)g_h1b;   // 32 uint2 per row

    float4 self = bf16x4_to_f4(h2p[(size_t)i * 32 + lane]);
    float sw = di * di;
    float4 acc = make_float4(self.x * sw, self.y * sw, self.z * sw, self.w * sw);

    const int rs = g_rowptr[i], re = g_rowptr[i + 1];
    for (int base = rs; base < re; base += 32) {
        int m = re - base; if (m > 32) m = 32;
        int2 cw = make_int2(0, 0);
        if (lane < m) cw = g_cw[base + lane];
#pragma unroll 4
        for (int j = 0; j < m; j++) {
            int ss = __shfl_sync(0xffffffffu, cw.x, j);
            float ww = __int_as_float(__shfl_sync(0xffffffffu, cw.y, j));
            float4 v = bf16x4_to_f4(h2p[(size_t)ss * 32 + lane]);
            acc.x += v.x * ww; acc.y += v.y * ww;
            acc.z += v.z * ww; acc.w += v.w * ww;
        }
    }
    float4 bb = ((const float4*)b1)[lane];
    acc.x = fmaxf(acc.x + bb.x, 0.f);
    acc.y = fmaxf(acc.y + bb.y, 0.f);
    acc.z = fmaxf(acc.z + bb.z, 0.f);
    acc.w = fmaxf(acc.w + bb.w, 0.f);
    ((float4*)g_out1)[(size_t)i * 32 + lane] = acc;
}

// ---------------- GEMM2: h2 = out1[n,128] @ W2[128,40] ----------------
__global__ __launch_bounds__(160) void k_gemm2(const float* __restrict__ W2, int n) {
    __shared__ __align__(16) float Ws[HID * NC];
    __shared__ float As[32 * 129];

    const int tid = threadIdx.x;
    for (int q = tid; q < HID * NC; q += 160) Ws[q] = W2[q];

    const int r0 = blockIdx.x * 32;
    for (int q = tid; q < 32 * HID; q += 160) {
        int r = q >> 7, k = q & 127;
        int grow = r0 + r;
        As[r * 129 + k] = (grow < n) ? g_out1[(size_t)grow * HID + k] : 0.f;
    }
    __syncthreads();

    const int r = tid & 31;
    const int cg = tid >> 5;
    const int c0 = cg * 8;
    float acc[8];
#pragma unroll
    for (int j = 0; j < 8; j++) acc[j] = 0.f;

#pragma unroll 4
    for (int k = 0; k < HID; k++) {
        float a = As[r * 129 + k];
        float4 w0 = *(const float4*)&Ws[k * NC + c0];
        float4 w1 = *(const float4*)&Ws[k * NC + c0 + 4];
        acc[0] += a * w0.x; acc[1] += a * w0.y; acc[2] += a * w0.z; acc[3] += a * w0.w;
        acc[4] += a * w1.x; acc[5] += a * w1.y; acc[6] += a * w1.z; acc[7] += a * w1.w;
    }
    int grow = r0 + r;
    if (grow < n) {
        *(float4*)(g_h2 + (size_t)grow * NC + c0) =
            make_float4(acc[0], acc[1], acc[2], acc[3]);
        *(float4*)(g_h2 + (size_t)grow * NC + c0 + 4) =
            make_float4(acc[4], acc[5], acc[6], acc[7]);
    }
}

// ---------------- agg2 + bias + log_softmax, warp per node ----------------
__global__ void k_agg2(const float* __restrict__ b2, float* __restrict__ out, int n) {
    int gw = (blockIdx.x * blockDim.x + threadIdx.x) >> 5;
    int lane = threadIdx.x & 31;
    if (gw >= n) return;
    const int i = gw;
    const float di = g_dinv[i];
    const float4* __restrict__ h4 = (const float4*)g_h2;

    float4 acc = make_float4(0.f, 0.f, 0.f, 0.f);
    if (lane < 10) {
        acc = h4[(size_t)i * 10 + lane];
        float sw = di * di;
        acc.x *= sw; acc.y *= sw; acc.z *= sw; acc.w *= sw;
    }
    const int rs = g_rowptr[i], re = g_rowptr[i + 1];
    for (int base = rs; base < re; base += 32) {
        int m = re - base; if (m > 32) m = 32;
        int2 cw = make_int2(0, 0);
        if (lane < m) cw = g_cw[base + lane];
#pragma unroll 4
        for (int j = 0; j < m; j++) {
            int ss = __shfl_sync(0xffffffffu, cw.x, j);
            float ww = __int_as_float(__shfl_sync(0xffffffffu, cw.y, j));
            if (lane < 10) {
                float4 v = h4[(size_t)ss * 10 + lane];
                acc.x += v.x * ww; acc.y += v.y * ww;
                acc.z += v.z * ww; acc.w += v.w * ww;
            }
        }
    }
    if (lane < 10) {
        float4 bb = ((const float4*)b2)[lane];
        acc.x += bb.x; acc.y += bb.y; acc.z += bb.z; acc.w += bb.w;
    }
    float m = (lane < 10)
        ? fmaxf(fmaxf(acc.x, acc.y), fmaxf(acc.z, acc.w)) : -3.0e38f;
#pragma unroll
    for (int off = 8; off; off >>= 1)
        m = fmaxf(m, __shfl_xor_sync(0xffffffffu, m, off, 16));
    float sum = (lane < 10)
        ? (expf(acc.x - m) + expf(acc.y - m) + expf(acc.z - m) + expf(acc.w - m))
        : 0.f;
#pragma unroll
    for (int off = 8; off; off >>= 1)
        sum += __shfl_xor_sync(0xffffffffu, sum, off, 16);
    float lse = m + logf(sum);
    if (lane < 10) {
        ((float4*)out)[(size_t)i * 10 + lane] =
            make_float4(acc.x - lse, acc.y - lse, acc.z - lse, acc.w - lse);
    }
}

// ---------------- launch: fork-join overlap of CSR build with GEMM1 --------------
extern "C" void kernel_launch(void* const* d_in, const int* in_sizes, int n_in,
                              void* d_out, int out_size) {
    const float* x  = (const float*)d_in[0];
    const void*  ei = d_in[1];
    const float* W1 = (const float*)d_in[2];
    const float* b1 = (const float*)d_in[3];
    const float* W2 = (const float*)d_in[4];
    const float* b2 = (const float*)d_in[5];
    float* out = (float*)d_out;

    const int n = in_sizes[0] / FIN;   // 50000
    const int e = in_sizes[1] / 2;     // 800000
    const int nb = (n + 255) / 256;    // 196

    cudaStream_t s2;
    cudaStreamCreateWithFlags(&s2, cudaStreamNonBlocking);
    cudaEvent_t evFork, evJoin;
    cudaEventCreateWithFlags(&evFork, cudaEventDisableTiming);
    cudaEventCreateWithFlags(&evJoin, cudaEventDisableTiming);

    cudaEventRecord(evFork, 0);
    cudaStreamWaitEvent(s2, evFork, 0);

    k_detect <<<1, 256, 0, s2>>>((const unsigned*)ei, e);
    k_zero   <<<(n + 255) / 256, 256, 0, s2>>>(n);
    k_count  <<<(e + 255) / 256, 256, 0, s2>>>(ei, e);
    k_partial<<<nb, 256, 0, s2>>>(n);
    k_scanb  <<<1, 256, 0, s2>>>(nb);
    k_rowptr <<<nb, 256, 0, s2>>>(n, e);
    k_fillw  <<<(e + 255) / 256, 256, 0, s2>>>(ei, e);
    cudaEventRecord(evJoin, s2);

    k_prepW  <<<(FIN * HID + 255) / 256, 256>>>(W1);
    k_gemm1  <<<(n + 127) / 128, 256>>>(x, n);

    cudaStreamWaitEvent(0, evJoin, 0);
    k_agg1   <<<(n + 7) / 8, 256>>>(b1, n);
    k_gemm2  <<<(n + 31) / 32, 160>>>(W2, n);
    k_agg2   <<<(n + 7) / 8, 256>>>(b2, out, n);
}

// round 12
// speedup vs baseline: 2.0726x; 1.0637x over previous
#include <cuda_runtime.h>
#include <cuda_fp16.h>
#include <cstdint>

#define NMAX 50000
#define EMAX 800000
#define FIN  512
#define HID  128
#define NC   40
#define NBLK 256

// ---------------- device scratch (static; no allocs allowed) ----------------
__device__ unsigned short g_h1b [NMAX * HID];   // x @ W1, bf16
__device__ unsigned short g_out1b[NMAX * HID];  // relu(agg1+b1), bf16
__device__ unsigned short g_h2b [NMAX * NC];    // out1 @ W2, bf16
__device__ float g_dinv[NMAX];
__device__ int   g_cnt [NMAX];
__device__ int   g_fill[NMAX];
__device__ int   g_rowptr[NMAX + 1];
__device__ int2  g_cw  [EMAX];
__device__ int   g_bsum[NBLK];
__device__ int   g_boff[NBLK];
__device__ int   g_is64;
// W1 transposed + fp16 hi/lo split: [n][k] layout
__device__ unsigned short g_wThi[HID * FIN];
__device__ unsigned short g_wTlo[HID * FIN];

typedef unsigned long long u64;

// pack two floats as bf16x2 (memory order: lo_elem first)
__device__ __forceinline__ uint32_t cvt2(float lo_elem, float hi_elem) {
    uint32_t r;
    asm("cvt.rn.bf16x2.f32 %0, %1, %2;" : "=r"(r) : "f"(hi_elem), "f"(lo_elem));
    return r;
}
// pack two floats as f16x2 (memory order: lo_elem first)
__device__ __forceinline__ uint32_t cvtf16x2(float lo_elem, float hi_elem) {
    uint32_t r;
    asm("cvt.rn.f16x2.f32 %0, %1, %2;" : "=r"(r) : "f"(hi_elem), "f"(lo_elem));
    return r;
}

#define LDSM4(d0, d1, d2, d3, addr) \
    asm volatile("ldmatrix.sync.aligned.m8n8.x4.shared.b16 {%0,%1,%2,%3}, [%4];" \
        : "=r"(d0), "=r"(d1), "=r"(d2), "=r"(d3) : "r"(addr))

#define MMAF16(c, a, b0, b1) \
    asm volatile("mma.sync.aligned.m16n8k16.row.col.f32.f16.f16.f32 " \
        "{%0,%1,%2,%3},{%4,%5,%6,%7},{%8,%9},{%0,%1,%2,%3};" \
        : "+f"((c)[0]), "+f"((c)[1]), "+f"((c)[2]), "+f"((c)[3]) \
        : "r"((a)[0]), "r"((a)[1]), "r"((a)[2]), "r"((a)[3]), "r"(b0), "r"(b1))

// edge index accessor
__device__ __forceinline__ int ld_idx(const void* ei, int pos) {
    if (g_is64) return (int)((const long long*)ei)[pos];
    return ((const int*)ei)[pos];
}

// unpack 4 bf16 (uint2) -> float4, exact
__device__ __forceinline__ float4 bf16x4_to_f4(uint2 u) {
    float4 v;
    v.x = __uint_as_float(u.x << 16);
    v.y = __uint_as_float(u.x & 0xffff0000u);
    v.z = __uint_as_float(u.y << 16);
    v.w = __uint_as_float(u.y & 0xffff0000u);
    return v;
}

// ---------------- dtype detection ----------------
__global__ void k_detect(const unsigned* __restrict__ w, int e) {
    __shared__ unsigned red[256];
    int total = e < 4096 ? e : 4096;
    unsigned acc = 0;
    for (int i = threadIdx.x; i < total; i += 256) acc |= w[2 * i + 1];
    red[threadIdx.x] = acc;
    __syncthreads();
    for (int s = 128; s > 0; s >>= 1) {
        if (threadIdx.x < s) red[threadIdx.x] |= red[threadIdx.x + s];
        __syncthreads();
    }
    if (threadIdx.x == 0) g_is64 = (red[0] == 0u) ? 1 : 0;
}

__global__ void k_zero(int n) {
    int i = blockIdx.x * blockDim.x + threadIdx.x;
    if (i < n) { g_cnt[i] = 0; g_fill[i] = 0; }
}

__global__ void k_count(const void* __restrict__ ei, int e) {
    int i = blockIdx.x * blockDim.x + threadIdx.x;
    if (i >= e) return;
    int dst = ld_idx(ei, e + i);
    atomicAdd(&g_cnt[dst], 1);
}

// ---------------- parallel exclusive scan (3 kernels) ----------------
__global__ __launch_bounds__(256) void k_partial(int n) {
    int i = blockIdx.x * 256 + threadIdx.x;
    int v = (i < n) ? g_cnt[i] : 0;
#pragma unroll
    for (int o = 16; o; o >>= 1) v += __shfl_down_sync(0xffffffffu, v, o);
    __shared__ int ws[8];
    if ((threadIdx.x & 31) == 0) ws[threadIdx.x >> 5] = v;
    __syncthreads();
    if (threadIdx.x < 8) {
        int s = ws[threadIdx.x];
#pragma unroll
        for (int o = 4; o; o >>= 1) s += __shfl_down_sync(0xffu, s, o);
        if (threadIdx.x == 0) g_bsum[blockIdx.x] = s;
    }
}

__global__ __launch_bounds__(256) void k_scanb(int nb) {
    const int t = threadIdx.x;
    const int lane = t & 31, w = t >> 5;
    int v = (t < nb) ? g_bsum[t] : 0;
    int inc = v;
#pragma unroll
    for (int o = 1; o < 32; o <<= 1) {
        int u = __shfl_up_sync(0xffffffffu, inc, o);
        if (lane >= o) inc += u;
    }
    __shared__ int ws[8];
    if (lane == 31) ws[w] = inc;
    __syncthreads();
    if (t < 8) {
        int s = ws[t];
#pragma unroll
        for (int o = 1; o < 8; o <<= 1) {
            int u = __shfl_up_sync(0xffu, s, o);
            if (t >= o) s += u;
        }
        ws[t] = s;
    }
    __syncthreads();
    int base = (w ? ws[w - 1] : 0);
    g_boff[t] = base + inc - v;
}

__global__ __launch_bounds__(256) void k_rowptr(int n, int e) {
    int i = blockIdx.x * 256 + threadIdx.x;
    int c = (i < n) ? g_cnt[i] : 0;
    const int lane = threadIdx.x & 31, w = threadIdx.x >> 5;
    int inc = c;
#pragma unroll
    for (int o = 1; o < 32; o <<= 1) {
        int u = __shfl_up_sync(0xffffffffu, inc, o);
        if (lane >= o) inc += u;
    }
    __shared__ int ws[8];
    if (lane == 31) ws[w] = inc;
    __syncthreads();
    if (threadIdx.x < 8) {
        int s = ws[threadIdx.x];
#pragma unroll
        for (int o = 1; o < 8; o <<= 1) {
            int u = __shfl_up_sync(0xffu, s, o);
            if (threadIdx.x >= o) s += u;
        }
        ws[threadIdx.x] = s;
    }
    __syncthreads();
    int base = g_boff[blockIdx.x] + (w ? ws[w - 1] : 0);
    if (i < n) {
        g_rowptr[i] = base + inc - c;
        g_dinv[i] = rsqrtf((float)(c + 1));
    }
    if (i == 0) g_rowptr[n] = e;
}

__global__ void k_fillw(const void* __restrict__ ei, int e) {
    int i = blockIdx.x * blockDim.x + threadIdx.x;
    if (i >= e) return;
    int src = ld_idx(ei, i);
    int dst = ld_idx(ei, e + i);
    int pos = g_rowptr[dst] + atomicAdd(&g_fill[dst], 1);
    float w = g_dinv[src] * g_dinv[dst];
    g_cw[pos] = make_int2(src, __float_as_int(w));
}

// ---------------- W1 prep: transpose to [n][k] + fp16 hi/lo split ----------------
__global__ void k_prepW(const float* __restrict__ W) {
    int i = blockIdx.x * 256 + threadIdx.x;
    if (i >= FIN * HID) return;
    int k = i >> 7, nn = i & 127;
    float w = W[i];
    __half hh = __float2half_rn(w);
    float l = w - __half2float(hh);
    __half hl = __float2half_rn(l);
    g_wThi[nn * FIN + k] = __half_as_ushort(hh);
    g_wTlo[nn * FIN + k] = __half_as_ushort(hl);
}

// ---------------- GEMM1: h1 = x[n,512] @ W1[512,128] via fp16 2-term mma.sync ----
// A = fp16(x) (no split needed: 11-bit significand), W = hi+lo fp16.
// Software-pipelined register prefetch; epilogue stores bf16 h1.
__global__ __launch_bounds__(256, 1) void k_gemm1(const float* __restrict__ x, int n) {
    __shared__ __align__(16) unsigned short Ah[128][40];
    __shared__ __align__(16) unsigned short Bh[128][40];
    __shared__ __align__(16) unsigned short Bl[128][40];

    const int tid = threadIdx.x;
    const int lane = tid & 31;
    const int wid = tid >> 5;
    const int wm = wid & 1;
    const int wn = wid >> 1;
    const int m_base = wm * 64;
    const int n_base = wn * 32;
    const int row0 = blockIdx.x * 128;

    const int ldrow = tid >> 1;
    const int half = tid & 1;

    float c[4][4][4];
#pragma unroll
    for (int mt = 0; mt < 4; mt++)
#pragma unroll
        for (int nt = 0; nt < 4; nt++)
#pragma unroll
            for (int q = 0; q < 4; q++) c[mt][nt][q] = 0.f;

    const int qd = lane >> 3;
    const int r8 = lane & 7;
    const int a_r = m_base + (qd & 1) * 8 + r8;
    const int a_c = (qd >> 1) * 8;
    const int b_r = n_base + (lane >> 4) * 8 + r8;
    const int b_c = ((lane >> 3) & 1) * 8;

    const uint32_t sAh = (uint32_t)__cvta_generic_to_shared(&Ah[0][0]);
    const uint32_t sBh = (uint32_t)__cvta_generic_to_shared(&Bh[0][0]);
    const uint32_t sBl = (uint32_t)__cvta_generic_to_shared(&Bl[0][0]);

    const bool rowOK = (row0 + ldrow) < n;
    const float* xbase = x + (size_t)(row0 + ldrow) * FIN + half * 16;
    const unsigned short* whb = g_wThi + ldrow * FIN + half * 16;
    const unsigned short* wlb = g_wTlo + ldrow * FIN + half * 16;

    float4 av[4];
    uint4 bvh[2], bvl[2];

#define LOADG(K0) do { \
        _Pragma("unroll") \
        for (int j = 0; j < 4; j++) \
            av[j] = rowOK ? *(const float4*)(xbase + (K0) + j * 4) \
                          : make_float4(0.f, 0.f, 0.f, 0.f); \
        bvh[0] = *(const uint4*)(whb + (K0)); \
        bvh[1] = *(const uint4*)(whb + (K0) + 8); \
        bvl[0] = *(const uint4*)(wlb + (K0)); \
        bvl[1] = *(const uint4*)(wlb + (K0) + 8); \
    } while (0)

    LOADG(0);

#pragma unroll 1
    for (int it = 0; it < FIN / 32; it++) {
        {
            uint32_t* dh = (uint32_t*)&Ah[ldrow][half * 16];
#pragma unroll
            for (int j = 0; j < 4; j++) {
                float4 v = av[j];
                dh[j * 2 + 0] = cvtf16x2(v.x, v.y);
                dh[j * 2 + 1] = cvtf16x2(v.z, v.w);
            }
            uint4* bdh = (uint4*)&Bh[ldrow][half * 16];
            uint4* bdl = (uint4*)&Bl[ldrow][half * 16];
            bdh[0] = bvh[0]; bdh[1] = bvh[1];
            bdl[0] = bvl[0]; bdl[1] = bvl[1];
        }
        if (it + 1 < FIN / 32) LOADG((it + 1) * 32);
        __syncthreads();

#pragma unroll
        for (int kk = 0; kk < 32; kk += 16) {
            uint32_t ah[4][4], bh[2][4], bl[2][4];
#pragma unroll
            for (int mt = 0; mt < 4; mt++) {
                uint32_t off = (uint32_t)(((a_r + mt * 16) * 40 + kk + a_c) * 2);
                LDSM4(ah[mt][0], ah[mt][1], ah[mt][2], ah[mt][3], sAh + off);
            }
#pragma unroll
            for (int pp = 0; pp < 2; pp++) {
                uint32_t off = (uint32_t)(((b_r + pp * 16) * 40 + kk + b_c) * 2);
                LDSM4(bh[pp][0], bh[pp][1], bh[pp][2], bh[pp][3], sBh + off);
                LDSM4(bl[pp][0], bl[pp][1], bl[pp][2], bl[pp][3], sBl + off);
            }
#pragma unroll
            for (int mt = 0; mt < 4; mt++) {
#pragma unroll
                for (int nt = 0; nt < 4; nt++) {
                    int pp = nt >> 1, ix = (nt & 1) * 2;
                    MMAF16(c[mt][nt], ah[mt], bh[pp][ix], bh[pp][ix + 1]);
                    MMAF16(c[mt][nt], ah[mt], bl[pp][ix], bl[pp][ix + 1]);
                }
            }
        }
        __syncthreads();
    }
#undef LOADG

    // ---- store C as bf16 ----
#pragma unroll
    for (int mt = 0; mt < 4; mt++) {
        int row = row0 + m_base + mt * 16 + (lane >> 2);
#pragma unroll
        for (int nt = 0; nt < 4; nt++) {
            int col = n_base + nt * 8 + (lane & 3) * 2;
            if (row < n)
                *(uint32_t*)(g_h1b + (size_t)row * HID + col) =
                    cvt2(c[mt][nt][0], c[mt][nt][1]);
            if (row + 8 < n)
                *(uint32_t*)(g_h1b + (size_t)(row + 8) * HID + col) =
                    cvt2(c[mt][nt][2], c[mt][nt][3]);
        }
    }
}

// ---------------- agg1: out1 = relu(b1 + sum_norm(h1_bf16)), warp per node --------
__global__ void k_agg1(const float* __restrict__ b1, int n) {
    int gw = (blockIdx.x * blockDim.x + threadIdx.x) >> 5;
    int lane = threadIdx.x & 31;
    if (gw >= n) return;
    const int i = gw;
    const float di = g_dinv[i];
    const uint2* __restrict__ h2p = (const uint2*)g_h1b;

    float4 self = bf16x4_to_f4(h2p[(size_t)i * 32 + lane]);
    float sw = di * di;
    float4 acc = make_float4(self.x * sw, self.y * sw, self.z * sw, self.w * sw);

    const int rs = g_rowptr[i], re = g_rowptr[i + 1];
    for (int base = rs; base < re; base += 32) {
        int m = re - base; if (m > 32) m = 32;
        int2 cw = make_int2(0, 0);
        if (lane < m) cw = g_cw[base + lane];
#pragma unroll 4
        for (int j = 0; j < m; j++) {
            int ss = __shfl_sync(0xffffffffu, cw.x, j);
            float ww = __int_as_float(__shfl_sync(0xffffffffu, cw.y, j));
            float4 v = bf16x4_to_f4(h2p[(size_t)ss * 32 + lane]);
            acc.x += v.x * ww; acc.y += v.y * ww;
            acc.z += v.z * ww; acc.w += v.w * ww;
        }
    }
    float4 bb = ((const float4*)b1)[lane];
    acc.x = fmaxf(acc.x + bb.x, 0.f);
    acc.y = fmaxf(acc.y + bb.y, 0.f);
    acc.z = fmaxf(acc.z + bb.z, 0.f);
    acc.w = fmaxf(acc.w + bb.w, 0.f);
    uint2 pk = make_uint2(cvt2(acc.x, acc.y), cvt2(acc.z, acc.w));
    ((uint2*)g_out1b)[(size_t)i * 32 + lane] = pk;
}

// ---------------- GEMM2: h2 = out1_bf16[n,128] @ W2[128,40], bf16 out ----------
__global__ __launch_bounds__(160) void k_gemm2(const float* __restrict__ W2, int n) {
    __shared__ __align__(16) float Ws[HID * NC];
    __shared__ float As[32 * 129];

    const int tid = threadIdx.x;
    for (int q = tid; q < HID * NC; q += 160) Ws[q] = W2[q];

    const int r0 = blockIdx.x * 32;
    for (int q = tid; q < 32 * (HID / 2); q += 160) {
        int r = q >> 6, kp = q & 63;
        int grow = r0 + r;
        uint32_t u = (grow < n)
            ? *(const uint32_t*)(g_out1b + (size_t)grow * HID + kp * 2) : 0u;
        As[r * 129 + kp * 2 + 0] = __uint_as_float(u << 16);
        As[r * 129 + kp * 2 + 1] = __uint_as_float(u & 0xffff0000u);
    }
    __syncthreads();

    const int r = tid & 31;
    const int cg = tid >> 5;
    const int c0 = cg * 8;
    float acc[8];
#pragma unroll
    for (int j = 0; j < 8; j++) acc[j] = 0.f;

#pragma unroll 4
    for (int k = 0; k < HID; k++) {
        float a = As[r * 129 + k];
        float4 w0 = *(const float4*)&Ws[k * NC + c0];
        float4 w1 = *(const float4*)&Ws[k * NC + c0 + 4];
        acc[0] += a * w0.x; acc[1] += a * w0.y; acc[2] += a * w0.z; acc[3] += a * w0.w;
        acc[4] += a * w1.x; acc[5] += a * w1.y; acc[6] += a * w1.z; acc[7] += a * w1.w;
    }
    int grow = r0 + r;
    if (grow < n) {
        uint2 p0 = make_uint2(cvt2(acc[0], acc[1]), cvt2(acc[2], acc[3]));
        uint2 p1 = make_uint2(cvt2(acc[4], acc[5]), cvt2(acc[6], acc[7]));
        *(uint2*)(g_h2b + (size_t)grow * NC + c0) = p0;
        *(uint2*)(g_h2b + (size_t)grow * NC + c0 + 4) = p1;
    }
}

// ---------------- agg2 + bias + log_softmax, warp per node ----------------
__global__ void k_agg2(const float* __restrict__ b2, float* __restrict__ out, int n) {
    int gw = (blockIdx.x * blockDim.x + threadIdx.x) >> 5;
    int lane = threadIdx.x & 31;
    if (gw >= n) return;
    const int i = gw;
    const float di = g_dinv[i];
    const uint2* __restrict__ h2p = (const uint2*)g_h2b;   // 10 uint2 per row

    float4 acc = make_float4(0.f, 0.f, 0.f, 0.f);
    if (lane < 10) {
        float4 v = bf16x4_to_f4(h2p[(size_t)i * 10 + lane]);
        float sw = di * di;
        acc = make_float4(v.x * sw, v.y * sw, v.z * sw, v.w * sw);
    }
    const int rs = g_rowptr[i], re = g_rowptr[i + 1];
    for (int base = rs; base < re; base += 32) {
        int m = re - base; if (m > 32) m = 32;
        int2 cw = make_int2(0, 0);
        if (lane < m) cw = g_cw[base + lane];
#pragma unroll 4
        for (int j = 0; j < m; j++) {
            int ss = __shfl_sync(0xffffffffu, cw.x, j);
            float ww = __int_as_float(__shfl_sync(0xffffffffu, cw.y, j));
            if (lane < 10) {
                float4 v = bf16x4_to_f4(h2p[(size_t)ss * 10 + lane]);
                acc.x += v.x * ww; acc.y += v.y * ww;
                acc.z += v.z * ww; acc.w += v.w * ww;
            }
        }
    }
    if (lane < 10) {
        float4 bb = ((const float4*)b2)[lane];
        acc.x += bb.x; acc.y += bb.y; acc.z += bb.z; acc.w += bb.w;
    }
    float m = (lane < 10)
        ? fmaxf(fmaxf(acc.x, acc.y), fmaxf(acc.z, acc.w)) : -3.0e38f;
#pragma unroll
    for (int off = 8; off; off >>= 1)
        m = fmaxf(m, __shfl_xor_sync(0xffffffffu, m, off, 16));
    float sum = (lane < 10)
        ? (expf(acc.x - m) + expf(acc.y - m) + expf(acc.z - m) + expf(acc.w - m))
        : 0.f;
#pragma unroll
    for (int off = 8; off; off >>= 1)
        sum += __shfl_xor_sync(0xffffffffu, sum, off, 16);
    float lse = m + logf(sum);
    if (lane < 10) {
        ((float4*)out)[(size_t)i * 10 + lane] =
            make_float4(acc.x - lse, acc.y - lse, acc.z - lse, acc.w - lse);
    }
}

// ---------------- launch: fork-join overlap of CSR build with GEMM1 --------------
extern "C" void kernel_launch(void* const* d_in, const int* in_sizes, int n_in,
                              void* d_out, int out_size) {
    const float* x  = (const float*)d_in[0];
    const void*  ei = d_in[1];
    const float* W1 = (const float*)d_in[2];
    const float* b1 = (const float*)d_in[3];
    const float* W2 = (const float*)d_in[4];
    const float* b2 = (const float*)d_in[5];
    float* out = (float*)d_out;

    const int n = in_sizes[0] / FIN;   // 50000
    const int e = in_sizes[1] / 2;     // 800000
    const int nb = (n + 255) / 256;    // 196

    cudaStream_t s2;
    cudaStreamCreateWithFlags(&s2, cudaStreamNonBlocking);
    cudaEvent_t evFork, evJoin;
    cudaEventCreateWithFlags(&evFork, cudaEventDisableTiming);
    cudaEventCreateWithFlags(&evJoin, cudaEventDisableTiming);

    cudaEventRecord(evFork, 0);
    cudaStreamWaitEvent(s2, evFork, 0);

    // submission order puts gemm1 at kernel #4 (profiler has been capturing #4)
    k_detect <<<1, 256, 0, s2>>>((const unsigned*)ei, e);           // #1
    k_zero   <<<(n + 255) / 256, 256, 0, s2>>>(n);                  // #2
    k_prepW  <<<(FIN * HID + 255) / 256, 256>>>(W1);                // #3 (main)
    k_gemm1  <<<(n + 127) / 128, 256>>>(x, n);                      // #4 (main)
    k_count  <<<(e + 255) / 256, 256, 0, s2>>>(ei, e);              // #5
    k_partial<<<nb, 256, 0, s2>>>(n);                               // #6
    k_scanb  <<<1, 256, 0, s2>>>(nb);                               // #7
    k_rowptr <<<nb, 256, 0, s2>>>(n, e);                            // #8
    k_fillw  <<<(e + 255) / 256, 256, 0, s2>>>(ei, e);              // #9
    cudaEventRecord(evJoin, s2);

    cudaStreamWaitEvent(0, evJoin, 0);
    k_agg1   <<<(n + 7) / 8, 256>>>(b1, n);                         // #10
    k_gemm2  <<<(n + 31) / 32, 160>>>(W2, n);                       // #11
    k_agg2   <<<(n + 7) / 8, 256>>>(b2, out, n);                    // #12
}

// round 13
// speedup vs baseline: 2.2021x; 1.0625x over previous
#include <cuda_runtime.h>
#include <cuda_fp16.h>
#include <cstdint>

#define NMAX 50000
#define EMAX 800000
#define FIN  512
#define HID  128
#define NC   40
#define NBLK 256

// ---------------- device scratch (static; no allocs allowed) ----------------
__device__ unsigned short g_h1b [NMAX * HID];   // x @ W1, bf16
__device__ unsigned short g_out1b[NMAX * HID];  // relu(agg1+b1), bf16
__device__ unsigned short g_h2b [NMAX * NC];    // out1 @ W2, bf16
__device__ float g_dinv[NMAX];
__device__ int   g_cnt [NMAX];
__device__ int   g_fill[NMAX];
__device__ int   g_rowptr[NMAX + 1];
__device__ int2  g_cw  [EMAX];
__device__ int   g_bsum[NBLK];
__device__ int   g_boff[NBLK];
__device__ int   g_is64;
// W1 transposed bf16: [n][k] layout
__device__ unsigned short g_wT[HID * FIN];

typedef unsigned long long u64;

// pack two floats as bf16x2 (memory order: lo_elem first)
__device__ __forceinline__ uint32_t cvt2(float lo_elem, float hi_elem) {
    uint32_t r;
    asm("cvt.rn.bf16x2.f32 %0, %1, %2;" : "=r"(r) : "f"(hi_elem), "f"(lo_elem));
    return r;
}

#define LDSM4(d0, d1, d2, d3, addr) \
    asm volatile("ldmatrix.sync.aligned.m8n8.x4.shared.b16 {%0,%1,%2,%3}, [%4];" \
        : "=r"(d0), "=r"(d1), "=r"(d2), "=r"(d3) : "r"(addr))

#define MMAB16(c, a, b0, b1) \
    asm volatile("mma.sync.aligned.m16n8k16.row.col.f32.bf16.bf16.f32 " \
        "{%0,%1,%2,%3},{%4,%5,%6,%7},{%8,%9},{%0,%1,%2,%3};" \
        : "+f"((c)[0]), "+f"((c)[1]), "+f"((c)[2]), "+f"((c)[3]) \
        : "r"((a)[0]), "r"((a)[1]), "r"((a)[2]), "r"((a)[3]), "r"(b0), "r"(b1))

// edge index accessor
__device__ __forceinline__ int ld_idx(const void* ei, int pos) {
    if (g_is64) return (int)((const long long*)ei)[pos];
    return ((const int*)ei)[pos];
}

// unpack 4 bf16 (uint2) -> float4, exact
__device__ __forceinline__ float4 bf16x4_to_f4(uint2 u) {
    float4 v;
    v.x = __uint_as_float(u.x << 16);
    v.y = __uint_as_float(u.x & 0xffff0000u);
    v.z = __uint_as_float(u.y << 16);
    v.w = __uint_as_float(u.y & 0xffff0000u);
    return v;
}

// ---------------- dtype detection ----------------
__global__ void k_detect(const unsigned* __restrict__ w, int e) {
    __shared__ unsigned red[256];
    int total = e < 4096 ? e : 4096;
    unsigned acc = 0;
    for (int i = threadIdx.x; i < total; i += 256) acc |= w[2 * i + 1];
    red[threadIdx.x] = acc;
    __syncthreads();
    for (int s = 128; s > 0; s >>= 1) {
        if (threadIdx.x < s) red[threadIdx.x] |= red[threadIdx.x + s];
        __syncthreads();
    }
    if (threadIdx.x == 0) g_is64 = (red[0] == 0u) ? 1 : 0;
}

__global__ void k_zero(int n) {
    int i = blockIdx.x * blockDim.x + threadIdx.x;
    if (i < n) { g_cnt[i] = 0; g_fill[i] = 0; }
}

__global__ void k_count(const void* __restrict__ ei, int e) {
    int i = blockIdx.x * blockDim.x + threadIdx.x;
    if (i >= e) return;
    int dst = ld_idx(ei, e + i);
    atomicAdd(&g_cnt[dst], 1);
}

// ---------------- parallel exclusive scan (3 kernels) ----------------
__global__ __launch_bounds__(256) void k_partial(int n) {
    int i = blockIdx.x * 256 + threadIdx.x;
    int v = (i < n) ? g_cnt[i] : 0;
#pragma unroll
    for (int o = 16; o; o >>= 1) v += __shfl_down_sync(0xffffffffu, v, o);
    __shared__ int ws[8];
    if ((threadIdx.x & 31) == 0) ws[threadIdx.x >> 5] = v;
    __syncthreads();
    if (threadIdx.x < 8) {
        int s = ws[threadIdx.x];
#pragma unroll
        for (int o = 4; o; o >>= 1) s += __shfl_down_sync(0xffu, s, o);
        if (threadIdx.x == 0) g_bsum[blockIdx.x] = s;
    }
}

__global__ __launch_bounds__(256) void k_scanb(int nb) {
    const int t = threadIdx.x;
    const int lane = t & 31, w = t >> 5;
    int v = (t < nb) ? g_bsum[t] : 0;
    int inc = v;
#pragma unroll
    for (int o = 1; o < 32; o <<= 1) {
        int u = __shfl_up_sync(0xffffffffu, inc, o);
        if (lane >= o) inc += u;
    }
    __shared__ int ws[8];
    if (lane == 31) ws[w] = inc;
    __syncthreads();
    if (t < 8) {
        int s = ws[t];
#pragma unroll
        for (int o = 1; o < 8; o <<= 1) {
            int u = __shfl_up_sync(0xffu, s, o);
            if (t >= o) s += u;
        }
        ws[t] = s;
    }
    __syncthreads();
    int base = (w ? ws[w - 1] : 0);
    g_boff[t] = base + inc - v;
}

__global__ __launch_bounds__(256) void k_rowptr(int n, int e) {
    int i = blockIdx.x * 256 + threadIdx.x;
    int c = (i < n) ? g_cnt[i] : 0;
    const int lane = threadIdx.x & 31, w = threadIdx.x >> 5;
    int inc = c;
#pragma unroll
    for (int o = 1; o < 32; o <<= 1) {
        int u = __shfl_up_sync(0xffffffffu, inc, o);
        if (lane >= o) inc += u;
    }
    __shared__ int ws[8];
    if (lane == 31) ws[w] = inc;
    __syncthreads();
    if (threadIdx.x < 8) {
        int s = ws[threadIdx.x];
#pragma unroll
        for (int o = 1; o < 8; o <<= 1) {
            int u = __shfl_up_sync(0xffu, s, o);
            if (threadIdx.x >= o) s += u;
        }
        ws[threadIdx.x] = s;
    }
    __syncthreads();
    int base = g_boff[blockIdx.x] + (w ? ws[w - 1] : 0);
    if (i < n) {
        g_rowptr[i] = base + inc - c;
        g_dinv[i] = rsqrtf((float)(c + 1));
    }
    if (i == 0) g_rowptr[n] = e;
}

__global__ void k_fillw(const void* __restrict__ ei, int e) {
    int i = blockIdx.x * blockDim.x + threadIdx.x;
    if (i >= e) return;
    int src = ld_idx(ei, i);
    int dst = ld_idx(ei, e + i);
    int pos = g_rowptr[dst] + atomicAdd(&g_fill[dst], 1);
    float w = g_dinv[src] * g_dinv[dst];
    g_cw[pos] = make_int2(src, __float_as_int(w));
}

// ---------------- W1 prep: transpose to [n][k], bf16 ----------------
__global__ void k_prepW(const float* __restrict__ W) {
    int i = blockIdx.x * 256 + threadIdx.x;
    if (i >= FIN * HID) return;
    int k = i >> 7, nn = i & 127;
    uint32_t p = cvt2(W[i], 0.f);
    g_wT[nn * FIN + k] = (unsigned short)(p & 0xffffu);
}

// ---------------- GEMM1: h1 = x[n,512] @ W1[512,128], single-pass bf16 mma -------
// A = bf16(x), B = bf16(W1). L1-traffic minimized: per kk-step 4 A-LDSM + 2 B-LDSM.
// Software-pipelined register prefetch; epilogue stores bf16 h1.
__global__ __launch_bounds__(256, 1) void k_gemm1(const float* __restrict__ x, int n) {
    __shared__ __align__(16) unsigned short Ah[128][40];
    __shared__ __align__(16) unsigned short Bh[128][40];

    const int tid = threadIdx.x;
    const int lane = tid & 31;
    const int wid = tid >> 5;
    const int wm = wid & 1;
    const int wn = wid >> 1;
    const int m_base = wm * 64;
    const int n_base = wn * 32;
    const int row0 = blockIdx.x * 128;

    const int ldrow = tid >> 1;
    const int half = tid & 1;

    float c[4][4][4];
#pragma unroll
    for (int mt = 0; mt < 4; mt++)
#pragma unroll
        for (int nt = 0; nt < 4; nt++)
#pragma unroll
            for (int q = 0; q < 4; q++) c[mt][nt][q] = 0.f;

    const int qd = lane >> 3;
    const int r8 = lane & 7;
    const int a_r = m_base + (qd & 1) * 8 + r8;
    const int a_c = (qd >> 1) * 8;
    const int b_r = n_base + (lane >> 4) * 8 + r8;
    const int b_c = ((lane >> 3) & 1) * 8;

    const uint32_t sAh = (uint32_t)__cvta_generic_to_shared(&Ah[0][0]);
    const uint32_t sBh = (uint32_t)__cvta_generic_to_shared(&Bh[0][0]);

    const bool rowOK = (row0 + ldrow) < n;
    const float* xbase = x + (size_t)(row0 + ldrow) * FIN + half * 16;
    const unsigned short* whb = g_wT + ldrow * FIN + half * 16;

    float4 av[4];
    uint4 bvh[2];

#define LOADG(K0) do { \
        _Pragma("unroll") \
        for (int j = 0; j < 4; j++) \
            av[j] = rowOK ? *(const float4*)(xbase + (K0) + j * 4) \
                          : make_float4(0.f, 0.f, 0.f, 0.f); \
        bvh[0] = *(const uint4*)(whb + (K0)); \
        bvh[1] = *(const uint4*)(whb + (K0) + 8); \
    } while (0)

    LOADG(0);

#pragma unroll 1
    for (int it = 0; it < FIN / 32; it++) {
        {
            uint32_t* dh = (uint32_t*)&Ah[ldrow][half * 16];
#pragma unroll
            for (int j = 0; j < 4; j++) {
                float4 v = av[j];
                dh[j * 2 + 0] = cvt2(v.x, v.y);
                dh[j * 2 + 1] = cvt2(v.z, v.w);
            }
            uint4* bdh = (uint4*)&Bh[ldrow][half * 16];
            bdh[0] = bvh[0]; bdh[1] = bvh[1];
        }
        if (it + 1 < FIN / 32) LOADG((it + 1) * 32);
        __syncthreads();

#pragma unroll
        for (int kk = 0; kk < 32; kk += 16) {
            uint32_t ah[4][4], bh[2][4];
#pragma unroll
            for (int mt = 0; mt < 4; mt++) {
                uint32_t off = (uint32_t)(((a_r + mt * 16) * 40 + kk + a_c) * 2);
                LDSM4(ah[mt][0], ah[mt][1], ah[mt][2], ah[mt][3], sAh + off);
            }
#pragma unroll
            for (int pp = 0; pp < 2; pp++) {
                uint32_t off = (uint32_t)(((b_r + pp * 16) * 40 + kk + b_c) * 2);
                LDSM4(bh[pp][0], bh[pp][1], bh[pp][2], bh[pp][3], sBh + off);
            }
#pragma unroll
            for (int mt = 0; mt < 4; mt++) {
#pragma unroll
                for (int nt = 0; nt < 4; nt++) {
                    int pp = nt >> 1, ix = (nt & 1) * 2;
                    MMAB16(c[mt][nt], ah[mt], bh[pp][ix], bh[pp][ix + 1]);
                }
            }
        }
        __syncthreads();
    }
#undef LOADG

    // ---- store C as bf16 ----
#pragma unroll
    for (int mt = 0; mt < 4; mt++) {
        int row = row0 + m_base + mt * 16 + (lane >> 2);
#pragma unroll
        for (int nt = 0; nt < 4; nt++) {
            int col = n_base + nt * 8 + (lane & 3) * 2;
            if (row < n)
                *(uint32_t*)(g_h1b + (size_t)row * HID + col) =
                    cvt2(c[mt][nt][0], c[mt][nt][1]);
            if (row + 8 < n)
                *(uint32_t*)(g_h1b + (size_t)(row + 8) * HID + col) =
                    cvt2(c[mt][nt][2], c[mt][nt][3]);
        }
    }
}

// ---------------- agg1: out1 = relu(b1 + sum_norm(h1_bf16)), warp per node --------
__global__ void k_agg1(const float* __restrict__ b1, int n) {
    int gw = (blockIdx.x * blockDim.x + threadIdx.x) >> 5;
    int lane = threadIdx.x & 31;
    if (gw >= n) return;
    const int i = gw;
    const float di = g_dinv[i];
    const uint2* __restrict__ h2p = (const uint2*)g_h1b;

    float4 self = bf16x4_to_f4(h2p[(size_t)i * 32 + lane]);
    float sw = di * di;
    float4 acc = make_float4(self.x * sw, self.y * sw, self.z * sw, self.w * sw);

    const int rs = g_rowptr[i], re = g_rowptr[i + 1];
    for (int base = rs; base < re; base += 32) {
        int m = re - base; if (m > 32) m = 32;
        int2 cw = make_int2(0, 0);
        if (lane < m) cw = g_cw[base + lane];
#pragma unroll 4
        for (int j = 0; j < m; j++) {
            int ss = __shfl_sync(0xffffffffu, cw.x, j);
            float ww = __int_as_float(__shfl_sync(0xffffffffu, cw.y, j));
            float4 v = bf16x4_to_f4(h2p[(size_t)ss * 32 + lane]);
            acc.x += v.x * ww; acc.y += v.y * ww;
            acc.z += v.z * ww; acc.w += v.w * ww;
        }
    }
    float4 bb = ((const float4*)b1)[lane];
    acc.x = fmaxf(acc.x + bb.x, 0.f);
    acc.y = fmaxf(acc.y + bb.y, 0.f);
    acc.z = fmaxf(acc.z + bb.z, 0.f);
    acc.w = fmaxf(acc.w + bb.w, 0.f);
    uint2 pk = make_uint2(cvt2(acc.x, acc.y), cvt2(acc.z, acc.w));
    ((uint2*)g_out1b)[(size_t)i * 32 + lane] = pk;
}

// ---------------- GEMM2: h2 = out1_bf16[n,128] @ W2[128,40], bf16 out ----------
__global__ __launch_bounds__(160) void k_gemm2(const float* __restrict__ W2, int n) {
    __shared__ __align__(16) float Ws[HID * NC];
    __shared__ float As[32 * 129];

    const int tid = threadIdx.x;
    for (int q = tid; q < HID * NC; q += 160) Ws[q] = W2[q];

    const int r0 = blockIdx.x * 32;
    for (int q = tid; q < 32 * (HID / 2); q += 160) {
        int r = q >> 6, kp = q & 63;
        int grow = r0 + r;
        uint32_t u = (grow < n)
            ? *(const uint32_t*)(g_out1b + (size_t)grow * HID + kp * 2) : 0u;
        As[r * 129 + kp * 2 + 0] = __uint_as_float(u << 16);
        As[r * 129 + kp * 2 + 1] = __uint_as_float(u & 0xffff0000u);
    }
    __syncthreads();

    const int r = tid & 31;
    const int cg = tid >> 5;
    const int c0 = cg * 8;
    float acc[8];
#pragma unroll
    for (int j = 0; j < 8; j++) acc[j] = 0.f;

#pragma unroll 4
    for (int k = 0; k < HID; k++) {
        float a = As[r * 129 + k];
        float4 w0 = *(const float4*)&Ws[k * NC + c0];
        float4 w1 = *(const float4*)&Ws[k * NC + c0 + 4];
        acc[0] += a * w0.x; acc[1] += a * w0.y; acc[2] += a * w0.z; acc[3] += a * w0.w;
        acc[4] += a * w1.x; acc[5] += a * w1.y; acc[6] += a * w1.z; acc[7] += a * w1.w;
    }
    int grow = r0 + r;
    if (grow < n) {
        uint2 p0 = make_uint2(cvt2(acc[0], acc[1]), cvt2(acc[2], acc[3]));
        uint2 p1 = make_uint2(cvt2(acc[4], acc[5]), cvt2(acc[6], acc[7]));
        *(uint2*)(g_h2b + (size_t)grow * NC + c0) = p0;
        *(uint2*)(g_h2b + (size_t)grow * NC + c0 + 4) = p1;
    }
}

// ---------------- agg2 + bias + log_softmax, warp per node ----------------
__global__ void k_agg2(const float* __restrict__ b2, float* __restrict__ out, int n) {
    int gw = (blockIdx.x * blockDim.x + threadIdx.x) >> 5;
    int lane = threadIdx.x & 31;
    if (gw >= n) return;
    const int i = gw;
    const float di = g_dinv[i];
    const uint2* __restrict__ h2p = (const uint2*)g_h2b;   // 10 uint2 per row

    float4 acc = make_float4(0.f, 0.f, 0.f, 0.f);
    if (lane < 10) {
        float4 v = bf16x4_to_f4(h2p[(size_t)i * 10 + lane]);
        float sw = di * di;
        acc = make_float4(v.x * sw, v.y * sw, v.z * sw, v.w * sw);
    }
    const int rs = g_rowptr[i], re = g_rowptr[i + 1];
    for (int base = rs; base < re; base += 32) {
        int m = re - base; if (m > 32) m = 32;
        int2 cw = make_int2(0, 0);
        if (lane < m) cw = g_cw[base + lane];
#pragma unroll 4
        for (int j = 0; j < m; j++) {
            int ss = __shfl_sync(0xffffffffu, cw.x, j);
            float ww = __int_as_float(__shfl_sync(0xffffffffu, cw.y, j));
            if (lane < 10) {
                float4 v = bf16x4_to_f4(h2p[(size_t)ss * 10 + lane]);
                acc.x += v.x * ww; acc.y += v.y * ww;
                acc.z += v.z * ww; acc.w += v.w * ww;
            }
        }
    }
    if (lane < 10) {
        float4 bb = ((const float4*)b2)[lane];
        acc.x += bb.x; acc.y += bb.y; acc.z += bb.z; acc.w += bb.w;
    }
    float m = (lane < 10)
        ? fmaxf(fmaxf(acc.x, acc.y), fmaxf(acc.z, acc.w)) : -3.0e38f;
#pragma unroll
    for (int off = 8; off; off >>= 1)
        m = fmaxf(m, __shfl_xor_sync(0xffffffffu, m, off, 16));
    float sum = (lane < 10)
        ? (expf(acc.x - m) + expf(acc.y - m) + expf(acc.z - m) + expf(acc.w - m))
        : 0.f;
#pragma unroll
    for (int off = 8; off; off >>= 1)
        sum += __shfl_xor_sync(0xffffffffu, sum, off, 16);
    float lse = m + logf(sum);
    if (lane < 10) {
        ((float4*)out)[(size_t)i * 10 + lane] =
            make_float4(acc.x - lse, acc.y - lse, acc.z - lse, acc.w - lse);
    }
}

// ---------------- launch: fork-join overlap of CSR build with GEMM1 --------------
extern "C" void kernel_launch(void* const* d_in, const int* in_sizes, int n_in,
                              void* d_out, int out_size) {
    const float* x  = (const float*)d_in[0];
    const void*  ei = d_in[1];
    const float* W1 = (const float*)d_in[2];
    const float* b1 = (const float*)d_in[3];
    const float* W2 = (const float*)d_in[4];
    const float* b2 = (const float*)d_in[5];
    float* out = (float*)d_out;

    const int n = in_sizes[0] / FIN;   // 50000
    const int e = in_sizes[1] / 2;     // 800000
    const int nb = (n + 255) / 256;    // 196

    cudaStream_t s2;
    cudaStreamCreateWithFlags(&s2, cudaStreamNonBlocking);
    cudaEvent_t evFork, evJoin;
    cudaEventCreateWithFlags(&evFork, cudaEventDisableTiming);
    cudaEventCreateWithFlags(&evJoin, cudaEventDisableTiming);

    cudaEventRecord(evFork, 0);
    cudaStreamWaitEvent(s2, evFork, 0);

    // submission order keeps gemm1 at kernel #4 (profiler captures #4)
    k_detect <<<1, 256, 0, s2>>>((const unsigned*)ei, e);           // #1
    k_zero   <<<(n + 255) / 256, 256, 0, s2>>>(n);                  // #2
    k_prepW  <<<(FIN * HID + 255) / 256, 256>>>(W1);                // #3 (main)
    k_gemm1  <<<(n + 127) / 128, 256>>>(x, n);                      // #4 (main)
    k_count  <<<(e + 255) / 256, 256, 0, s2>>>(ei, e);              // #5
    k_partial<<<nb, 256, 0, s2>>>(n);                               // #6
    k_scanb  <<<1, 256, 0, s2>>>(nb);                               // #7
    k_rowptr <<<nb, 256, 0, s2>>>(n, e);                            // #8
    k_fillw  <<<(e + 255) / 256, 256, 0, s2>>>(ei, e);              // #9
    cudaEventRecord(evJoin, s2);

    cudaStreamWaitEvent(0, evJoin, 0);
    k_agg1   <<<(n + 7) / 8, 256>>>(b1, n);                         // #10
    k_gemm2  <<<(n + 31) / 32, 160>>>(W2, n);                       // #11
    k_agg2   <<<(n + 7) / 8, 256>>>(b2, out, n);                    // #12
}

// round 15
// speedup vs baseline: 2.3288x; 1.0575x over previous
#include <cuda_runtime.h>
#include <cuda_fp16.h>
#include <cstdint>

#define NMAX 50000
#define EMAX 800000
#define FIN  512
#define HID  128
#define NC   40
#define NBLK 256

// ---------------- device scratch (static; no allocs allowed) ----------------
__device__ unsigned short g_h1b [NMAX * HID];   // x @ W1, bf16
__device__ unsigned short g_out1b[NMAX * HID];  // relu(agg1+b1), bf16
__device__ unsigned short g_h2b [NMAX * NC];    // out1 @ W2, bf16
__device__ float g_dinv[NMAX];
__device__ int   g_cnt [NMAX];
__device__ int   g_fill[NMAX];
__device__ int   g_rowptr[NMAX + 1];
__device__ int2  g_cw  [EMAX];
__device__ int   g_bsum[NBLK];
__device__ int   g_boff[NBLK];
__device__ int   g_is64;
// W1 transposed bf16: [n][k] layout
__device__ unsigned short g_wT[HID * FIN];

typedef unsigned long long u64;

// pack two floats as bf16x2 (memory order: lo_elem first)
__device__ __forceinline__ uint32_t cvt2(float lo_elem, float hi_elem) {
    uint32_t r;
    asm("cvt.rn.bf16x2.f32 %0, %1, %2;" : "=r"(r) : "f"(hi_elem), "f"(lo_elem));
    return r;
}

#define LDSM4(d0, d1, d2, d3, addr) \
    asm volatile("ldmatrix.sync.aligned.m8n8.x4.shared.b16 {%0,%1,%2,%3}, [%4];" \
        : "=r"(d0), "=r"(d1), "=r"(d2), "=r"(d3) : "r"(addr))

#define MMAB16(c, a, b0, b1) \
    asm volatile("mma.sync.aligned.m16n8k16.row.col.f32.bf16.bf16.f32 " \
        "{%0,%1,%2,%3},{%4,%5,%6,%7},{%8,%9},{%0,%1,%2,%3};" \
        : "+f"((c)[0]), "+f"((c)[1]), "+f"((c)[2]), "+f"((c)[3]) \
        : "r"((a)[0]), "r"((a)[1]), "r"((a)[2]), "r"((a)[3]), "r"(b0), "r"(b1))

// edge index accessor
__device__ __forceinline__ int ld_idx(const void* ei, int pos) {
    if (g_is64) return (int)((const long long*)ei)[pos];
    return ((const int*)ei)[pos];
}

// unpack 4 bf16 (uint2) -> float4, exact
__device__ __forceinline__ float4 bf16x4_to_f4(uint2 u) {
    float4 v;
    v.x = __uint_as_float(u.x << 16);
    v.y = __uint_as_float(u.x & 0xffff0000u);
    v.z = __uint_as_float(u.y << 16);
    v.w = __uint_as_float(u.y & 0xffff0000u);
    return v;
}

// ---------------- dtype detection ----------------
__global__ void k_detect(const unsigned* __restrict__ w, int e) {
    __shared__ unsigned red[256];
    int total = e < 4096 ? e : 4096;
    unsigned acc = 0;
    for (int i = threadIdx.x; i < total; i += 256) acc |= w[2 * i + 1];
    red[threadIdx.x] = acc;
    __syncthreads();
    for (int s = 128; s > 0; s >>= 1) {
        if (threadIdx.x < s) red[threadIdx.x] |= red[threadIdx.x + s];
        __syncthreads();
    }
    if (threadIdx.x == 0) g_is64 = (red[0] == 0u) ? 1 : 0;
}

__global__ void k_zero(int n) {
    int i = blockIdx.x * blockDim.x + threadIdx.x;
    if (i < n) { g_cnt[i] = 0; g_fill[i] = 0; }
}

__global__ void k_count(const void* __restrict__ ei, int e) {
    int i = blockIdx.x * blockDim.x + threadIdx.x;
    if (i >= e) return;
    int dst = ld_idx(ei, e + i);
    atomicAdd(&g_cnt[dst], 1);
}

// ---------------- parallel exclusive scan (3 kernels) ----------------
__global__ __launch_bounds__(256) void k_partial(int n) {
    int i = blockIdx.x * 256 + threadIdx.x;
    int v = (i < n) ? g_cnt[i] : 0;
#pragma unroll
    for (int o = 16; o; o >>= 1) v += __shfl_down_sync(0xffffffffu, v, o);
    __shared__ int ws[8];
    if ((threadIdx.x & 31) == 0) ws[threadIdx.x >> 5] = v;
    __syncthreads();
    if (threadIdx.x < 8) {
        int s = ws[threadIdx.x];
#pragma unroll
        for (int o = 4; o; o >>= 1) s += __shfl_down_sync(0xffu, s, o);
        if (threadIdx.x == 0) g_bsum[blockIdx.x] = s;
    }
}

__global__ __launch_bounds__(256) void k_scanb(int nb) {
    const int t = threadIdx.x;
    const int lane = t & 31, w = t >> 5;
    int v = (t < nb) ? g_bsum[t] : 0;
    int inc = v;
#pragma unroll
    for (int o = 1; o < 32; o <<= 1) {
        int u = __shfl_up_sync(0xffffffffu, inc, o);
        if (lane >= o) inc += u;
    }
    __shared__ int ws[8];
    if (lane == 31) ws[w] = inc;
    __syncthreads();
    if (t < 8) {
        int s = ws[t];
#pragma unroll
        for (int o = 1; o < 8; o <<= 1) {
            int u = __shfl_up_sync(0xffu, s, o);
            if (t >= o) s += u;
        }
        ws[t] = s;
    }
    __syncthreads();
    int base = (w ? ws[w - 1] : 0);
    g_boff[t] = base + inc - v;
}

__global__ __launch_bounds__(256) void k_rowptr(int n, int e) {
    int i = blockIdx.x * 256 + threadIdx.x;
    int c = (i < n) ? g_cnt[i] : 0;
    const int lane = threadIdx.x & 31, w = threadIdx.x >> 5;
    int inc = c;
#pragma unroll
    for (int o = 1; o < 32; o <<= 1) {
        int u = __shfl_up_sync(0xffffffffu, inc, o);
        if (lane >= o) inc += u;
    }
    __shared__ int ws[8];
    if (lane == 31) ws[w] = inc;
    __syncthreads();
    if (threadIdx.x < 8) {
        int s = ws[threadIdx.x];
#pragma unroll
        for (int o = 1; o < 8; o <<= 1) {
            int u = __shfl_up_sync(0xffu, s, o);
            if (threadIdx.x >= o) s += u;
        }
        ws[threadIdx.x] = s;
    }
    __syncthreads();
    int base = g_boff[blockIdx.x] + (w ? ws[w - 1] : 0);
    if (i < n) {
        g_rowptr[i] = base + inc - c;
        g_dinv[i] = rsqrtf((float)(c + 1));
    }
    if (i == 0) g_rowptr[n] = e;
}

__global__ void k_fillw(const void* __restrict__ ei, int e) {
    int i = blockIdx.x * blockDim.x + threadIdx.x;
    if (i >= e) return;
    int src = ld_idx(ei, i);
    int dst = ld_idx(ei, e + i);
    int pos = g_rowptr[dst] + atomicAdd(&g_fill[dst], 1);
    float w = g_dinv[src] * g_dinv[dst];
    g_cw[pos] = make_int2(src, __float_as_int(w));
}

// ---------------- W1 prep: transpose to [n][k], bf16 ----------------
__global__ void k_prepW(const float* __restrict__ W) {
    int i = blockIdx.x * 256 + threadIdx.x;
    if (i >= FIN * HID) return;
    int k = i >> 7, nn = i & 127;
    uint32_t p = cvt2(W[i], 0.f);
    g_wT[nn * FIN + k] = (unsigned short)(p & 0xffffu);
}

// ---------------- GEMM1: h1 = x[n,512] @ W1[512,128], single-pass bf16 mma -------
// A: LDG fp32 -> cvt -> STS.64. B: cp.async double-buffered straight from g_wT.
// __launch_bounds__(256,2): 2 CTAs/SM for latency hiding.
__global__ __launch_bounds__(256, 2) void k_gemm1(const float* __restrict__ x, int n) {
    __shared__ __align__(16) unsigned short Ah[128][40];
    __shared__ __align__(16) unsigned short Bh[2][128][40];

    const int tid = threadIdx.x;
    const int lane = tid & 31;
    const int wid = tid >> 5;
    const int wm = wid & 1;
    const int wn = wid >> 1;
    const int m_base = wm * 64;
    const int n_base = wn * 32;
    const int row0 = blockIdx.x * 128;

    const int ldrow = tid >> 1;
    const int half = tid & 1;

    float c[4][4][4];
#pragma unroll
    for (int mt = 0; mt < 4; mt++)
#pragma unroll
        for (int nt = 0; nt < 4; nt++)
#pragma unroll
            for (int q = 0; q < 4; q++) c[mt][nt][q] = 0.f;

    const int qd = lane >> 3;
    const int r8 = lane & 7;
    const int a_r = m_base + (qd & 1) * 8 + r8;
    const int a_c = (qd >> 1) * 8;
    const int b_r = n_base + (lane >> 4) * 8 + r8;
    const int b_c = ((lane >> 3) & 1) * 8;

    const uint32_t sAh = (uint32_t)__cvta_generic_to_shared(&Ah[0][0]);
    const uint32_t sBh = (uint32_t)__cvta_generic_to_shared(&Bh[0][0][0]);
    const uint32_t BUFB = 128u * 40u * 2u;   // 10240 bytes per B buffer

    const bool rowOK = (row0 + ldrow) < n;
    const float* xbase = x + (size_t)(row0 + ldrow) * FIN + half * 16;
    const unsigned short* wsrc = g_wT + ldrow * FIN + half * 16;
    const uint32_t bdst = sBh + (uint32_t)((ldrow * 40 + half * 16) * 2);

    float4 av[4];

#define LOADA(K0) do { \
        _Pragma("unroll") \
        for (int j = 0; j < 4; j++) \
            av[j] = rowOK ? *(const float4*)(xbase + (K0) + j * 4) \
                          : make_float4(0.f, 0.f, 0.f, 0.f); \
    } while (0)

#define CPB(K0, buf) \
    asm volatile( \
        "cp.async.cg.shared.global [%0], [%1], 16;\n\t" \
        "cp.async.cg.shared.global [%2], [%3], 16;\n\t" \
        "cp.async.commit_group;\n\t" \
        :: "r"(bdst + (buf) * BUFB), "l"(wsrc + (K0)), \
           "r"(bdst + (buf) * BUFB + 16), "l"(wsrc + (K0) + 8) \
        : "memory")

    CPB(0, 0u);
    LOADA(0);

#pragma unroll 1
    for (int it = 0; it < FIN / 32; it++) {
        // ---- convert + store A tile (STS.64) ----
        {
            uint2* dh = (uint2*)&Ah[ldrow][half * 16];
#pragma unroll
            for (int j = 0; j < 4; j++) {
                float4 v = av[j];
                dh[j] = make_uint2(cvt2(v.x, v.y), cvt2(v.z, v.w));
            }
        }
        // ---- prefetch next tile: A into regs, B via cp.async ----
        if (it + 1 < FIN / 32) {
            LOADA((it + 1) * 32);
            CPB((it + 1) * 32, (uint32_t)((it + 1) & 1));
            asm volatile("cp.async.wait_group 1;" ::: "memory");
        } else {
            asm volatile("cp.async.wait_group 0;" ::: "memory");
        }
        __syncthreads();

        const uint32_t bbuf = (uint32_t)(it & 1) * BUFB;
#pragma unroll
        for (int kk = 0; kk < 32; kk += 16) {
            uint32_t ah[4][4], bh[2][4];
#pragma unroll
            for (int mt = 0; mt < 4; mt++) {
                uint32_t off = (uint32_t)(((a_r + mt * 16) * 40 + kk + a_c) * 2);
                LDSM4(ah[mt][0], ah[mt][1], ah[mt][2], ah[mt][3], sAh + off);
            }
#pragma unroll
            for (int pp = 0; pp < 2; pp++) {
                uint32_t off = (uint32_t)(((b_r + pp * 16) * 40 + kk + b_c) * 2);
                LDSM4(bh[pp][0], bh[pp][1], bh[pp][2], bh[pp][3], sBh + bbuf + off);
            }
#pragma unroll
            for (int mt = 0; mt < 4; mt++) {
#pragma unroll
                for (int nt = 0; nt < 4; nt++) {
                    int pp = nt >> 1, ix = (nt & 1) * 2;
                    MMAB16(c[mt][nt], ah[mt], bh[pp][ix], bh[pp][ix + 1]);
                }
            }
        }
        __syncthreads();
    }
#undef LOADA
#undef CPB

    // ---- store C as bf16 ----
#pragma unroll
    for (int mt = 0; mt < 4; mt++) {
        int row = row0 + m_base + mt * 16 + (lane >> 2);
#pragma unroll
        for (int nt = 0; nt < 4; nt++) {
            int col = n_base + nt * 8 + (lane & 3) * 2;
            if (row < n)
                *(uint32_t*)(g_h1b + (size_t)row * HID + col) =
                    cvt2(c[mt][nt][0], c[mt][nt][1]);
            if (row + 8 < n)
                *(uint32_t*)(g_h1b + (size_t)(row + 8) * HID + col) =
                    cvt2(c[mt][nt][2], c[mt][nt][3]);
        }
    }
}

// ---------------- agg1: out1 = relu(b1 + sum_norm(h1_bf16)), warp per node --------
__global__ void k_agg1(const float* __restrict__ b1, int n) {
    int gw = (blockIdx.x * blockDim.x + threadIdx.x) >> 5;
    int lane = threadIdx.x & 31;
    if (gw >= n) return;
    const int i = gw;
    const float di = g_dinv[i];
    const uint2* __restrict__ h2p = (const uint2*)g_h1b;

    float4 self = bf16x4_to_f4(h2p[(size_t)i * 32 + lane]);
    float sw = di * di;
    float4 acc = make_float4(self.x * sw, self.y * sw, self.z * sw, self.w * sw);

    const int rs = g_rowptr[i], re = g_rowptr[i + 1];
    for (int base = rs; base < re; base += 32) {
        int m = re - base; if (m > 32) m = 32;
        int2 cw = make_int2(0, 0);
        if (lane < m) cw = g_cw[base + lane];
#pragma unroll 4
        for (int j = 0; j < m; j++) {
            int ss = __shfl_sync(0xffffffffu, cw.x, j);
            float ww = __int_as_float(__shfl_sync(0xffffffffu, cw.y, j));
            float4 v = bf16x4_to_f4(h2p[(size_t)ss * 32 + lane]);
            acc.x += v.x * ww; acc.y += v.y * ww;
            acc.z += v.z * ww; acc.w += v.w * ww;
        }
    }
    float4 bb = ((const float4*)b1)[lane];
    acc.x = fmaxf(acc.x + bb.x, 0.f);
    acc.y = fmaxf(acc.y + bb.y, 0.f);
    acc.z = fmaxf(acc.z + bb.z, 0.f);
    acc.w = fmaxf(acc.w + bb.w, 0.f);
    uint2 pk = make_uint2(cvt2(acc.x, acc.y), cvt2(acc.z, acc.w));
    ((uint2*)g_out1b)[(size_t)i * 32 + lane] = pk;
}

// ---------------- GEMM2: h2 = out1_bf16[n,128] @ W2[128,40], bf16 out ----------
__global__ __launch_bounds__(160) void k_gemm2(const float* __restrict__ W2, int n) {
    __shared__ __align__(16) float Ws[HID * NC];
    __shared__ float As[32 * 129];

    const int tid = threadIdx.x;
    for (int q = tid; q < HID * NC; q += 160) Ws[q] = W2[q];

    const int r0 = blockIdx.x * 32;
    for (int q = tid; q < 32 * (HID / 2); q += 160) {
        int r = q >> 6, kp = q & 63;
        int grow = r0 + r;
        uint32_t u = (grow < n)
            ? *(const uint32_t*)(g_out1b + (size_t)grow * HID + kp * 2) : 0u;
        As[r * 129 + kp * 2 + 0] = __uint_as_float(u << 16);
        As[r * 129 + kp * 2 + 1] = __uint_as_float(u & 0xffff0000u);
    }
    __syncthreads();

    const int r = tid & 31;
    const int cg = tid >> 5;
    const int c0 = cg * 8;
    float acc[8];
#pragma unroll
    for (int j = 0; j < 8; j++) acc[j] = 0.f;

#pragma unroll 4
    for (int k = 0; k < HID; k++) {
        float a = As[r * 129 + k];
        float4 w0 = *(const float4*)&Ws[k * NC + c0];
        float4 w1 = *(const float4*)&Ws[k * NC + c0 + 4];
        acc[0] += a * w0.x; acc[1] += a * w0.y; acc[2] += a * w0.z; acc[3] += a * w0.w;
        acc[4] += a * w1.x; acc[5] += a * w1.y; acc[6] += a * w1.z; acc[7] += a * w1.w;
    }
    int grow = r0 + r;
    if (grow < n) {
        uint2 p0 = make_uint2(cvt2(acc[0], acc[1]), cvt2(acc[2], acc[3]));
        uint2 p1 = make_uint2(cvt2(acc[4], acc[5]), cvt2(acc[6], acc[7]));
        *(uint2*)(g_h2b + (size_t)grow * NC + c0) = p0;
        *(uint2*)(g_h2b + (size_t)grow * NC + c0 + 4) = p1;
    }
}

// ---------------- agg2 + bias + log_softmax, warp per node ----------------
__global__ void k_agg2(const float* __restrict__ b2, float* __restrict__ out, int n) {
    int gw = (blockIdx.x * blockDim.x + threadIdx.x) >> 5;
    int lane = threadIdx.x & 31;
    if (gw >= n) return;
    const int i = gw;
    const float di = g_dinv[i];
    const uint2* __restrict__ h2p = (const uint2*)g_h2b;   // 10 uint2 per row

    float4 acc = make_float4(0.f, 0.f, 0.f, 0.f);
    if (lane < 10) {
        float4 v = bf16x4_to_f4(h2p[(size_t)i * 10 + lane]);
        float sw = di * di;
        acc = make_float4(v.x * sw, v.y * sw, v.z * sw, v.w * sw);
    }
    const int rs = g_rowptr[i], re = g_rowptr[i + 1];
    for (int base = rs; base < re; base += 32) {
        int m = re - base; if (m > 32) m = 32;
        int2 cw = make_int2(0, 0);
        if (lane < m) cw = g_cw[base + lane];
#pragma unroll 4
        for (int j = 0; j < m; j++) {
            int ss = __shfl_sync(0xffffffffu, cw.x, j);
            float ww = __int_as_float(__shfl_sync(0xffffffffu, cw.y, j));
            if (lane < 10) {
                float4 v = bf16x4_to_f4(h2p[(size_t)ss * 10 + lane]);
                acc.x += v.x * ww; acc.y += v.y * ww;
                acc.z += v.z * ww; acc.w += v.w * ww;
            }
        }
    }
    if (lane < 10) {
        float4 bb = ((const float4*)b2)[lane];
        acc.x += bb.x; acc.y += bb.y; acc.z += bb.z; acc.w += bb.w;
    }
    float m = (lane < 10)
        ? fmaxf(fmaxf(acc.x, acc.y), fmaxf(acc.z, acc.w)) : -3.0e38f;
#pragma unroll
    for (int off = 8; off; off >>= 1)
        m = fmaxf(m, __shfl_xor_sync(0xffffffffu, m, off, 16));
    float sum = (lane < 10)
        ? (expf(acc.x - m) + expf(acc.y - m) + expf(acc.z - m) + expf(acc.w - m))
        : 0.f;
#pragma unroll
    for (int off = 8; off; off >>= 1)
        sum += __shfl_xor_sync(0xffffffffu, sum, off, 16);
    float lse = m + logf(sum);
    if (lane < 10) {
        ((float4*)out)[(size_t)i * 10 + lane] =
            make_float4(acc.x - lse, acc.y - lse, acc.z - lse, acc.w - lse);
    }
}

// ---------------- launch: fork-join overlap of CSR build with GEMM1 --------------
extern "C" void kernel_launch(void* const* d_in, const int* in_sizes, int n_in,
                              void* d_out, int out_size) {
    const float* x  = (const float*)d_in[0];
    const void*  ei = d_in[1];
    const float* W1 = (const float*)d_in[2];
    const float* b1 = (const float*)d_in[3];
    const float* W2 = (const float*)d_in[4];
    const float* b2 = (const float*)d_in[5];
    float* out = (float*)d_out;

    const int n = in_sizes[0] / FIN;   // 50000
    const int e = in_sizes[1] / 2;     // 800000
    const int nb = (n + 255) / 256;    // 196

    cudaStream_t s2;
    cudaStreamCreateWithFlags(&s2, cudaStreamNonBlocking);
    cudaEvent_t evFork, evJoin;
    cudaEventCreateWithFlags(&evFork, cudaEventDisableTiming);
    cudaEventCreateWithFlags(&evJoin, cudaEventDisableTiming);

    cudaEventRecord(evFork, 0);
    cudaStreamWaitEvent(s2, evFork, 0);

    // submission order keeps gemm1 at kernel #4 (profiler captures #4)
    k_detect <<<1, 256, 0, s2>>>((const unsigned*)ei, e);           // #1
    k_zero   <<<(n + 255) / 256, 256, 0, s2>>>(n);                  // #2
    k_prepW  <<<(FIN * HID + 255) / 256, 256>>>(W1);                // #3 (main)
    k_gemm1  <<<(n + 127) / 128, 256>>>(x, n);                      // #4 (main)
    k_count  <<<(e + 255) / 256, 256, 0, s2>>>(ei, e);              // #5
    k_partial<<<nb, 256, 0, s2>>>(n);                               // #6
    k_scanb  <<<1, 256, 0, s2>>>(nb);                               // #7
    k_rowptr <<<nb, 256, 0, s2>>>(n, e);                            // #8
    k_fillw  <<<(e + 255) / 256, 256, 0, s2>>>(ei, e);              // #9
    cudaEventRecord(evJoin, s2);

    cudaStreamWaitEvent(0, evJoin, 0);
    k_agg1   <<<(n + 7) / 8, 256>>>(b1, n);                         // #10
    k_gemm2  <<<(n + 31) / 32, 160>>>(W2, n);                       // #11
    k_agg2   <<<(n + 7) / 8, 256>>>(b2, out, n);                    // #12
}

// round 17
// speedup vs baseline: 2.5131x; 1.0791x over previous
#include <cuda_runtime.h>
#include <cuda_fp16.h>
#include <cstdint>

#define NMAX 50000
#define EMAX 800000
#define FIN  512
#define HID  128
#define NC   40
#define NBLK 256
#define FULL 0xffffffffu

// ---------------- device scratch (static; no allocs allowed) ----------------
__device__ unsigned short g_h1b [NMAX * HID];   // x @ W1, bf16
__device__ unsigned short g_out1b[NMAX * HID];  // relu(agg1+b1), bf16
__device__ unsigned short g_h2b [NMAX * NC];    // out1 @ W2, bf16
__device__ float g_dinv[NMAX];
__device__ int   g_cnt [NMAX];
__device__ int   g_fill[NMAX];
__device__ int   g_rowptr[NMAX + 1];
__device__ int2  g_cw  [EMAX];
__device__ int   g_bsum[NBLK];
__device__ int   g_boff[NBLK];
__device__ int   g_is64;
// W1 transposed bf16: [n][k] layout
__device__ unsigned short g_wT[HID * FIN];

typedef unsigned long long u64;

// pack two floats as bf16x2 (memory order: lo_elem first)
__device__ __forceinline__ uint32_t cvt2(float lo_elem, float hi_elem) {
    uint32_t r;
    asm("cvt.rn.bf16x2.f32 %0, %1, %2;" : "=r"(r) : "f"(hi_elem), "f"(lo_elem));
    return r;
}

#define LDSM4(d0, d1, d2, d3, addr) \
    asm volatile("ldmatrix.sync.aligned.m8n8.x4.shared.b16 {%0,%1,%2,%3}, [%4];" \
        : "=r"(d0), "=r"(d1), "=r"(d2), "=r"(d3) : "r"(addr))

#define MMAB16(c, a, b0, b1) \
    asm volatile("mma.sync.aligned.m16n8k16.row.col.f32.bf16.bf16.f32 " \
        "{%0,%1,%2,%3},{%4,%5,%6,%7},{%8,%9},{%0,%1,%2,%3};" \
        : "+f"((c)[0]), "+f"((c)[1]), "+f"((c)[2]), "+f"((c)[3]) \
        : "r"((a)[0]), "r"((a)[1]), "r"((a)[2]), "r"((a)[3]), "r"(b0), "r"(b1))

// edge index accessor
__device__ __forceinline__ int ld_idx(const void* ei, int pos) {
    if (g_is64) return (int)((const long long*)ei)[pos];
    return ((const int*)ei)[pos];
}

// unpack 4 bf16 (uint2) -> float4, exact
__device__ __forceinline__ float4 bf16x4_to_f4(uint2 u) {
    float4 v;
    v.x = __uint_as_float(u.x << 16);
    v.y = __uint_as_float(u.x & 0xffff0000u);
    v.z = __uint_as_float(u.y << 16);
    v.w = __uint_as_float(u.y & 0xffff0000u);
    return v;
}

// ---------------- dtype detection ----------------
__global__ void k_detect(const unsigned* __restrict__ w, int e) {
    __shared__ unsigned red[256];
    int total = e < 4096 ? e : 4096;
    unsigned acc = 0;
    for (int i = threadIdx.x; i < total; i += 256) acc |= w[2 * i + 1];
    red[threadIdx.x] = acc;
    __syncthreads();
    for (int s = 128; s > 0; s >>= 1) {
        if (threadIdx.x < s) red[threadIdx.x] |= red[threadIdx.x + s];
        __syncthreads();
    }
    if (threadIdx.x == 0) g_is64 = (red[0] == 0u) ? 1 : 0;
}

__global__ void k_zero(int n) {
    int i = blockIdx.x * blockDim.x + threadIdx.x;
    if (i < n) { g_cnt[i] = 0; g_fill[i] = 0; }
}

__global__ void k_count(const void* __restrict__ ei, int e) {
    int i = blockIdx.x * blockDim.x + threadIdx.x;
    if (i >= e) return;
    int dst = ld_idx(ei, e + i);
    atomicAdd(&g_cnt[dst], 1);
}

// ---------------- parallel exclusive scan (3 kernels) ----------------
__global__ __launch_bounds__(256) void k_partial(int n) {
    int i = blockIdx.x * 256 + threadIdx.x;
    int v = (i < n) ? g_cnt[i] : 0;
#pragma unroll
    for (int o = 16; o; o >>= 1) v += __shfl_down_sync(FULL, v, o);
    __shared__ int ws[8];
    if ((threadIdx.x & 31) == 0) ws[threadIdx.x >> 5] = v;
    __syncthreads();
    if (threadIdx.x < 8) {
        int s = ws[threadIdx.x];
#pragma unroll
        for (int o = 4; o; o >>= 1) s += __shfl_down_sync(0xffu, s, o);
        if (threadIdx.x == 0) g_bsum[blockIdx.x] = s;
    }
}

__global__ __launch_bounds__(256) void k_scanb(int nb) {
    const int t = threadIdx.x;
    const int lane = t & 31, w = t >> 5;
    int v = (t < nb) ? g_bsum[t] : 0;
    int inc = v;
#pragma unroll
    for (int o = 1; o < 32; o <<= 1) {
        int u = __shfl_up_sync(FULL, inc, o);
        if (lane >= o) inc += u;
    }
    __shared__ int ws[8];
    if (lane == 31) ws[w] = inc;
    __syncthreads();
    if (t < 8) {
        int s = ws[t];
#pragma unroll
        for (int o = 1; o < 8; o <<= 1) {
            int u = __shfl_up_sync(0xffu, s, o);
            if (t >= o) s += u;
        }
        ws[t] = s;
    }
    __syncthreads();
    int base = (w ? ws[w - 1] : 0);
    g_boff[t] = base + inc - v;
}

__global__ __launch_bounds__(256) void k_rowptr(int n, int e) {
    int i = blockIdx.x * 256 + threadIdx.x;
    int c = (i < n) ? g_cnt[i] : 0;
    const int lane = threadIdx.x & 31, w = threadIdx.x >> 5;
    int inc = c;
#pragma unroll
    for (int o = 1; o < 32; o <<= 1) {
        int u = __shfl_up_sync(FULL, inc, o);
        if (lane >= o) inc += u;
    }
    __shared__ int ws[8];
    if (lane == 31) ws[w] = inc;
    __syncthreads();
    if (threadIdx.x < 8) {
        int s = ws[threadIdx.x];
#pragma unroll
        for (int o = 1; o < 8; o <<= 1) {
            int u = __shfl_up_sync(0xffu, s, o);
            if (threadIdx.x >= o) s += u;
        }
        ws[threadIdx.x] = s;
    }
    __syncthreads();
    int base = g_boff[blockIdx.x] + (w ? ws[w - 1] : 0);
    if (i < n) {
        g_rowptr[i] = base + inc - c;
        g_dinv[i] = rsqrtf((float)(c + 1));
    }
    if (i == 0) g_rowptr[n] = e;
}

__global__ void k_fillw(const void* __restrict__ ei, int e) {
    int i = blockIdx.x * blockDim.x + threadIdx.x;
    if (i >= e) return;
    int src = ld_idx(ei, i);
    int dst = ld_idx(ei, e + i);
    int pos = g_rowptr[dst] + atomicAdd(&g_fill[dst], 1);
    float w = g_dinv[src] * g_dinv[dst];
    g_cw[pos] = make_int2(src, __float_as_int(w));
}

// ---------------- W1 prep: transpose to [n][k], bf16 ----------------
__global__ void k_prepW(const float* __restrict__ W) {
    int i = blockIdx.x * 256 + threadIdx.x;
    if (i >= FIN * HID) return;
    int k = i >> 7, nn = i & 127;
    uint32_t p = cvt2(W[i], 0.f);
    g_wT[nn * FIN + k] = (unsigned short)(p & 0xffffu);
}

// ---------------- GEMM1: h1 = x[n,512] @ W1[512,128], single-pass bf16 mma -------
// A: LDG fp32 -> cvt -> STS.64. B: cp.async double-buffered straight from g_wT.
__global__ __launch_bounds__(256, 2) void k_gemm1(const float* __restrict__ x, int n) {
    __shared__ __align__(16) unsigned short Ah[128][40];
    __shared__ __align__(16) unsigned short Bh[2][128][40];

    const int tid = threadIdx.x;
    const int lane = tid & 31;
    const int wid = tid >> 5;
    const int wm = wid & 1;
    const int wn = wid >> 1;
    const int m_base = wm * 64;
    const int n_base = wn * 32;
    const int row0 = blockIdx.x * 128;

    const int ldrow = tid >> 1;
    const int half = tid & 1;

    float c[4][4][4];
#pragma unroll
    for (int mt = 0; mt < 4; mt++)
#pragma unroll
        for (int nt = 0; nt < 4; nt++)
#pragma unroll
            for (int q = 0; q < 4; q++) c[mt][nt][q] = 0.f;

    const int qd = lane >> 3;
    const int r8 = lane & 7;
    const int a_r = m_base + (qd & 1) * 8 + r8;
    const int a_c = (qd >> 1) * 8;
    const int b_r = n_base + (lane >> 4) * 8 + r8;
    const int b_c = ((lane >> 3) & 1) * 8;

    const uint32_t sAh = (uint32_t)__cvta_generic_to_shared(&Ah[0][0]);
    const uint32_t sBh = (uint32_t)__cvta_generic_to_shared(&Bh[0][0][0]);
    const uint32_t BUFB = 128u * 40u * 2u;

    const bool rowOK = (row0 + ldrow) < n;
    const float* xbase = x + (size_t)(row0 + ldrow) * FIN + half * 16;
    const unsigned short* wsrc = g_wT + ldrow * FIN + half * 16;
    const uint32_t bdst = sBh + (uint32_t)((ldrow * 40 + half * 16) * 2);

    float4 av[4];

#define LOADA(K0) do { \
        _Pragma("unroll") \
        for (int j = 0; j < 4; j++) \
            av[j] = rowOK ? *(const float4*)(xbase + (K0) + j * 4) \
                          : make_float4(0.f, 0.f, 0.f, 0.f); \
    } while (0)

#define CPB(K0, buf) \
    asm volatile( \
        "cp.async.cg.shared.global [%0], [%1], 16;\n\t" \
        "cp.async.cg.shared.global [%2], [%3], 16;\n\t" \
        "cp.async.commit_group;\n\t" \
        :: "r"(bdst + (buf) * BUFB), "l"(wsrc + (K0)), \
           "r"(bdst + (buf) * BUFB + 16), "l"(wsrc + (K0) + 8) \
        : "memory")

    CPB(0, 0u);
    LOADA(0);

#pragma unroll 1
    for (int it = 0; it < FIN / 32; it++) {
        {
            uint2* dh = (uint2*)&Ah[ldrow][half * 16];
#pragma unroll
            for (int j = 0; j < 4; j++) {
                float4 v = av[j];
                dh[j] = make_uint2(cvt2(v.x, v.y), cvt2(v.z, v.w));
            }
        }
        if (it + 1 < FIN / 32) {
            LOADA((it + 1) * 32);
            CPB((it + 1) * 32, (uint32_t)((it + 1) & 1));
            asm volatile("cp.async.wait_group 1;" ::: "memory");
        } else {
            asm volatile("cp.async.wait_group 0;" ::: "memory");
        }
        __syncthreads();

        const uint32_t bbuf = (uint32_t)(it & 1) * BUFB;
#pragma unroll
        for (int kk = 0; kk < 32; kk += 16) {
            uint32_t ah[4][4], bh[2][4];
#pragma unroll
            for (int mt = 0; mt < 4; mt++) {
                uint32_t off = (uint32_t)(((a_r + mt * 16) * 40 + kk + a_c) * 2);
                LDSM4(ah[mt][0], ah[mt][1], ah[mt][2], ah[mt][3], sAh + off);
            }
#pragma unroll
            for (int pp = 0; pp < 2; pp++) {
                uint32_t off = (uint32_t)(((b_r + pp * 16) * 40 + kk + b_c) * 2);
                LDSM4(bh[pp][0], bh[pp][1], bh[pp][2], bh[pp][3], sBh + bbuf + off);
            }
#pragma unroll
            for (int mt = 0; mt < 4; mt++) {
#pragma unroll
                for (int nt = 0; nt < 4; nt++) {
                    int pp = nt >> 1, ix = (nt & 1) * 2;
                    MMAB16(c[mt][nt], ah[mt], bh[pp][ix], bh[pp][ix + 1]);
                }
            }
        }
        __syncthreads();
    }
#undef LOADA
#undef CPB

#pragma unroll
    for (int mt = 0; mt < 4; mt++) {
        int row = row0 + m_base + mt * 16 + (lane >> 2);
#pragma unroll
        for (int nt = 0; nt < 4; nt++) {
            int col = n_base + nt * 8 + (lane & 3) * 2;
            if (row < n)
                *(uint32_t*)(g_h1b + (size_t)row * HID + col) =
                    cvt2(c[mt][nt][0], c[mt][nt][1]);
            if (row + 8 < n)
                *(uint32_t*)(g_h1b + (size_t)(row + 8) * HID + col) =
                    cvt2(c[mt][nt][2], c[mt][nt][3]);
        }
    }
}

// ---------------- agg1: 2 nodes per warp (16-lane halves), uint4 row loads -------
__global__ void k_agg1(const float* __restrict__ b1, int n) {
    int gw = (blockIdx.x * blockDim.x + threadIdx.x) >> 5;
    const int lane = threadIdx.x & 31;
    const int half = lane >> 4;      // 0 or 1
    const int hl = lane & 15;        // lane within half
    const int i = 2 * gw + half;
    const bool active = i < n;
    const uint4* __restrict__ h4p = (const uint4*)g_h1b;   // 16 uint4 per row
    if (2 * gw >= n) return;         // whole warp out of range

    float a[8];
    int rs = 0, re = 0;
    if (active) {
        float di = g_dinv[i];
        float sw = di * di;
        uint4 u = h4p[(size_t)i * 16 + hl];
        float4 v0 = bf16x4_to_f4(make_uint2(u.x, u.y));
        float4 v1 = bf16x4_to_f4(make_uint2(u.z, u.w));
        a[0] = v0.x * sw; a[1] = v0.y * sw; a[2] = v0.z * sw; a[3] = v0.w * sw;
        a[4] = v1.x * sw; a[5] = v1.y * sw; a[6] = v1.z * sw; a[7] = v1.w * sw;
        rs = g_rowptr[i]; re = g_rowptr[i + 1];
    } else {
#pragma unroll
        for (int q = 0; q < 8; q++) a[q] = 0.f;
    }

    int myNb = (re - rs + 15) >> 4;
    int nb = max(__shfl_sync(FULL, myNb, 0), __shfl_sync(FULL, myNb, 16));

    for (int b = 0; b < nb; b++) {
        int base = rs + b * 16;
        int m = re - base;
        if (m > 16) m = 16; if (m < 0) m = 0;
        int2 cw = make_int2(0, 0);
        if (hl < m) cw = g_cw[base + hl];
        int mm = max(__shfl_sync(FULL, m, 0), __shfl_sync(FULL, m, 16));
#pragma unroll 4
        for (int j = 0; j < mm; j++) {
            int ss = __shfl_sync(FULL, cw.x, (half << 4) + j);
            float ww = __int_as_float(__shfl_sync(FULL, cw.y, (half << 4) + j));
            if (j < m) {
                uint4 u = h4p[(size_t)ss * 16 + hl];
                float4 v0 = bf16x4_to_f4(make_uint2(u.x, u.y));
                float4 v1 = bf16x4_to_f4(make_uint2(u.z, u.w));
                a[0] += v0.x * ww; a[1] += v0.y * ww;
                a[2] += v0.z * ww; a[3] += v0.w * ww;
                a[4] += v1.x * ww; a[5] += v1.y * ww;
                a[6] += v1.z * ww; a[7] += v1.w * ww;
            }
        }
    }

    if (active) {
        float4 bb0 = ((const float4*)b1)[hl * 2];
        float4 bb1 = ((const float4*)b1)[hl * 2 + 1];
        a[0] = fmaxf(a[0] + bb0.x, 0.f); a[1] = fmaxf(a[1] + bb0.y, 0.f);
        a[2] = fmaxf(a[2] + bb0.z, 0.f); a[3] = fmaxf(a[3] + bb0.w, 0.f);
        a[4] = fmaxf(a[4] + bb1.x, 0.f); a[5] = fmaxf(a[5] + bb1.y, 0.f);
        a[6] = fmaxf(a[6] + bb1.z, 0.f); a[7] = fmaxf(a[7] + bb1.w, 0.f);
        uint4 pk = make_uint4(cvt2(a[0], a[1]), cvt2(a[2], a[3]),
                              cvt2(a[4], a[5]), cvt2(a[6], a[7]));
        ((uint4*)g_out1b)[(size_t)i * 16 + hl] = pk;
    }
}

// ---------------- GEMM2: h2 = out1_bf16[n,128] @ W2[128,40], bf16 out ----------
__global__ __launch_bounds__(160) void k_gemm2(const float* __restrict__ W2, int n) {
    __shared__ __align__(16) float Ws[HID * NC];
    __shared__ float As[32 * 129];

    const int tid = threadIdx.x;
    for (int q = tid; q < HID * NC; q += 160) Ws[q] = W2[q];

    const int r0 = blockIdx.x * 32;
    for (int q = tid; q < 32 * (HID / 2); q += 160) {
        int r = q >> 6, kp = q & 63;
        int grow = r0 + r;
        uint32_t u = (grow < n)
            ? *(const uint32_t*)(g_out1b + (size_t)grow * HID + kp * 2) : 0u;
        As[r * 129 + kp * 2 + 0] = __uint_as_float(u << 16);
        As[r * 129 + kp * 2 + 1] = __uint_as_float(u & 0xffff0000u);
    }
    __syncthreads();

    const int r = tid & 31;
    const int cg = tid >> 5;
    const int c0 = cg * 8;
    float acc[8];
#pragma unroll
    for (int j = 0; j < 8; j++) acc[j] = 0.f;

#pragma unroll 4
    for (int k = 0; k < HID; k++) {
        float a = As[r * 129 + k];
        float4 w0 = *(const float4*)&Ws[k * NC + c0];
        float4 w1 = *(const float4*)&Ws[k * NC + c0 + 4];
        acc[0] += a * w0.x; acc[1] += a * w0.y; acc[2] += a * w0.z; acc[3] += a * w0.w;
        acc[4] += a * w1.x; acc[5] += a * w1.y; acc[6] += a * w1.z; acc[7] += a * w1.w;
    }
    int grow = r0 + r;
    if (grow < n) {
        uint2 p0 = make_uint2(cvt2(acc[0], acc[1]), cvt2(acc[2], acc[3]));
        uint2 p1 = make_uint2(cvt2(acc[4], acc[5]), cvt2(acc[6], acc[7]));
        *(uint2*)(g_h2b + (size_t)grow * NC + c0) = p0;
        *(uint2*)(g_h2b + (size_t)grow * NC + c0 + 4) = p1;
    }
}

// ---------------- agg2 + bias + log_softmax: 2 nodes per warp (16-lane halves) ----
__global__ void k_agg2(const float* __restrict__ b2, float* __restrict__ out, int n) {
    int gw = (blockIdx.x * blockDim.x + threadIdx.x) >> 5;
    const int lane = threadIdx.x & 31;
    const int half = lane >> 4;
    const int hl = lane & 15;
    const int i = 2 * gw + half;
    const bool act = (i < n) && (hl < 10);
    const uint2* __restrict__ h2p = (const uint2*)g_h2b;   // 10 uint2 per row
    if (2 * gw >= n) return;

    float4 acc = make_float4(0.f, 0.f, 0.f, 0.f);
    int rs = 0, re = 0;
    if (i < n) { rs = g_rowptr[i]; re = g_rowptr[i + 1]; }
    if (act) {
        float di = g_dinv[i];
        float sw = di * di;
        float4 v = bf16x4_to_f4(h2p[(size_t)i * 10 + hl]);
        acc = make_float4(v.x * sw, v.y * sw, v.z * sw, v.w * sw);
    }

    int myNb = (re - rs + 15) >> 4;
    int nb = max(__shfl_sync(FULL, myNb, 0), __shfl_sync(FULL, myNb, 16));

    for (int b = 0; b < nb; b++) {
        int base = rs + b * 16;
        int m = re - base;
        if (m > 16) m = 16; if (m < 0) m = 0;
        int2 cw = make_int2(0, 0);
        if (hl < m) cw = g_cw[base + hl];
        int mm = max(__shfl_sync(FULL, m, 0), __shfl_sync(FULL, m, 16));
#pragma unroll 4
        for (int j = 0; j < mm; j++) {
            int ss = __shfl_sync(FULL, cw.x, (half << 4) + j);
            float ww = __int_as_float(__shfl_sync(FULL, cw.y, (half << 4) + j));
            if (j < m && hl < 10) {
                float4 v = bf16x4_to_f4(h2p[(size_t)ss * 10 + hl]);
                acc.x += v.x * ww; acc.y += v.y * ww;
                acc.z += v.z * ww; acc.w += v.w * ww;
            }
        }
    }

    if (act) {
        float4 bb = ((const float4*)b2)[hl];
        acc.x += bb.x; acc.y += bb.y; acc.z += bb.z; acc.w += bb.w;
    }
    // log-softmax over 40 values in lanes hl=0..9 of each 16-lane half
    float m = act
        ? fmaxf(fmaxf(acc.x, acc.y), fmaxf(acc.z, acc.w)) : -3.0e38f;
#pragma unroll
    for (int off = 8; off; off >>= 1)
        m = fmaxf(m, __shfl_xor_sync(FULL, m, off, 16));
    float sum = act
        ? (expf(acc.x - m) + expf(acc.y - m) + expf(acc.z - m) + expf(acc.w - m))
        : 0.f;
#pragma unroll
    for (int off = 8; off; off >>= 1)
        sum += __shfl_xor_sync(FULL, sum, off, 16);
    float lse = m + logf(sum);
    if (act) {
        ((float4*)out)[(size_t)i * 10 + hl] =
            make_float4(acc.x - lse, acc.y - lse, acc.z - lse, acc.w - lse);
    }
}

// ---------------- launch: fork-join overlap of CSR build with GEMM1 --------------
extern "C" void kernel_launch(void* const* d_in, const int* in_sizes, int n_in,
                              void* d_out, int out_size) {
    const float* x  = (const float*)d_in[0];
    const void*  ei = d_in[1];
    const float* W1 = (const float*)d_in[2];
    const float* b1 = (const float*)d_in[3];
    const float* W2 = (const float*)d_in[4];
    const float* b2 = (const float*)d_in[5];
    float* out = (float*)d_out;

    const int n = in_sizes[0] / FIN;   // 50000
    const int e = in_sizes[1] / 2;     // 800000
    const int nb = (n + 255) / 256;    // 196
    const int pairs = (n + 1) / 2;     // 25000 (2 nodes per warp)

    cudaStream_t s2;
    cudaStreamCreateWithFlags(&s2, cudaStreamNonBlocking);
    cudaEvent_t evFork, evJoin;
    cudaEventCreateWithFlags(&evFork, cudaEventDisableTiming);
    cudaEventCreateWithFlags(&evJoin, cudaEventDisableTiming);

    cudaEventRecord(evFork, 0);
    cudaStreamWaitEvent(s2, evFork, 0);

    k_detect <<<1, 256, 0, s2>>>((const unsigned*)ei, e);           // #1
    k_zero   <<<(n + 255) / 256, 256, 0, s2>>>(n);                  // #2
    k_prepW  <<<(FIN * HID + 255) / 256, 256>>>(W1);                // #3 (main)
    k_gemm1  <<<(n + 127) / 128, 256>>>(x, n);                      // #4 (main)
    k_count  <<<(e + 255) / 256, 256, 0, s2>>>(ei, e);              // #5
    k_partial<<<nb, 256, 0, s2>>>(n);                               // #6
    k_scanb  <<<1, 256, 0, s2>>>(nb);                               // #7
    k_rowptr <<<nb, 256, 0, s2>>>(n, e);                            // #8
    k_fillw  <<<(e + 255) / 256, 256, 0, s2>>>(ei, e);              // #9
    cudaEventRecord(evJoin, s2);

    cudaStreamWaitEvent(0, evJoin, 0);
    k_agg1   <<<(pairs + 7) / 8, 256>>>(b1, n);                     // #10
    k_gemm2  <<<(n + 31) / 32, 160>>>(W2, n);                       // #11
    k_agg2   <<<(pairs + 7) / 8, 256>>>(b2, out, n);                // #12
}